// round 5
// baseline (speedup 1.0000x reference)
#include <cuda_runtime.h>
#include <cuda_bf16.h>
#include <math.h>
#include <stdint.h>

#define BB   8
#define LL   1024
#define HW   1024
#define HID  512
#define NH   8
#define DH   64

typedef __nv_bfloat16 bf16;

// Persistent split-bf16 scratch (allocation-free rule: __device__ globals)
__device__ bf16 g_kin_h[BB*LL*HID],  g_kin_l[BB*LL*HID];
__device__ bf16 g_vin_h[BB*LL*HID],  g_vin_l[BB*LL*HID];
__device__ bf16 g_qt_h [BB*HW*HID],  g_qt_l [BB*HW*HID];
__device__ bf16 g_wk_h[HID*HID], g_wk_l[HID*HID];
__device__ bf16 g_wv_h[HID*HID], g_wv_l[HID*HID];
__device__ bf16 g_wq_h[HID*HID], g_wq_l[HID*HID];
__device__ bf16 g_wm_h[HID*HID], g_wm_l[HID*HID];
__device__ bf16 g_k_h[BB*LL*HID], g_k_l[BB*LL*HID];
__device__ bf16 g_v_h[BB*LL*HID], g_v_l[BB*LL*HID];
__device__ bf16 g_q_h[BB*HW*HID], g_q_l[BB*HW*HID];
__device__ bf16 g_ao_h[BB*HW*HID], g_ao_l[BB*HW*HID];
__device__ unsigned char g_mask[BB*LL];

// ---------------------------------------------------------------------------
// helpers
// ---------------------------------------------------------------------------
__device__ __forceinline__ void split2(float a, float b, uint32_t& h, uint32_t& l)
{
    __nv_bfloat162 hv = __floats2bfloat162_rn(a, b);
    float ra = a - __bfloat162float(hv.x);
    float rb = b - __bfloat162float(hv.y);
    __nv_bfloat162 lv = __floats2bfloat162_rn(ra, rb);
    h = *reinterpret_cast<uint32_t*>(&hv);
    l = *reinterpret_cast<uint32_t*>(&lv);
}

// fast exp2 on FMA pipe (x <= 0), rel err ~1e-6
__device__ __forceinline__ float fexp2f(float x)
{
    x = fmaxf(x, -126.0f);
    int   n = __float2int_rn(x);
    float f = x - (float)n;
    float p = 1.33336498e-3f;
    p = fmaf(p, f, 9.61817007e-3f);
    p = fmaf(p, f, 5.55041087e-2f);
    p = fmaf(p, f, 2.40226507e-1f);
    p = fmaf(p, f, 6.93147181e-1f);
    p = fmaf(p, f, 1.0f);
    return p * __int_as_float((n + 127) << 23);
}

__device__ __forceinline__ void ldsm4(uint32_t& r0, uint32_t& r1, uint32_t& r2, uint32_t& r3, uint32_t addr)
{
    asm volatile("ldmatrix.sync.aligned.m8n8.x4.shared.b16 {%0,%1,%2,%3}, [%4];"
                 : "=r"(r0), "=r"(r1), "=r"(r2), "=r"(r3) : "r"(addr));
}
__device__ __forceinline__ void ldsm4t(uint32_t& r0, uint32_t& r1, uint32_t& r2, uint32_t& r3, uint32_t addr)
{
    asm volatile("ldmatrix.sync.aligned.m8n8.x4.trans.shared.b16 {%0,%1,%2,%3}, [%4];"
                 : "=r"(r0), "=r"(r1), "=r"(r2), "=r"(r3) : "r"(addr));
}
__device__ __forceinline__ void mma16816(float* d, const uint32_t* a, uint32_t b0, uint32_t b1)
{
    asm volatile("mma.sync.aligned.m16n8k16.row.col.f32.bf16.bf16.f32 "
                 "{%0,%1,%2,%3}, {%4,%5,%6,%7}, {%8,%9}, {%0,%1,%2,%3};"
                 : "+f"(d[0]), "+f"(d[1]), "+f"(d[2]), "+f"(d[3])
                 : "r"(a[0]), "r"(a[1]), "r"(a[2]), "r"(a[3]), "r"(b0), "r"(b1));
}
__device__ __forceinline__ void cpa16(uint32_t dst, const void* src)
{
    asm volatile("cp.async.cg.shared.global [%0], [%1], 16;" :: "r"(dst), "l"(src));
}
#define CP_COMMIT() asm volatile("cp.async.commit_group;")
#define CP_WAIT(n)  asm volatile("cp.async.wait_group %0;" :: "n"(n))

// ---------------------------------------------------------------------------
// Mask normalization (unchanged, verified)
// ---------------------------------------------------------------------------
__global__ void mask_norm_kernel(const unsigned char* __restrict__ m)
{
    __shared__ int s_wide;
    __shared__ int s_bytes;
    if (threadIdx.x == 0) { s_wide = 0; s_bytes = 0; }
    __syncthreads();
    int wide = 0, bytes = 0;
    for (int i = threadIdx.x; i < BB*LL; i += blockDim.x) {
        unsigned char c = m[i];
        if (c > 1) wide = 1;
        else if (c != 0 && (i & 3) != 0) bytes = 1;
    }
    if (wide)  atomicOr(&s_wide, 1);
    if (bytes) atomicOr(&s_bytes, 1);
    __syncthreads();
    const bool is_u8 = (!s_wide) && s_bytes;
    for (int i = threadIdx.x; i < BB*LL; i += blockDim.x) {
        unsigned char v;
        if (is_u8) v = (m[i] != 0);
        else       v = (((const int*)m)[i] != 0);
        g_mask[i] = v;
    }
}

// ---------------------------------------------------------------------------
// split fp32 array -> bf16 hi/lo arrays
// ---------------------------------------------------------------------------
__global__ void split_arr(const float* __restrict__ in, bf16* __restrict__ oh,
                          bf16* __restrict__ ol, int n4)
{
    int i = blockIdx.x * blockDim.x + threadIdx.x;
    if (i >= n4) return;
    float4 v = ((const float4*)in)[i];
    uint32_t h0, l0, h1, l1;
    split2(v.x, v.y, h0, l0); split2(v.z, v.w, h1, l1);
    ((uint32_t*)oh)[2*i] = h0; ((uint32_t*)oh)[2*i+1] = h1;
    ((uint32_t*)ol)[2*i] = l0; ((uint32_t*)ol)[2*i+1] = l1;
}

// ---------------------------------------------------------------------------
// q transpose + split: [B][512 c][1024 hw] fp32 -> [B][1024 hw][512 c] bf16 h/l
// ---------------------------------------------------------------------------
__global__ void transpose_split_q(const float* __restrict__ in,
                                  bf16* __restrict__ oh, bf16* __restrict__ ol)
{
    __shared__ float t[32][33];
    int b = blockIdx.z;
    int hw0 = blockIdx.x * 32, c0 = blockIdx.y * 32;
    const float* ip = in + ((long)b * HID + c0) * HW + hw0;
#pragma unroll
    for (int j = 0; j < 32; j += 8)
        t[threadIdx.y + j][threadIdx.x] = ip[(long)(threadIdx.y + j) * HW + threadIdx.x];
    __syncthreads();
    long ob = ((long)b * HW + hw0) * HID + c0;
#pragma unroll
    for (int j = 0; j < 32; j += 8) {
        float v = t[threadIdx.x][threadIdx.y + j];
        bf16 h = __float2bfloat16_rn(v);
        bf16 l = __float2bfloat16_rn(v - __bfloat162float(h));
        long idx = ob + (long)(threadIdx.y + j) * HID + threadIdx.x;
        oh[idx] = h; ol[idx] = l;
    }
}

// ---------------------------------------------------------------------------
// split-bf16 tensor-core GEMM, pre-split operands, cp.async double-buffered.
// C[m,n] = post( sum_k A[m,k]*B[n,k] + bias )
// 128x128x32 tiles, 512 threads (16 warps, 4m x 4n), warp tile 32x32.
// SPLIT_OUT: write bf16 hi/lo pair arrays instead of fp32.
// ---------------------------------------------------------------------------
template<bool BIAS_N, bool RELU, bool SPLIT_OUT>
__global__ __launch_bounds__(512, 1)
void bgemm(const bf16* __restrict__ Ah, const bf16* __restrict__ Al,
           const bf16* __restrict__ Bh, const bf16* __restrict__ Bl,
           const float* __restrict__ bias,
           float* __restrict__ Cf, bf16* __restrict__ Ch, bf16* __restrict__ Cl,
           int M, int N, int K, long strideB, long strideC)
{
    extern __shared__ uint32_t sm[];   // [buf 2][op 4][2560 u32]  = 80 KB
    const int tid = threadIdx.x, lane = tid & 31, wid = tid >> 5;
    const int m0 = blockIdx.y * 128, n0 = blockIdx.x * 128;
    const int z = blockIdx.z;
    const int wm = (wid & 3) * 32, wn = (wid >> 2) * 32;
    const int arow = lane & 15, acol8 = (lane >> 4) * 8;
    const uint32_t sb = (uint32_t)__cvta_generic_to_shared(sm);

    const bf16* bph = Bh + (long)z * strideB;
    const bf16* bpl = Bl + (long)z * strideB;

    const int r = tid >> 2, ch = tid & 3;         // 128 rows x 4 chunks
    const uint32_t dstoff = (uint32_t)((r * 20 + ch * 4) * 4);

    auto issue = [&](int kb, int buf) {
        uint32_t base = sb + (uint32_t)(buf * 4 * 2560 * 4) + dstoff;
        long ao = (long)(m0 + r) * K + kb + ch * 8;
        long bo = (long)(n0 + r) * K + kb + ch * 8;
        cpa16(base,                 Ah  + ao);
        cpa16(base + 2560*4,        Al  + ao);
        cpa16(base + 2*2560*4,      bph + bo);
        cpa16(base + 3*2560*4,      bpl + bo);
    };

    float acc[2][4][4] = {};
    const int nk = K / 32;

    issue(0, 0); CP_COMMIT();
    for (int kb = 0; kb < nk; kb++) {
        if (kb + 1 < nk) { issue((kb + 1) * 32, (kb + 1) & 1); CP_COMMIT(); CP_WAIT(1); }
        else             { CP_WAIT(0); }
        __syncthreads();
        uint32_t bufb = sb + (uint32_t)((kb & 1) * 4 * 2560 * 4);
#pragma unroll
        for (int ks = 0; ks < 32; ks += 16) {
            uint32_t ah[2][4], al[2][4];
#pragma unroll
            for (int i = 0; i < 2; i++) {
                uint32_t off = (uint32_t)(((wm + 16 * i + arow) * 40 + ks + acol8) * 2);
                ldsm4(ah[i][0], ah[i][1], ah[i][2], ah[i][3], bufb + off);
                ldsm4(al[i][0], al[i][1], al[i][2], al[i][3], bufb + 2560*4 + off);
            }
#pragma unroll
            for (int jj = 0; jj < 2; jj++) {
                uint32_t bh[4], bl[4];
                uint32_t off = (uint32_t)(((wn + 16 * jj + arow) * 40 + ks + acol8) * 2);
                ldsm4(bh[0], bh[1], bh[2], bh[3], bufb + 2*2560*4 + off);
                ldsm4(bl[0], bl[1], bl[2], bl[3], bufb + 3*2560*4 + off);
#pragma unroll
                for (int i = 0; i < 2; i++) {
                    mma16816(acc[i][2*jj],   ah[i], bh[0], bh[2]);
                    mma16816(acc[i][2*jj],   ah[i], bl[0], bl[2]);
                    mma16816(acc[i][2*jj],   al[i], bh[0], bh[2]);
                    mma16816(acc[i][2*jj+1], ah[i], bh[1], bh[3]);
                    mma16816(acc[i][2*jj+1], ah[i], bl[1], bl[3]);
                    mma16816(acc[i][2*jj+1], al[i], bh[1], bh[3]);
                }
            }
        }
        __syncthreads();
    }

    const int g = lane >> 2, lam = lane & 3;
    float* cfp = Cf ? Cf + (long)z * strideC : (float*)0;
    bf16*  chp = Ch; bf16* clp = Cl;
#pragma unroll
    for (int i = 0; i < 2; i++) {
#pragma unroll
        for (int j = 0; j < 4; j++) {
            int row0 = m0 + wm + 16 * i + g;
            int col  = n0 + wn + 8 * j + 2 * lam;
            float b00, b01, b10, b11;
            if (BIAS_N) { b00 = bias[col]; b01 = bias[col + 1]; b10 = b00; b11 = b01; }
            else        { b00 = b01 = bias[row0]; b10 = b11 = bias[row0 + 8]; }
            float v00 = acc[i][j][0] + b00, v01 = acc[i][j][1] + b01;
            float v10 = acc[i][j][2] + b10, v11 = acc[i][j][3] + b11;
            if (RELU) {
                v00 = fmaxf(v00, 0.f); v01 = fmaxf(v01, 0.f);
                v10 = fmaxf(v10, 0.f); v11 = fmaxf(v11, 0.f);
            }
            if (SPLIT_OUT) {
                uint32_t h0, l0, h1, l1;
                split2(v00, v01, h0, l0);
                split2(v10, v11, h1, l1);
                *(uint32_t*)&chp[(long)row0 * N + col]       = h0;
                *(uint32_t*)&clp[(long)row0 * N + col]       = l0;
                *(uint32_t*)&chp[(long)(row0 + 8) * N + col] = h1;
                *(uint32_t*)&clp[(long)(row0 + 8) * N + col] = l1;
            } else {
                *(float2*)&cfp[(long)row0 * N + col]       = make_float2(v00, v01);
                *(float2*)&cfp[(long)(row0 + 8) * N + col] = make_float2(v10, v11);
            }
        }
    }
}

// ---------------------------------------------------------------------------
// Flash attention: Br=128 (8 warps x 16 rows), Bc=64, cp.async double-buffered
// K/V tiles, pre-split bf16 inputs, split bf16 output.
// 2 CTAs/SM (launch bounds) -> 16 warps/SM for latency hiding.
// Dynamic smem: QH(4608 u32)|QL(4608) then 2 x [KH|KL|VH|VL](2304 each)
// ---------------------------------------------------------------------------
__global__ __launch_bounds__(256, 2)
void attn_kernel()
{
    extern __shared__ uint32_t dsm[];
    __shared__ unsigned char s_maskAll[LL];
    const int tid = threadIdx.x, lane = tid & 31, wid = tid >> 5;
    const int b = blockIdx.z, h = blockIdx.y, q0 = blockIdx.x * 128;
    const int arow = lane & 15, acol8 = (lane >> 4) * 8;
    const int g = lane >> 2, lam = lane & 3;
    const uint32_t sb = (uint32_t)__cvta_generic_to_shared(dsm);
    const uint32_t KVB0 = 9216u * 4u;   // byte offset of KV buf 0
    const uint32_t KVSZ = 9216u * 4u;   // bytes per KV buffer
    const uint32_t OP   = 2304u * 4u;   // bytes per op within buffer

    // preload mask for this batch
    for (int i = tid; i < LL; i += 256) s_maskAll[i] = g_mask[b * LL + i];

    // ---- Q cp.async into QH/QL ----
    {
        int r = tid >> 1;
        long src = (long)(b * HW + q0 + r) * HID + h * DH;
        uint32_t dst = sb + (uint32_t)(r * 36 * 4);
#pragma unroll
        for (int cc = 0; cc < 4; cc++) {
            int chs = (tid & 1) * 4 + cc;
            cpa16(dst + chs * 16,             g_q_h + src + chs * 8);
            cpa16(dst + 4608*4 + chs * 16,    g_q_l + src + chs * 8);
        }
    }
    CP_COMMIT();

    auto issueKV = [&](int kt) {
        int r = tid >> 2;
        long src = (long)(b * LL + kt * 64 + r) * HID + h * DH;
        uint32_t dst = sb + KVB0 + (uint32_t)(kt & 1) * KVSZ + (uint32_t)(r * 36 * 4);
#pragma unroll
        for (int cc = 0; cc < 2; cc++) {
            int chs = (tid & 3) * 2 + cc;
            cpa16(dst +            chs * 16, g_k_h + src + chs * 8);
            cpa16(dst + OP       + chs * 16, g_k_l + src + chs * 8);
            cpa16(dst + 2u * OP  + chs * 16, g_v_h + src + chs * 8);
            cpa16(dst + 3u * OP  + chs * 16, g_v_l + src + chs * 8);
        }
    };
    issueKV(0); CP_COMMIT();

    // wait for Q (the KV0 group may still be pending), extract Q fragments
    CP_WAIT(1);
    __syncthreads();
    uint32_t qh[4][4], ql[4][4];
    {
        int m0w = wid * 16;
#pragma unroll
        for (int ks = 0; ks < 4; ks++) {
            uint32_t off = (uint32_t)(((m0w + arow) * 72 + ks * 16 + acol8) * 2);
            ldsm4(qh[ks][0], qh[ks][1], qh[ks][2], qh[ks][3], sb + off);
            ldsm4(ql[ks][0], ql[ks][1], ql[ks][2], ql[ks][3], sb + 4608*4 + off);
        }
    }

    float oacc[8][4] = {};
    float mr0 = -1e30f, mr1 = -1e30f, lr0 = 0.f, lr1 = 0.f;

    for (int kt = 0; kt < LL / 64; kt++) {
        if (kt + 1 < LL / 64) { issueKV(kt + 1); CP_COMMIT(); CP_WAIT(1); }
        else                  { CP_WAIT(0); }
        __syncthreads();
        const uint32_t kvb = sb + KVB0 + (uint32_t)(kt & 1) * KVSZ;
        const int k0g = kt * 64;

        // S = Q K^T (3-term split)
        float sacc[8][4] = {};
#pragma unroll
        for (int ks = 0; ks < 4; ks++) {
#pragma unroll
            for (int jj = 0; jj < 4; jj++) {
                uint32_t bh[4], bl[4];
                uint32_t off = (uint32_t)(((16 * jj + arow) * 72 + ks * 16 + acol8) * 2);
                ldsm4(bh[0], bh[1], bh[2], bh[3], kvb + off);
                ldsm4(bl[0], bl[1], bl[2], bl[3], kvb + OP + off);
                mma16816(sacc[2*jj],   qh[ks], bh[0], bh[2]);
                mma16816(sacc[2*jj],   qh[ks], bl[0], bl[2]);
                mma16816(sacc[2*jj],   ql[ks], bh[0], bh[2]);
                mma16816(sacc[2*jj+1], qh[ks], bh[1], bh[3]);
                mma16816(sacc[2*jj+1], qh[ks], bl[1], bl[3]);
                mma16816(sacc[2*jj+1], ql[ks], bh[1], bh[3]);
            }
        }

        // softmax (log2 domain)
        const float cscale = 0.1803368801f;
        float mn0 = mr0, mn1 = mr1;
#pragma unroll
        for (int j = 0; j < 8; j++) {
            int kc = 8 * j + 2 * lam;
            bool k0m = s_maskAll[k0g + kc] != 0, k1m = s_maskAll[k0g + kc + 1] != 0;
            sacc[j][0] = k0m ? -1e9f : sacc[j][0] * cscale;
            sacc[j][1] = k1m ? -1e9f : sacc[j][1] * cscale;
            sacc[j][2] = k0m ? -1e9f : sacc[j][2] * cscale;
            sacc[j][3] = k1m ? -1e9f : sacc[j][3] * cscale;
            mn0 = fmaxf(mn0, fmaxf(sacc[j][0], sacc[j][1]));
            mn1 = fmaxf(mn1, fmaxf(sacc[j][2], sacc[j][3]));
        }
        mn0 = fmaxf(mn0, __shfl_xor_sync(0xffffffffu, mn0, 1));
        mn0 = fmaxf(mn0, __shfl_xor_sync(0xffffffffu, mn0, 2));
        mn1 = fmaxf(mn1, __shfl_xor_sync(0xffffffffu, mn1, 1));
        mn1 = fmaxf(mn1, __shfl_xor_sync(0xffffffffu, mn1, 2));
        float cs0 = fexp2f(mr0 - mn0), cs1 = fexp2f(mr1 - mn1);
        mr0 = mn0; mr1 = mn1;
        float rs0 = 0.f, rs1 = 0.f;
        uint32_t ph[8][2], pl[8][2];
#pragma unroll
        for (int j = 0; j < 8; j++) {
            float p0 = fexp2f(sacc[j][0] - mn0);
            float p1 = fexp2f(sacc[j][1] - mn0);
            float p2 = fexp2f(sacc[j][2] - mn1);
            float p3 = fexp2f(sacc[j][3] - mn1);
            rs0 += p0 + p1; rs1 += p2 + p3;
            split2(p0, p1, ph[j][0], pl[j][0]);
            split2(p2, p3, ph[j][1], pl[j][1]);
        }
        rs0 += __shfl_xor_sync(0xffffffffu, rs0, 1);
        rs0 += __shfl_xor_sync(0xffffffffu, rs0, 2);
        rs1 += __shfl_xor_sync(0xffffffffu, rs1, 1);
        rs1 += __shfl_xor_sync(0xffffffffu, rs1, 2);
        lr0 = lr0 * cs0 + rs0;
        lr1 = lr1 * cs1 + rs1;
#pragma unroll
        for (int j = 0; j < 8; j++) {
            oacc[j][0] *= cs0; oacc[j][1] *= cs0;
            oacc[j][2] *= cs1; oacc[j][3] *= cs1;
        }

        // O += P V (3-term split)
#pragma unroll
        for (int s = 0; s < 4; s++) {
            uint32_t pah[4] = { ph[2*s][0], ph[2*s][1], ph[2*s+1][0], ph[2*s+1][1] };
            uint32_t pal[4] = { pl[2*s][0], pl[2*s][1], pl[2*s+1][0], pl[2*s+1][1] };
#pragma unroll
            for (int jj = 0; jj < 4; jj++) {
                uint32_t vh[4], vl[4];
                uint32_t off = (uint32_t)(((16 * s + arow) * 72 + jj * 16 + acol8) * 2);
                ldsm4t(vh[0], vh[1], vh[2], vh[3], kvb + 2u * OP + off);
                ldsm4t(vl[0], vl[1], vl[2], vl[3], kvb + 3u * OP + off);
                mma16816(oacc[2*jj],   pah, vh[0], vh[1]);
                mma16816(oacc[2*jj],   pah, vl[0], vl[1]);
                mma16816(oacc[2*jj],   pal, vh[0], vh[1]);
                mma16816(oacc[2*jj+1], pah, vh[2], vh[3]);
                mma16816(oacc[2*jj+1], pah, vl[2], vl[3]);
                mma16816(oacc[2*jj+1], pal, vh[2], vh[3]);
            }
        }
        __syncthreads();
    }

    // epilogue: write split bf16
    float i0 = 1.f / lr0, i1 = 1.f / lr1;
    int row0 = q0 + wid * 16 + g;
#pragma unroll
    for (int j = 0; j < 8; j++) {
        int d = 8 * j + 2 * lam;
        uint32_t h0, l0, h1, l1;
        split2(oacc[j][0] * i0, oacc[j][1] * i0, h0, l0);
        split2(oacc[j][2] * i1, oacc[j][3] * i1, h1, l1);
        long i0x = (long)(b * HW + row0) * HID + h * DH + d;
        long i1x = (long)(b * HW + row0 + 8) * HID + h * DH + d;
        *(uint32_t*)&g_ao_h[i0x] = h0; *(uint32_t*)&g_ao_l[i0x] = l0;
        *(uint32_t*)&g_ao_h[i1x] = h1; *(uint32_t*)&g_ao_l[i1x] = l1;
    }
}

// ---------------------------------------------------------------------------
extern "C" void kernel_launch(void* const* d_in, const int* in_sizes, int n_in,
                              void* d_out, int out_size)
{
    const float* v  = (const float*)d_in[0];
    const float* k  = (const float*)d_in[1];
    const float* q  = (const float*)d_in[2];
    const unsigned char* mask = (const unsigned char*)d_in[3];
    const float* Wv = (const float*)d_in[4];
    const float* bv = (const float*)d_in[5];
    const float* Wk = (const float*)d_in[6];
    const float* bk = (const float*)d_in[7];
    const float* Wq = (const float*)d_in[8];
    const float* bq = (const float*)d_in[9];
    const float* Wm = (const float*)d_in[10];
    const float* bm = (const float*)d_in[11];
    float* out = (float*)d_out;

    // symbol addresses
    bf16 *kin_h, *kin_l, *vin_h, *vin_l, *qt_h, *qt_l;
    bf16 *wk_h, *wk_l, *wv_h, *wv_l, *wq_h, *wq_l, *wm_h, *wm_l;
    bf16 *k_h, *k_l, *v_h, *v_l, *q_h, *q_l, *ao_h, *ao_l;
    cudaGetSymbolAddress((void**)&kin_h, g_kin_h); cudaGetSymbolAddress((void**)&kin_l, g_kin_l);
    cudaGetSymbolAddress((void**)&vin_h, g_vin_h); cudaGetSymbolAddress((void**)&vin_l, g_vin_l);
    cudaGetSymbolAddress((void**)&qt_h,  g_qt_h);  cudaGetSymbolAddress((void**)&qt_l,  g_qt_l);
    cudaGetSymbolAddress((void**)&wk_h,  g_wk_h);  cudaGetSymbolAddress((void**)&wk_l,  g_wk_l);
    cudaGetSymbolAddress((void**)&wv_h,  g_wv_h);  cudaGetSymbolAddress((void**)&wv_l,  g_wv_l);
    cudaGetSymbolAddress((void**)&wq_h,  g_wq_h);  cudaGetSymbolAddress((void**)&wq_l,  g_wq_l);
    cudaGetSymbolAddress((void**)&wm_h,  g_wm_h);  cudaGetSymbolAddress((void**)&wm_l,  g_wm_l);
    cudaGetSymbolAddress((void**)&k_h,   g_k_h);   cudaGetSymbolAddress((void**)&k_l,   g_k_l);
    cudaGetSymbolAddress((void**)&v_h,   g_v_h);   cudaGetSymbolAddress((void**)&v_l,   g_v_l);
    cudaGetSymbolAddress((void**)&q_h,   g_q_h);   cudaGetSymbolAddress((void**)&q_l,   g_q_l);
    cudaGetSymbolAddress((void**)&ao_h,  g_ao_h);  cudaGetSymbolAddress((void**)&ao_l,  g_ao_l);

    const int GEMM_SMEM = 2 * 4 * 2560 * 4;        // 81920
    const int ATTN_SMEM = (9216 + 2 * 9216) * 4;   // 110592
    cudaFuncSetAttribute((const void*)bgemm<true,  false, true >, cudaFuncAttributeMaxDynamicSharedMemorySize, GEMM_SMEM);
    cudaFuncSetAttribute((const void*)bgemm<false, true,  false>, cudaFuncAttributeMaxDynamicSharedMemorySize, GEMM_SMEM);
    cudaFuncSetAttribute((const void*)attn_kernel, cudaFuncAttributeMaxDynamicSharedMemorySize, ATTN_SMEM);

    mask_norm_kernel<<<1, 256>>>(mask);

    // pre-split inputs & weights
    split_arr<<<(BB*LL*HID/4 + 255)/256, 256>>>(k,  kin_h, kin_l, BB*LL*HID/4);
    split_arr<<<(BB*LL*HID/4 + 255)/256, 256>>>(v,  vin_h, vin_l, BB*LL*HID/4);
    split_arr<<<(HID*HID/4 + 255)/256, 256>>>(Wk, wk_h, wk_l, HID*HID/4);
    split_arr<<<(HID*HID/4 + 255)/256, 256>>>(Wv, wv_h, wv_l, HID*HID/4);
    split_arr<<<(HID*HID/4 + 255)/256, 256>>>(Wq, wq_h, wq_l, HID*HID/4);
    split_arr<<<(HID*HID/4 + 255)/256, 256>>>(Wm, wm_h, wm_l, HID*HID/4);
    transpose_split_q<<<dim3(HW/32, HID/32, BB), dim3(32, 8)>>>(q, qt_h, qt_l);

    // projections -> split outputs
    bgemm<true, false, true><<<dim3(HID/128, (BB*LL)/128, 1), 512, GEMM_SMEM>>>(
        kin_h, kin_l, wk_h, wk_l, bk, nullptr, k_h, k_l, BB*LL, HID, HID, 0, 0);
    bgemm<true, false, true><<<dim3(HID/128, (BB*LL)/128, 1), 512, GEMM_SMEM>>>(
        vin_h, vin_l, wv_h, wv_l, bv, nullptr, v_h, v_l, BB*LL, HID, HID, 0, 0);
    bgemm<true, false, true><<<dim3(HID/128, (BB*HW)/128, 1), 512, GEMM_SMEM>>>(
        qt_h, qt_l, wq_h, wq_l, bq, nullptr, q_h, q_l, BB*HW, HID, HID, 0, 0);

    // attention
    attn_kernel<<<dim3(HW/128, NH, BB), 256, ATTN_SMEM>>>();

    // output projection: per batch C[o][hw] = Wm[o][:]. ao[b][hw][:] + bm[o], relu
    bgemm<false, true, false><<<dim3(HW/128, 512/128, BB), 512, GEMM_SMEM>>>(
        wm_h, wm_l, ao_h, ao_l, bm, out, nullptr, nullptr,
        512, HW, HID, (long)HW * HID, (long)512 * HW);
}

// round 6
// speedup vs baseline: 1.0077x; 1.0077x over previous
#include <cuda_runtime.h>
#include <cuda_bf16.h>
#include <math.h>
#include <stdint.h>

#define BB   8
#define LL   1024
#define HW   1024
#define HID  512
#define NH   8
#define DH   64

typedef __nv_bfloat16 bf16;

// Persistent split-bf16 scratch (allocation-free rule: __device__ globals)
__device__ bf16 g_kin_h[BB*LL*HID],  g_kin_l[BB*LL*HID];
__device__ bf16 g_vin_h[BB*LL*HID],  g_vin_l[BB*LL*HID];
__device__ bf16 g_qt_h [BB*HW*HID],  g_qt_l [BB*HW*HID];
__device__ bf16 g_wk_h[HID*HID], g_wk_l[HID*HID];
__device__ bf16 g_wv_h[HID*HID], g_wv_l[HID*HID];
__device__ bf16 g_wq_h[HID*HID], g_wq_l[HID*HID];
__device__ bf16 g_wm_h[HID*HID], g_wm_l[HID*HID];
__device__ bf16 g_k_h[BB*LL*HID], g_k_l[BB*LL*HID];
__device__ bf16 g_v_h[BB*LL*HID], g_v_l[BB*LL*HID];
__device__ bf16 g_q_h[BB*HW*HID], g_q_l[BB*HW*HID];
__device__ bf16 g_ao_h[BB*HW*HID], g_ao_l[BB*HW*HID];
__device__ unsigned char g_mask[BB*LL];

// ---------------------------------------------------------------------------
// helpers
// ---------------------------------------------------------------------------
__device__ __forceinline__ void split2(float a, float b, uint32_t& h, uint32_t& l)
{
    __nv_bfloat162 hv = __floats2bfloat162_rn(a, b);
    float ra = a - __bfloat162float(hv.x);
    float rb = b - __bfloat162float(hv.y);
    __nv_bfloat162 lv = __floats2bfloat162_rn(ra, rb);
    h = *reinterpret_cast<uint32_t*>(&hv);
    l = *reinterpret_cast<uint32_t*>(&lv);
}

// fast exp2 on FMA pipe (x <= 0), rel err ~1e-6
__device__ __forceinline__ float fexp2f(float x)
{
    x = fmaxf(x, -126.0f);
    int   n = __float2int_rn(x);
    float f = x - (float)n;
    float p = 1.33336498e-3f;
    p = fmaf(p, f, 9.61817007e-3f);
    p = fmaf(p, f, 5.55041087e-2f);
    p = fmaf(p, f, 2.40226507e-1f);
    p = fmaf(p, f, 6.93147181e-1f);
    p = fmaf(p, f, 1.0f);
    return p * __int_as_float((n + 127) << 23);
}

__device__ __forceinline__ void ldsm4(uint32_t& r0, uint32_t& r1, uint32_t& r2, uint32_t& r3, uint32_t addr)
{
    asm volatile("ldmatrix.sync.aligned.m8n8.x4.shared.b16 {%0,%1,%2,%3}, [%4];"
                 : "=r"(r0), "=r"(r1), "=r"(r2), "=r"(r3) : "r"(addr));
}
__device__ __forceinline__ void ldsm4t(uint32_t& r0, uint32_t& r1, uint32_t& r2, uint32_t& r3, uint32_t addr)
{
    asm volatile("ldmatrix.sync.aligned.m8n8.x4.trans.shared.b16 {%0,%1,%2,%3}, [%4];"
                 : "=r"(r0), "=r"(r1), "=r"(r2), "=r"(r3) : "r"(addr));
}
__device__ __forceinline__ void mma16816(float* d, const uint32_t* a, uint32_t b0, uint32_t b1)
{
    asm volatile("mma.sync.aligned.m16n8k16.row.col.f32.bf16.bf16.f32 "
                 "{%0,%1,%2,%3}, {%4,%5,%6,%7}, {%8,%9}, {%0,%1,%2,%3};"
                 : "+f"(d[0]), "+f"(d[1]), "+f"(d[2]), "+f"(d[3])
                 : "r"(a[0]), "r"(a[1]), "r"(a[2]), "r"(a[3]), "r"(b0), "r"(b1));
}
__device__ __forceinline__ void cpa16(uint32_t dst, const void* src)
{
    asm volatile("cp.async.cg.shared.global [%0], [%1], 16;" :: "r"(dst), "l"(src));
}
#define CP_COMMIT() asm volatile("cp.async.commit_group;")
#define CP_WAIT(n)  asm volatile("cp.async.wait_group %0;" :: "n"(n))

// ---------------------------------------------------------------------------
// Mask normalization (unchanged, verified)
// ---------------------------------------------------------------------------
__global__ void mask_norm_kernel(const unsigned char* __restrict__ m)
{
    __shared__ int s_wide;
    __shared__ int s_bytes;
    if (threadIdx.x == 0) { s_wide = 0; s_bytes = 0; }
    __syncthreads();
    int wide = 0, bytes = 0;
    for (int i = threadIdx.x; i < BB*LL; i += blockDim.x) {
        unsigned char c = m[i];
        if (c > 1) wide = 1;
        else if (c != 0 && (i & 3) != 0) bytes = 1;
    }
    if (wide)  atomicOr(&s_wide, 1);
    if (bytes) atomicOr(&s_bytes, 1);
    __syncthreads();
    const bool is_u8 = (!s_wide) && s_bytes;
    for (int i = threadIdx.x; i < BB*LL; i += blockDim.x) {
        unsigned char v;
        if (is_u8) v = (m[i] != 0);
        else       v = (((const int*)m)[i] != 0);
        g_mask[i] = v;
    }
}

// ---------------------------------------------------------------------------
// split fp32 array -> bf16 hi/lo arrays
// ---------------------------------------------------------------------------
__global__ void split_arr(const float* __restrict__ in, bf16* __restrict__ oh,
                          bf16* __restrict__ ol, int n4)
{
    int i = blockIdx.x * blockDim.x + threadIdx.x;
    if (i >= n4) return;
    float4 v = ((const float4*)in)[i];
    uint32_t h0, l0, h1, l1;
    split2(v.x, v.y, h0, l0); split2(v.z, v.w, h1, l1);
    ((uint32_t*)oh)[2*i] = h0; ((uint32_t*)oh)[2*i+1] = h1;
    ((uint32_t*)ol)[2*i] = l0; ((uint32_t*)ol)[2*i+1] = l1;
}

// ---------------------------------------------------------------------------
// q transpose + split: [B][512 c][1024 hw] fp32 -> [B][1024 hw][512 c] bf16 h/l
// ---------------------------------------------------------------------------
__global__ void transpose_split_q(const float* __restrict__ in,
                                  bf16* __restrict__ oh, bf16* __restrict__ ol)
{
    __shared__ float t[32][33];
    int b = blockIdx.z;
    int hw0 = blockIdx.x * 32, c0 = blockIdx.y * 32;
    const float* ip = in + ((long)b * HID + c0) * HW + hw0;
#pragma unroll
    for (int j = 0; j < 32; j += 8)
        t[threadIdx.y + j][threadIdx.x] = ip[(long)(threadIdx.y + j) * HW + threadIdx.x];
    __syncthreads();
    long ob = ((long)b * HW + hw0) * HID + c0;
#pragma unroll
    for (int j = 0; j < 32; j += 8) {
        float v = t[threadIdx.x][threadIdx.y + j];
        bf16 h = __float2bfloat16_rn(v);
        bf16 l = __float2bfloat16_rn(v - __bfloat162float(h));
        long idx = ob + (long)(threadIdx.y + j) * HID + threadIdx.x;
        oh[idx] = h; ol[idx] = l;
    }
}

// ---------------------------------------------------------------------------
// split-bf16 tensor-core GEMM, pre-split operands, cp.async double-buffered.
// C[m,n] = post( sum_k A[m,k]*B[n,k] + bias )
// 128x128x32 tiles, 512 threads (16 warps, 4m x 4n), warp tile 32x32.
// SPLIT_OUT: write bf16 hi/lo pair arrays instead of fp32.
// ---------------------------------------------------------------------------
template<bool BIAS_N, bool RELU, bool SPLIT_OUT>
__global__ __launch_bounds__(512, 1)
void bgemm(const bf16* __restrict__ Ah, const bf16* __restrict__ Al,
           const bf16* __restrict__ Bh, const bf16* __restrict__ Bl,
           const float* __restrict__ bias,
           float* __restrict__ Cf, bf16* __restrict__ Ch, bf16* __restrict__ Cl,
           int M, int N, int K, long strideB, long strideC)
{
    extern __shared__ uint32_t sm[];   // [buf 2][op 4][2560 u32]  = 80 KB
    const int tid = threadIdx.x, lane = tid & 31, wid = tid >> 5;
    const int m0 = blockIdx.y * 128, n0 = blockIdx.x * 128;
    const int z = blockIdx.z;
    const int wm = (wid & 3) * 32, wn = (wid >> 2) * 32;
    const int arow = lane & 15, acol8 = (lane >> 4) * 8;
    const uint32_t sb = (uint32_t)__cvta_generic_to_shared(sm);

    const bf16* bph = Bh + (long)z * strideB;
    const bf16* bpl = Bl + (long)z * strideB;

    const int r = tid >> 2, ch = tid & 3;         // 128 rows x 4 chunks
    const uint32_t dstoff = (uint32_t)((r * 20 + ch * 4) * 4);

    auto issue = [&](int kb, int buf) {
        uint32_t base = sb + (uint32_t)(buf * 4 * 2560 * 4) + dstoff;
        long ao = (long)(m0 + r) * K + kb + ch * 8;
        long bo = (long)(n0 + r) * K + kb + ch * 8;
        cpa16(base,                 Ah  + ao);
        cpa16(base + 2560*4,        Al  + ao);
        cpa16(base + 2*2560*4,      bph + bo);
        cpa16(base + 3*2560*4,      bpl + bo);
    };

    float acc[2][4][4] = {};
    const int nk = K / 32;

    issue(0, 0); CP_COMMIT();
    for (int kb = 0; kb < nk; kb++) {
        if (kb + 1 < nk) { issue((kb + 1) * 32, (kb + 1) & 1); CP_COMMIT(); CP_WAIT(1); }
        else             { CP_WAIT(0); }
        __syncthreads();
        uint32_t bufb = sb + (uint32_t)((kb & 1) * 4 * 2560 * 4);
#pragma unroll
        for (int ks = 0; ks < 32; ks += 16) {
            uint32_t ah[2][4], al[2][4];
#pragma unroll
            for (int i = 0; i < 2; i++) {
                uint32_t off = (uint32_t)(((wm + 16 * i + arow) * 40 + ks + acol8) * 2);
                ldsm4(ah[i][0], ah[i][1], ah[i][2], ah[i][3], bufb + off);
                ldsm4(al[i][0], al[i][1], al[i][2], al[i][3], bufb + 2560*4 + off);
            }
#pragma unroll
            for (int jj = 0; jj < 2; jj++) {
                uint32_t bh[4], bl[4];
                uint32_t off = (uint32_t)(((wn + 16 * jj + arow) * 40 + ks + acol8) * 2);
                ldsm4(bh[0], bh[1], bh[2], bh[3], bufb + 2*2560*4 + off);
                ldsm4(bl[0], bl[1], bl[2], bl[3], bufb + 3*2560*4 + off);
#pragma unroll
                for (int i = 0; i < 2; i++) {
                    mma16816(acc[i][2*jj],   ah[i], bh[0], bh[2]);
                    mma16816(acc[i][2*jj],   ah[i], bl[0], bl[2]);
                    mma16816(acc[i][2*jj],   al[i], bh[0], bh[2]);
                    mma16816(acc[i][2*jj+1], ah[i], bh[1], bh[3]);
                    mma16816(acc[i][2*jj+1], ah[i], bl[1], bl[3]);
                    mma16816(acc[i][2*jj+1], al[i], bh[1], bh[3]);
                }
            }
        }
        __syncthreads();
    }

    const int g = lane >> 2, lam = lane & 3;
    float* cfp = Cf ? Cf + (long)z * strideC : (float*)0;
    bf16*  chp = Ch; bf16* clp = Cl;
#pragma unroll
    for (int i = 0; i < 2; i++) {
#pragma unroll
        for (int j = 0; j < 4; j++) {
            int row0 = m0 + wm + 16 * i + g;
            int col  = n0 + wn + 8 * j + 2 * lam;
            float b00, b01, b10, b11;
            if (BIAS_N) { b00 = bias[col]; b01 = bias[col + 1]; b10 = b00; b11 = b01; }
            else        { b00 = b01 = bias[row0]; b10 = b11 = bias[row0 + 8]; }
            float v00 = acc[i][j][0] + b00, v01 = acc[i][j][1] + b01;
            float v10 = acc[i][j][2] + b10, v11 = acc[i][j][3] + b11;
            if (RELU) {
                v00 = fmaxf(v00, 0.f); v01 = fmaxf(v01, 0.f);
                v10 = fmaxf(v10, 0.f); v11 = fmaxf(v11, 0.f);
            }
            if (SPLIT_OUT) {
                uint32_t h0, l0, h1, l1;
                split2(v00, v01, h0, l0);
                split2(v10, v11, h1, l1);
                *(uint32_t*)&chp[(long)row0 * N + col]       = h0;
                *(uint32_t*)&clp[(long)row0 * N + col]       = l0;
                *(uint32_t*)&chp[(long)(row0 + 8) * N + col] = h1;
                *(uint32_t*)&clp[(long)(row0 + 8) * N + col] = l1;
            } else {
                *(float2*)&cfp[(long)row0 * N + col]       = make_float2(v00, v01);
                *(float2*)&cfp[(long)(row0 + 8) * N + col] = make_float2(v10, v11);
            }
        }
    }
}

// ---------------------------------------------------------------------------
// Flash attention: Br=128 (8 warps x 16 rows), Bc=64, cp.async double-buffered
// K/V tiles, pre-split bf16 inputs, split bf16 output.
// 2 CTAs/SM (launch bounds) -> 16 warps/SM for latency hiding.
// Dynamic smem: QH(4608 u32)|QL(4608) then 2 x [KH|KL|VH|VL](2304 each)
// ---------------------------------------------------------------------------
__global__ __launch_bounds__(256, 2)
void attn_kernel()
{
    extern __shared__ uint32_t dsm[];
    __shared__ unsigned char s_maskAll[LL];
    const int tid = threadIdx.x, lane = tid & 31, wid = tid >> 5;
    const int b = blockIdx.z, h = blockIdx.y, q0 = blockIdx.x * 128;
    const int arow = lane & 15, acol8 = (lane >> 4) * 8;
    const int g = lane >> 2, lam = lane & 3;
    const uint32_t sb = (uint32_t)__cvta_generic_to_shared(dsm);
    const uint32_t KVB0 = 9216u * 4u;   // byte offset of KV buf 0
    const uint32_t KVSZ = 9216u * 4u;   // bytes per KV buffer
    const uint32_t OP   = 2304u * 4u;   // bytes per op within buffer

    // preload mask for this batch
    for (int i = tid; i < LL; i += 256) s_maskAll[i] = g_mask[b * LL + i];

    // ---- Q cp.async into QH/QL ----
    {
        int r = tid >> 1;
        long src = (long)(b * HW + q0 + r) * HID + h * DH;
        uint32_t dst = sb + (uint32_t)(r * 36 * 4);
#pragma unroll
        for (int cc = 0; cc < 4; cc++) {
            int chs = (tid & 1) * 4 + cc;
            cpa16(dst + chs * 16,             g_q_h + src + chs * 8);
            cpa16(dst + 4608*4 + chs * 16,    g_q_l + src + chs * 8);
        }
    }
    CP_COMMIT();

    auto issueKV = [&](int kt) {
        int r = tid >> 2;
        long src = (long)(b * LL + kt * 64 + r) * HID + h * DH;
        uint32_t dst = sb + KVB0 + (uint32_t)(kt & 1) * KVSZ + (uint32_t)(r * 36 * 4);
#pragma unroll
        for (int cc = 0; cc < 2; cc++) {
            int chs = (tid & 3) * 2 + cc;
            cpa16(dst +            chs * 16, g_k_h + src + chs * 8);
            cpa16(dst + OP       + chs * 16, g_k_l + src + chs * 8);
            cpa16(dst + 2u * OP  + chs * 16, g_v_h + src + chs * 8);
            cpa16(dst + 3u * OP  + chs * 16, g_v_l + src + chs * 8);
        }
    };
    issueKV(0); CP_COMMIT();

    // wait for Q (the KV0 group may still be pending), extract Q fragments
    CP_WAIT(1);
    __syncthreads();
    uint32_t qh[4][4], ql[4][4];
    {
        int m0w = wid * 16;
#pragma unroll
        for (int ks = 0; ks < 4; ks++) {
            uint32_t off = (uint32_t)(((m0w + arow) * 72 + ks * 16 + acol8) * 2);
            ldsm4(qh[ks][0], qh[ks][1], qh[ks][2], qh[ks][3], sb + off);
            ldsm4(ql[ks][0], ql[ks][1], ql[ks][2], ql[ks][3], sb + 4608*4 + off);
        }
    }

    float oacc[8][4] = {};
    float mr0 = -1e30f, mr1 = -1e30f, lr0 = 0.f, lr1 = 0.f;

    for (int kt = 0; kt < LL / 64; kt++) {
        if (kt + 1 < LL / 64) { issueKV(kt + 1); CP_COMMIT(); CP_WAIT(1); }
        else                  { CP_WAIT(0); }
        __syncthreads();
        const uint32_t kvb = sb + KVB0 + (uint32_t)(kt & 1) * KVSZ;
        const int k0g = kt * 64;

        // S = Q K^T (3-term split)
        float sacc[8][4] = {};
#pragma unroll
        for (int ks = 0; ks < 4; ks++) {
#pragma unroll
            for (int jj = 0; jj < 4; jj++) {
                uint32_t bh[4], bl[4];
                uint32_t off = (uint32_t)(((16 * jj + arow) * 72 + ks * 16 + acol8) * 2);
                ldsm4(bh[0], bh[1], bh[2], bh[3], kvb + off);
                ldsm4(bl[0], bl[1], bl[2], bl[3], kvb + OP + off);
                mma16816(sacc[2*jj],   qh[ks], bh[0], bh[2]);
                mma16816(sacc[2*jj],   qh[ks], bl[0], bl[2]);
                mma16816(sacc[2*jj],   ql[ks], bh[0], bh[2]);
                mma16816(sacc[2*jj+1], qh[ks], bh[1], bh[3]);
                mma16816(sacc[2*jj+1], qh[ks], bl[1], bl[3]);
                mma16816(sacc[2*jj+1], ql[ks], bh[1], bh[3]);
            }
        }

        // softmax (log2 domain)
        const float cscale = 0.1803368801f;
        float mn0 = mr0, mn1 = mr1;
#pragma unroll
        for (int j = 0; j < 8; j++) {
            int kc = 8 * j + 2 * lam;
            bool k0m = s_maskAll[k0g + kc] != 0, k1m = s_maskAll[k0g + kc + 1] != 0;
            sacc[j][0] = k0m ? -1e9f : sacc[j][0] * cscale;
            sacc[j][1] = k1m ? -1e9f : sacc[j][1] * cscale;
            sacc[j][2] = k0m ? -1e9f : sacc[j][2] * cscale;
            sacc[j][3] = k1m ? -1e9f : sacc[j][3] * cscale;
            mn0 = fmaxf(mn0, fmaxf(sacc[j][0], sacc[j][1]));
            mn1 = fmaxf(mn1, fmaxf(sacc[j][2], sacc[j][3]));
        }
        mn0 = fmaxf(mn0, __shfl_xor_sync(0xffffffffu, mn0, 1));
        mn0 = fmaxf(mn0, __shfl_xor_sync(0xffffffffu, mn0, 2));
        mn1 = fmaxf(mn1, __shfl_xor_sync(0xffffffffu, mn1, 1));
        mn1 = fmaxf(mn1, __shfl_xor_sync(0xffffffffu, mn1, 2));
        float cs0 = fexp2f(mr0 - mn0), cs1 = fexp2f(mr1 - mn1);
        mr0 = mn0; mr1 = mn1;
        float rs0 = 0.f, rs1 = 0.f;
        uint32_t ph[8][2], pl[8][2];
#pragma unroll
        for (int j = 0; j < 8; j++) {
            float p0 = fexp2f(sacc[j][0] - mn0);
            float p1 = fexp2f(sacc[j][1] - mn0);
            float p2 = fexp2f(sacc[j][2] - mn1);
            float p3 = fexp2f(sacc[j][3] - mn1);
            rs0 += p0 + p1; rs1 += p2 + p3;
            split2(p0, p1, ph[j][0], pl[j][0]);
            split2(p2, p3, ph[j][1], pl[j][1]);
        }
        rs0 += __shfl_xor_sync(0xffffffffu, rs0, 1);
        rs0 += __shfl_xor_sync(0xffffffffu, rs0, 2);
        rs1 += __shfl_xor_sync(0xffffffffu, rs1, 1);
        rs1 += __shfl_xor_sync(0xffffffffu, rs1, 2);
        lr0 = lr0 * cs0 + rs0;
        lr1 = lr1 * cs1 + rs1;
#pragma unroll
        for (int j = 0; j < 8; j++) {
            oacc[j][0] *= cs0; oacc[j][1] *= cs0;
            oacc[j][2] *= cs1; oacc[j][3] *= cs1;
        }

        // O += P V (3-term split)
#pragma unroll
        for (int s = 0; s < 4; s++) {
            uint32_t pah[4] = { ph[2*s][0], ph[2*s][1], ph[2*s+1][0], ph[2*s+1][1] };
            uint32_t pal[4] = { pl[2*s][0], pl[2*s][1], pl[2*s+1][0], pl[2*s+1][1] };
#pragma unroll
            for (int jj = 0; jj < 4; jj++) {
                uint32_t vh[4], vl[4];
                uint32_t off = (uint32_t)(((16 * s + arow) * 72 + jj * 16 + acol8) * 2);
                ldsm4t(vh[0], vh[1], vh[2], vh[3], kvb + 2u * OP + off);
                ldsm4t(vl[0], vl[1], vl[2], vl[3], kvb + 3u * OP + off);
                mma16816(oacc[2*jj],   pah, vh[0], vh[1]);
                mma16816(oacc[2*jj],   pah, vl[0], vl[1]);
                mma16816(oacc[2*jj],   pal, vh[0], vh[1]);
                mma16816(oacc[2*jj+1], pah, vh[2], vh[3]);
                mma16816(oacc[2*jj+1], pah, vl[2], vl[3]);
                mma16816(oacc[2*jj+1], pal, vh[2], vh[3]);
            }
        }
        __syncthreads();
    }

    // epilogue: write split bf16
    float i0 = 1.f / lr0, i1 = 1.f / lr1;
    int row0 = q0 + wid * 16 + g;
#pragma unroll
    for (int j = 0; j < 8; j++) {
        int d = 8 * j + 2 * lam;
        uint32_t h0, l0, h1, l1;
        split2(oacc[j][0] * i0, oacc[j][1] * i0, h0, l0);
        split2(oacc[j][2] * i1, oacc[j][3] * i1, h1, l1);
        long i0x = (long)(b * HW + row0) * HID + h * DH + d;
        long i1x = (long)(b * HW + row0 + 8) * HID + h * DH + d;
        *(uint32_t*)&g_ao_h[i0x] = h0; *(uint32_t*)&g_ao_l[i0x] = l0;
        *(uint32_t*)&g_ao_h[i1x] = h1; *(uint32_t*)&g_ao_l[i1x] = l1;
    }
}

// ---------------------------------------------------------------------------
extern "C" void kernel_launch(void* const* d_in, const int* in_sizes, int n_in,
                              void* d_out, int out_size)
{
    const float* v  = (const float*)d_in[0];
    const float* k  = (const float*)d_in[1];
    const float* q  = (const float*)d_in[2];
    const unsigned char* mask = (const unsigned char*)d_in[3];
    const float* Wv = (const float*)d_in[4];
    const float* bv = (const float*)d_in[5];
    const float* Wk = (const float*)d_in[6];
    const float* bk = (const float*)d_in[7];
    const float* Wq = (const float*)d_in[8];
    const float* bq = (const float*)d_in[9];
    const float* Wm = (const float*)d_in[10];
    const float* bm = (const float*)d_in[11];
    float* out = (float*)d_out;

    // symbol addresses
    bf16 *kin_h, *kin_l, *vin_h, *vin_l, *qt_h, *qt_l;
    bf16 *wk_h, *wk_l, *wv_h, *wv_l, *wq_h, *wq_l, *wm_h, *wm_l;
    bf16 *k_h, *k_l, *v_h, *v_l, *q_h, *q_l, *ao_h, *ao_l;
    cudaGetSymbolAddress((void**)&kin_h, g_kin_h); cudaGetSymbolAddress((void**)&kin_l, g_kin_l);
    cudaGetSymbolAddress((void**)&vin_h, g_vin_h); cudaGetSymbolAddress((void**)&vin_l, g_vin_l);
    cudaGetSymbolAddress((void**)&qt_h,  g_qt_h);  cudaGetSymbolAddress((void**)&qt_l,  g_qt_l);
    cudaGetSymbolAddress((void**)&wk_h,  g_wk_h);  cudaGetSymbolAddress((void**)&wk_l,  g_wk_l);
    cudaGetSymbolAddress((void**)&wv_h,  g_wv_h);  cudaGetSymbolAddress((void**)&wv_l,  g_wv_l);
    cudaGetSymbolAddress((void**)&wq_h,  g_wq_h);  cudaGetSymbolAddress((void**)&wq_l,  g_wq_l);
    cudaGetSymbolAddress((void**)&wm_h,  g_wm_h);  cudaGetSymbolAddress((void**)&wm_l,  g_wm_l);
    cudaGetSymbolAddress((void**)&k_h,   g_k_h);   cudaGetSymbolAddress((void**)&k_l,   g_k_l);
    cudaGetSymbolAddress((void**)&v_h,   g_v_h);   cudaGetSymbolAddress((void**)&v_l,   g_v_l);
    cudaGetSymbolAddress((void**)&q_h,   g_q_h);   cudaGetSymbolAddress((void**)&q_l,   g_q_l);
    cudaGetSymbolAddress((void**)&ao_h,  g_ao_h);  cudaGetSymbolAddress((void**)&ao_l,  g_ao_l);

    const int GEMM_SMEM = 2 * 4 * 2560 * 4;        // 81920
    const int ATTN_SMEM = (9216 + 2 * 9216) * 4;   // 110592
    cudaFuncSetAttribute((const void*)bgemm<true,  false, true >, cudaFuncAttributeMaxDynamicSharedMemorySize, GEMM_SMEM);
    cudaFuncSetAttribute((const void*)bgemm<false, true,  false>, cudaFuncAttributeMaxDynamicSharedMemorySize, GEMM_SMEM);
    cudaFuncSetAttribute((const void*)attn_kernel, cudaFuncAttributeMaxDynamicSharedMemorySize, ATTN_SMEM);

    mask_norm_kernel<<<1, 256>>>(mask);

    // pre-split inputs & weights
    split_arr<<<(BB*LL*HID/4 + 255)/256, 256>>>(k,  kin_h, kin_l, BB*LL*HID/4);
    split_arr<<<(BB*LL*HID/4 + 255)/256, 256>>>(v,  vin_h, vin_l, BB*LL*HID/4);
    split_arr<<<(HID*HID/4 + 255)/256, 256>>>(Wk, wk_h, wk_l, HID*HID/4);
    split_arr<<<(HID*HID/4 + 255)/256, 256>>>(Wv, wv_h, wv_l, HID*HID/4);
    split_arr<<<(HID*HID/4 + 255)/256, 256>>>(Wq, wq_h, wq_l, HID*HID/4);
    split_arr<<<(HID*HID/4 + 255)/256, 256>>>(Wm, wm_h, wm_l, HID*HID/4);
    transpose_split_q<<<dim3(HW/32, HID/32, BB), dim3(32, 8)>>>(q, qt_h, qt_l);

    // projections -> split outputs
    bgemm<true, false, true><<<dim3(HID/128, (BB*LL)/128, 1), 512, GEMM_SMEM>>>(
        kin_h, kin_l, wk_h, wk_l, bk, nullptr, k_h, k_l, BB*LL, HID, HID, 0, 0);
    bgemm<true, false, true><<<dim3(HID/128, (BB*LL)/128, 1), 512, GEMM_SMEM>>>(
        vin_h, vin_l, wv_h, wv_l, bv, nullptr, v_h, v_l, BB*LL, HID, HID, 0, 0);
    bgemm<true, false, true><<<dim3(HID/128, (BB*HW)/128, 1), 512, GEMM_SMEM>>>(
        qt_h, qt_l, wq_h, wq_l, bq, nullptr, q_h, q_l, BB*HW, HID, HID, 0, 0);

    // attention
    attn_kernel<<<dim3(HW/128, NH, BB), 256, ATTN_SMEM>>>();

    // output projection: per batch C[o][hw] = Wm[o][:]. ao[b][hw][:] + bm[o], relu
    bgemm<false, true, false><<<dim3(HW/128, 512/128, BB), 512, GEMM_SMEM>>>(
        wm_h, wm_l, ao_h, ao_l, bm, out, nullptr, nullptr,
        512, HW, HID, (long)HW * HID, (long)512 * HW);
}

// round 8
// speedup vs baseline: 1.1649x; 1.1560x over previous
#include <cuda_runtime.h>
#include <cuda_bf16.h>
#include <math.h>
#include <stdint.h>

#define BB   8
#define LL   1024
#define HW   1024
#define HID  512
#define NH   8
#define DH   64

typedef __nv_bfloat16 bf16;

// tiled-swizzled GEMM operands: [tile (row>>7)*8 + (k>>6)][128x64 SW128 16KB]
__device__ bf16 g_kin_h[BB*LL*HID],  g_kin_l[BB*LL*HID];
__device__ bf16 g_vin_h[BB*LL*HID],  g_vin_l[BB*LL*HID];
__device__ bf16 g_qt_h [BB*HW*HID],  g_qt_l [BB*HW*HID];
__device__ bf16 g_wk_h[HID*HID], g_wk_l[HID*HID];
__device__ bf16 g_wv_h[HID*HID], g_wv_l[HID*HID];
__device__ bf16 g_wq_h[HID*HID], g_wq_l[HID*HID];
__device__ bf16 g_wm_h[HID*HID], g_wm_l[HID*HID];
__device__ bf16 g_ao_h[BB*HW*HID], g_ao_l[BB*HW*HID];   // tiled
// row-major (attention I/O)
__device__ bf16 g_k_h[BB*LL*HID], g_k_l[BB*LL*HID];
__device__ bf16 g_v_h[BB*LL*HID], g_v_l[BB*LL*HID];
__device__ bf16 g_q_h[BB*HW*HID], g_q_l[BB*HW*HID];
__device__ unsigned char g_mask[BB*LL];

// ---------------- helpers ----------------
__device__ __forceinline__ void split2(float a, float b, uint32_t& h, uint32_t& l)
{
    __nv_bfloat162 hv = __floats2bfloat162_rn(a, b);
    float ra = a - __bfloat162float(hv.x);
    float rb = b - __bfloat162float(hv.y);
    __nv_bfloat162 lv = __floats2bfloat162_rn(ra, rb);
    h = *reinterpret_cast<uint32_t*>(&hv);
    l = *reinterpret_cast<uint32_t*>(&lv);
}
__device__ __forceinline__ float fexp2f(float x)
{
    x = fmaxf(x, -126.0f);
    int   n = __float2int_rn(x);
    float f = x - (float)n;
    float p = 1.33336498e-3f;
    p = fmaf(p, f, 9.61817007e-3f);
    p = fmaf(p, f, 5.55041087e-2f);
    p = fmaf(p, f, 2.40226507e-1f);
    p = fmaf(p, f, 6.93147181e-1f);
    p = fmaf(p, f, 1.0f);
    return p * __int_as_float((n + 127) << 23);
}
__device__ __forceinline__ void ldsm4(uint32_t& r0, uint32_t& r1, uint32_t& r2, uint32_t& r3, uint32_t a)
{
    asm volatile("ldmatrix.sync.aligned.m8n8.x4.shared.b16 {%0,%1,%2,%3}, [%4];"
                 : "=r"(r0), "=r"(r1), "=r"(r2), "=r"(r3) : "r"(a));
}
__device__ __forceinline__ void ldsm4t(uint32_t& r0, uint32_t& r1, uint32_t& r2, uint32_t& r3, uint32_t a)
{
    asm volatile("ldmatrix.sync.aligned.m8n8.x4.trans.shared.b16 {%0,%1,%2,%3}, [%4];"
                 : "=r"(r0), "=r"(r1), "=r"(r2), "=r"(r3) : "r"(a));
}
__device__ __forceinline__ void mma16816(float* d, const uint32_t* a, uint32_t b0, uint32_t b1)
{
    asm volatile("mma.sync.aligned.m16n8k16.row.col.f32.bf16.bf16.f32 "
                 "{%0,%1,%2,%3}, {%4,%5,%6,%7}, {%8,%9}, {%0,%1,%2,%3};"
                 : "+f"(d[0]), "+f"(d[1]), "+f"(d[2]), "+f"(d[3])
                 : "r"(a[0]), "r"(a[1]), "r"(a[2]), "r"(a[3]), "r"(b0), "r"(b1));
}
__device__ __forceinline__ void cpa16(uint32_t dst, const void* src)
{
    asm volatile("cp.async.ca.shared.global [%0], [%1], 16;" :: "r"(dst), "l"(src));
}
#define CP_COMMIT() asm volatile("cp.async.commit_group;")
#define CP_WAIT(n)  asm volatile("cp.async.wait_group %0;" :: "n"(n))

__device__ __forceinline__ uint32_t swz128(uint32_t o) { return o ^ ((o >> 3) & 0x70); }

__device__ __forceinline__ void mbar_init(uint32_t a, uint32_t c)
{ asm volatile("mbarrier.init.shared.b64 [%0], %1;" :: "r"(a), "r"(c) : "memory"); }
__device__ __forceinline__ void mbar_expect(uint32_t a, uint32_t bytes)
{ asm volatile("mbarrier.arrive.expect_tx.shared.b64 _, [%0], %1;" :: "r"(a), "r"(bytes) : "memory"); }
__device__ __forceinline__ void mbar_wait(uint32_t a, uint32_t par)
{
    asm volatile(
        "{\n\t.reg .pred P;\n"
        "W%=:\n\tmbarrier.try_wait.parity.acquire.cta.shared::cta.b64 P, [%0], %1, 0x989680;\n"
        "\t@P bra.uni D%=;\n\tbra.uni W%=;\nD%=:\n\t}"
        :: "r"(a), "r"(par) : "memory");
}
__device__ __forceinline__ void bulk_g2s(uint32_t dst, const void* src, uint32_t bytes, uint32_t mbar)
{
    asm volatile("cp.async.bulk.shared::cta.global.mbarrier::complete_tx::bytes [%0], [%1], %2, [%3];"
                 :: "r"(dst), "l"(src), "r"(bytes), "r"(mbar) : "memory");
}

// ---------------- mask normalization (verified) ----------------
__global__ void mask_norm_kernel(const unsigned char* __restrict__ m)
{
    __shared__ int s_wide, s_bytes;
    if (threadIdx.x == 0) { s_wide = 0; s_bytes = 0; }
    __syncthreads();
    int wide = 0, bytes = 0;
    for (int i = threadIdx.x; i < BB*LL; i += blockDim.x) {
        unsigned char c = m[i];
        if (c > 1) wide = 1;
        else if (c != 0 && (i & 3) != 0) bytes = 1;
    }
    if (wide)  atomicOr(&s_wide, 1);
    if (bytes) atomicOr(&s_bytes, 1);
    __syncthreads();
    const bool is_u8 = (!s_wide) && s_bytes;
    for (int i = threadIdx.x; i < BB*LL; i += blockDim.x) {
        unsigned char vv;
        if (is_u8) vv = (m[i] != 0);
        else       vv = (((const int*)m)[i] != 0);
        g_mask[i] = vv;
    }
}

// ---------------- split fp32 [R][512] -> tiled-swizzled bf16 h/l ----------------
__global__ void split_tiled(const float* __restrict__ in, bf16* __restrict__ oh,
                            bf16* __restrict__ ol, int nch)
{
    int i = blockIdx.x * blockDim.x + threadIdx.x;
    if (i >= nch) return;
    int row = i >> 6;
    int kc  = (i & 63) * 8;
    const float4* p = (const float4*)(in + (size_t)row * HID + kc);
    float4 a = p[0], b = p[1];
    uint32_t h0,l0,h1,l1,h2,l2,h3,l3;
    split2(a.x, a.y, h0, l0); split2(a.z, a.w, h1, l1);
    split2(b.x, b.y, h2, l2); split2(b.z, b.w, h3, l3);
    uint32_t o = swz128((uint32_t)((row & 127) * 128 + (kc & 63) * 2));
    size_t base = ((size_t)(row >> 7) * 8 + (kc >> 6)) * 16384 + o;
    *(uint4*)((char*)oh + base) = make_uint4(h0, h1, h2, h3);
    *(uint4*)((char*)ol + base) = make_uint4(l0, l1, l2, l3);
}

// ---------------- q transpose + split -> tiled ----------------
__global__ void transpose_split_q(const float* __restrict__ in,
                                  bf16* __restrict__ oh, bf16* __restrict__ ol)
{
    __shared__ float t[32][33];
    int b = blockIdx.z;
    int hw0 = blockIdx.x * 32, c0 = blockIdx.y * 32;
    const float* ip = in + ((long)b * HID + c0) * HW + hw0;
#pragma unroll
    for (int j = 0; j < 32; j += 8)
        t[threadIdx.y + j][threadIdx.x] = ip[(long)(threadIdx.y + j) * HW + threadIdx.x];
    __syncthreads();
#pragma unroll
    for (int j = 0; j < 32; j += 8) {
        float v = t[threadIdx.x][threadIdx.y + j];
        bf16 h = __float2bfloat16_rn(v);
        bf16 l = __float2bfloat16_rn(v - __bfloat162float(h));
        int rowg = b * HW + hw0 + threadIdx.y + j;
        int col  = c0 + threadIdx.x;
        uint32_t o = swz128((uint32_t)((rowg & 127) * 128 + (col & 63) * 2));
        size_t base = ((size_t)(rowg >> 7) * 8 + (col >> 6)) * 16384 + o;
        *(bf16*)((char*)oh + base) = h;
        *(bf16*)((char*)ol + base) = l;
    }
}

// ---------------------------------------------------------------------------
// Shared GEMM mainloop: bulk-copy pipelined loads, legacy bf16 mma, 3-term.
// CTA tile 128x128, K=512 in 8 stages of 64. smem: 2 x 64KB + 2 mbarriers.
// 8 warps: wm=(wid&1)*64, wn=(wid>>1)*32; acc[4][4][4] (verified R3 layout).
// ---------------------------------------------------------------------------
__device__ __forceinline__ void gemm_mainloop(
    const bf16* Ah, const bf16* Al, const bf16* Bh, const bf16* Bl,
    size_t at, size_t bt, uint32_t sb, int tid, int lane, int wid,
    float acc[4][4][4])
{
    const int wm = (wid & 1) * 64, wn = (wid >> 1) * 32;
    const int arow = lane & 15, acol8 = (lane >> 4) * 8;
    const uint32_t F0 = 131072u, F1 = 131080u;

    if (tid == 0) { mbar_init(sb + F0, 1); mbar_init(sb + F1, 1); }
    __syncthreads();
    if (tid == 0) {
        mbar_expect(sb + F0, 65536u);
        bulk_g2s(sb,           Ah + at * 8192, 16384u, sb + F0);
        bulk_g2s(sb + 16384u,  Al + at * 8192, 16384u, sb + F0);
        bulk_g2s(sb + 32768u,  Bh + bt * 8192, 16384u, sb + F0);
        bulk_g2s(sb + 49152u,  Bl + bt * 8192, 16384u, sb + F0);
        mbar_expect(sb + F1, 65536u);
        bulk_g2s(sb + 65536u,  Ah + (at + 1) * 8192, 16384u, sb + F1);
        bulk_g2s(sb + 81920u,  Al + (at + 1) * 8192, 16384u, sb + F1);
        bulk_g2s(sb + 98304u,  Bh + (bt + 1) * 8192, 16384u, sb + F1);
        bulk_g2s(sb + 114688u, Bl + (bt + 1) * 8192, 16384u, sb + F1);
    }
    for (int s = 0; s < 8; s++) {
        mbar_wait((s & 1) ? sb + F1 : sb + F0, (uint32_t)((s >> 1) & 1));
        uint32_t bb = sb + (uint32_t)(s & 1) * 65536u;
#pragma unroll
        for (int ks = 0; ks < 4; ks++) {
            const int kc = ks * 16 + acol8;
            uint32_t ah[4][4], al[4][4];
#pragma unroll
            for (int i = 0; i < 4; i++) {
                uint32_t off = swz128((uint32_t)(((wm + 16 * i + arow) << 7) + (kc << 1)));
                ldsm4(ah[i][0], ah[i][1], ah[i][2], ah[i][3], bb + off);
                ldsm4(al[i][0], al[i][1], al[i][2], al[i][3], bb + 16384u + off);
            }
#pragma unroll
            for (int jj = 0; jj < 2; jj++) {
                uint32_t bh[4], bl[4];
                uint32_t off = swz128((uint32_t)(((wn + 16 * jj + arow) << 7) + (kc << 1)));
                ldsm4(bh[0], bh[1], bh[2], bh[3], bb + 32768u + off);
                ldsm4(bl[0], bl[1], bl[2], bl[3], bb + 49152u + off);
#pragma unroll
                for (int i = 0; i < 4; i++) {
                    mma16816(acc[i][2*jj],   ah[i], bh[0], bh[2]);
                    mma16816(acc[i][2*jj],   ah[i], bl[0], bl[2]);
                    mma16816(acc[i][2*jj],   al[i], bh[0], bh[2]);
                    mma16816(acc[i][2*jj+1], ah[i], bh[1], bh[3]);
                    mma16816(acc[i][2*jj+1], ah[i], bl[1], bl[3]);
                    mma16816(acc[i][2*jj+1], al[i], bh[1], bh[3]);
                }
            }
        }
        __syncthreads();
        if (tid == 0 && s + 2 < 8) {
            uint32_t full = (s & 1) ? sb + F1 : sb + F0;
            uint32_t base = sb + (uint32_t)(s & 1) * 65536u;
            mbar_expect(full, 65536u);
            bulk_g2s(base,           Ah + (at + s + 2) * 8192, 16384u, full);
            bulk_g2s(base + 16384u,  Al + (at + s + 2) * 8192, 16384u, full);
            bulk_g2s(base + 32768u,  Bh + (bt + s + 2) * 8192, 16384u, full);
            bulk_g2s(base + 49152u,  Bl + (bt + s + 2) * 8192, 16384u, full);
        }
    }
}

// ---- fused k/v/q projections: z selects problem; split-bf16 row-major out ----
__global__ __launch_bounds__(256, 1)
void proj_gemm(const float* __restrict__ bk, const float* __restrict__ bv,
               const float* __restrict__ bq)
{
    extern __shared__ char smc[];
    const uint32_t sb = (uint32_t)__cvta_generic_to_shared(smc);
    const int tid = threadIdx.x, lane = tid & 31, wid = tid >> 5;
    const int m0 = blockIdx.y * 128, n0 = blockIdx.x * 128, z = blockIdx.z;

    const bf16 *Ah, *Al, *Bh, *Bl;
    bf16 *Ch, *Cl;
    const float* bias;
    if (z == 0)      { Ah = g_kin_h; Al = g_kin_l; Bh = g_wk_h; Bl = g_wk_l; Ch = g_k_h; Cl = g_k_l; bias = bk; }
    else if (z == 1) { Ah = g_vin_h; Al = g_vin_l; Bh = g_wv_h; Bl = g_wv_l; Ch = g_v_h; Cl = g_v_l; bias = bv; }
    else             { Ah = g_qt_h;  Al = g_qt_l;  Bh = g_wq_h; Bl = g_wq_l; Ch = g_q_h; Cl = g_q_l; bias = bq; }

    float acc[4][4][4] = {};
    gemm_mainloop(Ah, Al, Bh, Bl, (size_t)(m0 >> 7) * 8, (size_t)(n0 >> 7) * 8,
                  sb, tid, lane, wid, acc);

    const int wm = (wid & 1) * 64, wn = (wid >> 1) * 32;
    const int g = lane >> 2, lam = lane & 3;
#pragma unroll
    for (int i = 0; i < 4; i++) {
#pragma unroll
        for (int j = 0; j < 4; j++) {
            int row0 = m0 + wm + 16 * i + g;
            int col  = n0 + wn + 8 * j + 2 * lam;
            float b0 = bias[col], b1 = bias[col + 1];
            uint32_t h0, l0, h1, l1;
            split2(acc[i][j][0] + b0, acc[i][j][1] + b1, h0, l0);
            split2(acc[i][j][2] + b0, acc[i][j][3] + b1, h1, l1);
            *(uint32_t*)&Ch[(size_t)row0 * HID + col]       = h0;
            *(uint32_t*)&Cl[(size_t)row0 * HID + col]       = l0;
            *(uint32_t*)&Ch[(size_t)(row0 + 8) * HID + col] = h1;
            *(uint32_t*)&Cl[(size_t)(row0 + 8) * HID + col] = l1;
        }
    }
}

// ---- output projection: C[z][o][hw] = Wm[o][:] . ao[z][hw][:] + bm[o], relu ----
__global__ __launch_bounds__(256, 1)
void out_gemm(const float* __restrict__ bm, float* __restrict__ out)
{
    extern __shared__ char smc[];
    const uint32_t sb = (uint32_t)__cvta_generic_to_shared(smc);
    const int tid = threadIdx.x, lane = tid & 31, wid = tid >> 5;
    const int m0 = blockIdx.y * 128, n0 = blockIdx.x * 128, z = blockIdx.z;

    float acc[4][4][4] = {};
    gemm_mainloop(g_wm_h, g_wm_l, g_ao_h, g_ao_l,
                  (size_t)(m0 >> 7) * 8, (size_t)((z * HW + n0) >> 7) * 8,
                  sb, tid, lane, wid, acc);

    const int wm = (wid & 1) * 64, wn = (wid >> 1) * 32;
    const int g = lane >> 2, lam = lane & 3;
    float* cfp = out + (size_t)z * 512 * HW;
#pragma unroll
    for (int i = 0; i < 4; i++) {
#pragma unroll
        for (int j = 0; j < 4; j++) {
            int row0 = m0 + wm + 16 * i + g;
            int col  = n0 + wn + 8 * j + 2 * lam;
            float ba = bm[row0], bb2 = bm[row0 + 8];
            float v00 = fmaxf(acc[i][j][0] + ba, 0.f),  v01 = fmaxf(acc[i][j][1] + ba, 0.f);
            float v10 = fmaxf(acc[i][j][2] + bb2, 0.f), v11 = fmaxf(acc[i][j][3] + bb2, 0.f);
            *(float2*)&cfp[(size_t)row0 * HW + col]       = make_float2(v00, v01);
            *(float2*)&cfp[(size_t)(row0 + 8) * HW + col] = make_float2(v10, v11);
        }
    }
}

// ---------------------------------------------------------------------------
// Flash attention — R4-verified; epilogue writes tiled ao.
// ---------------------------------------------------------------------------
__global__ __launch_bounds__(256, 1)
void attn_kernel()
{
    extern __shared__ uint32_t dsm[];
    __shared__ unsigned char s_maskAll[LL];
    const int tid = threadIdx.x, lane = tid & 31, wid = tid >> 5;
    const int b = blockIdx.z, h = blockIdx.y, q0 = blockIdx.x * 128;
    const int arow = lane & 15, acol8 = (lane >> 4) * 8;
    const int g = lane >> 2, lam = lane & 3;
    const uint32_t sb = (uint32_t)__cvta_generic_to_shared(dsm);
    const uint32_t KVB0 = 9216u * 4u, KVSZ = 9216u * 4u, OP = 2304u * 4u;

    for (int i = tid; i < LL; i += 256) s_maskAll[i] = g_mask[b * LL + i];

    {
        int r = tid >> 1;
        long src = (long)(b * HW + q0 + r) * HID + h * DH;
        uint32_t dst = sb + (uint32_t)(r * 36 * 4);
#pragma unroll
        for (int cc = 0; cc < 4; cc++) {
            int chs = (tid & 1) * 4 + cc;
            cpa16(dst + chs * 16,           g_q_h + src + chs * 8);
            cpa16(dst + 18432u + chs * 16,  g_q_l + src + chs * 8);
        }
    }
    CP_COMMIT();

    auto issueKV = [&](int kt) {
        int r = tid >> 2;
        long src = (long)(b * LL + kt * 64 + r) * HID + h * DH;
        uint32_t dst = sb + KVB0 + (uint32_t)(kt & 1) * KVSZ + (uint32_t)(r * 36 * 4);
#pragma unroll
        for (int cc = 0; cc < 2; cc++) {
            int chs = (tid & 3) * 2 + cc;
            cpa16(dst +           chs * 16, g_k_h + src + chs * 8);
            cpa16(dst + OP      + chs * 16, g_k_l + src + chs * 8);
            cpa16(dst + 2u * OP + chs * 16, g_v_h + src + chs * 8);
            cpa16(dst + 3u * OP + chs * 16, g_v_l + src + chs * 8);
        }
    };
    issueKV(0); CP_COMMIT();

    CP_WAIT(1);
    __syncthreads();
    uint32_t qh[4][4], ql[4][4];
    {
        int m0w = wid * 16;
#pragma unroll
        for (int ks = 0; ks < 4; ks++) {
            uint32_t off = (uint32_t)(((m0w + arow) * 72 + ks * 16 + acol8) * 2);
            ldsm4(qh[ks][0], qh[ks][1], qh[ks][2], qh[ks][3], sb + off);
            ldsm4(ql[ks][0], ql[ks][1], ql[ks][2], ql[ks][3], sb + 18432u + off);
        }
    }

    float oacc[8][4] = {};
    float mr0 = -1e30f, mr1 = -1e30f, lr0 = 0.f, lr1 = 0.f;

    for (int kt = 0; kt < LL / 64; kt++) {
        if (kt + 1 < LL / 64) { issueKV(kt + 1); CP_COMMIT(); CP_WAIT(1); }
        else                  { CP_WAIT(0); }
        __syncthreads();
        const uint32_t kvb = sb + KVB0 + (uint32_t)(kt & 1) * KVSZ;
        const int k0g = kt * 64;

        float sacc[8][4] = {};
#pragma unroll
        for (int ks = 0; ks < 4; ks++) {
#pragma unroll
            for (int jj = 0; jj < 4; jj++) {
                uint32_t bh[4], bl[4];
                uint32_t off = (uint32_t)(((16 * jj + arow) * 72 + ks * 16 + acol8) * 2);
                ldsm4(bh[0], bh[1], bh[2], bh[3], kvb + off);
                ldsm4(bl[0], bl[1], bl[2], bl[3], kvb + OP + off);
                mma16816(sacc[2*jj],   qh[ks], bh[0], bh[2]);
                mma16816(sacc[2*jj],   qh[ks], bl[0], bl[2]);
                mma16816(sacc[2*jj],   ql[ks], bh[0], bh[2]);
                mma16816(sacc[2*jj+1], qh[ks], bh[1], bh[3]);
                mma16816(sacc[2*jj+1], qh[ks], bl[1], bl[3]);
                mma16816(sacc[2*jj+1], ql[ks], bh[1], bh[3]);
            }
        }

        const float cscale = 0.1803368801f;
        float mn0 = mr0, mn1 = mr1;
#pragma unroll
        for (int j = 0; j < 8; j++) {
            int kc = 8 * j + 2 * lam;
            bool k0m = s_maskAll[k0g + kc] != 0, k1m = s_maskAll[k0g + kc + 1] != 0;
            sacc[j][0] = k0m ? -1e9f : sacc[j][0] * cscale;
            sacc[j][1] = k1m ? -1e9f : sacc[j][1] * cscale;
            sacc[j][2] = k0m ? -1e9f : sacc[j][2] * cscale;
            sacc[j][3] = k1m ? -1e9f : sacc[j][3] * cscale;
            mn0 = fmaxf(mn0, fmaxf(sacc[j][0], sacc[j][1]));
            mn1 = fmaxf(mn1, fmaxf(sacc[j][2], sacc[j][3]));
        }
        mn0 = fmaxf(mn0, __shfl_xor_sync(0xffffffffu, mn0, 1));
        mn0 = fmaxf(mn0, __shfl_xor_sync(0xffffffffu, mn0, 2));
        mn1 = fmaxf(mn1, __shfl_xor_sync(0xffffffffu, mn1, 1));
        mn1 = fmaxf(mn1, __shfl_xor_sync(0xffffffffu, mn1, 2));
        float cs0 = fexp2f(mr0 - mn0), cs1 = fexp2f(mr1 - mn1);
        mr0 = mn0; mr1 = mn1;
        float rs0 = 0.f, rs1 = 0.f;
        uint32_t ph[8][2], pl[8][2];
#pragma unroll
        for (int j = 0; j < 8; j++) {
            float p0 = fexp2f(sacc[j][0] - mn0);
            float p1 = fexp2f(sacc[j][1] - mn0);
            float p2 = fexp2f(sacc[j][2] - mn1);
            float p3 = fexp2f(sacc[j][3] - mn1);
            rs0 += p0 + p1; rs1 += p2 + p3;
            split2(p0, p1, ph[j][0], pl[j][0]);
            split2(p2, p3, ph[j][1], pl[j][1]);
        }
        rs0 += __shfl_xor_sync(0xffffffffu, rs0, 1);
        rs0 += __shfl_xor_sync(0xffffffffu, rs0, 2);
        rs1 += __shfl_xor_sync(0xffffffffu, rs1, 1);
        rs1 += __shfl_xor_sync(0xffffffffu, rs1, 2);
        lr0 = lr0 * cs0 + rs0;
        lr1 = lr1 * cs1 + rs1;
#pragma unroll
        for (int j = 0; j < 8; j++) {
            oacc[j][0] *= cs0; oacc[j][1] *= cs0;
            oacc[j][2] *= cs1; oacc[j][3] *= cs1;
        }

#pragma unroll
        for (int s = 0; s < 4; s++) {
            uint32_t pah[4] = { ph[2*s][0], ph[2*s][1], ph[2*s+1][0], ph[2*s+1][1] };
            uint32_t pal[4] = { pl[2*s][0], pl[2*s][1], pl[2*s+1][0], pl[2*s+1][1] };
#pragma unroll
            for (int jj = 0; jj < 4; jj++) {
                uint32_t vh[4], vl[4];
                uint32_t off = (uint32_t)(((16 * s + arow) * 72 + jj * 16 + acol8) * 2);
                ldsm4t(vh[0], vh[1], vh[2], vh[3], kvb + 2u * OP + off);
                ldsm4t(vl[0], vl[1], vl[2], vl[3], kvb + 3u * OP + off);
                mma16816(oacc[2*jj],   pah, vh[0], vh[1]);
                mma16816(oacc[2*jj],   pah, vl[0], vl[1]);
                mma16816(oacc[2*jj],   pal, vh[0], vh[1]);
                mma16816(oacc[2*jj+1], pah, vh[2], vh[3]);
                mma16816(oacc[2*jj+1], pah, vl[2], vl[3]);
                mma16816(oacc[2*jj+1], pal, vh[2], vh[3]);
            }
        }
        __syncthreads();
    }

    // epilogue -> tiled ao (row-tile (b*HW+q0)>>7, k-tile h)
    float i0 = 1.f / lr0, i1 = 1.f / lr1;
    int row0 = q0 + wid * 16 + g;
    size_t tbase = ((size_t)b * HW + q0) * HID * 2 + (size_t)h * 16384;
#pragma unroll
    for (int j = 0; j < 8; j++) {
        int cin = 8 * j + 2 * lam;
        uint32_t h0, l0, h1, l1;
        split2(oacc[j][0] * i0, oacc[j][1] * i0, h0, l0);
        split2(oacc[j][2] * i1, oacc[j][3] * i1, h1, l1);
        uint32_t o0 = swz128((uint32_t)((row0 - q0) * 128 + cin * 2));
        uint32_t o1 = swz128((uint32_t)((row0 - q0 + 8) * 128 + cin * 2));
        *(uint32_t*)((char*)g_ao_h + tbase + o0) = h0;
        *(uint32_t*)((char*)g_ao_l + tbase + o0) = l0;
        *(uint32_t*)((char*)g_ao_h + tbase + o1) = h1;
        *(uint32_t*)((char*)g_ao_l + tbase + o1) = l1;
    }
}

// ---------------------------------------------------------------------------
extern "C" void kernel_launch(void* const* d_in, const int* in_sizes, int n_in,
                              void* d_out, int out_size)
{
    const float* v  = (const float*)d_in[0];
    const float* k  = (const float*)d_in[1];
    const float* q  = (const float*)d_in[2];
    const unsigned char* mask = (const unsigned char*)d_in[3];
    const float* Wv = (const float*)d_in[4];
    const float* bv = (const float*)d_in[5];
    const float* Wk = (const float*)d_in[6];
    const float* bk = (const float*)d_in[7];
    const float* Wq = (const float*)d_in[8];
    const float* bq = (const float*)d_in[9];
    const float* Wm = (const float*)d_in[10];
    const float* bm = (const float*)d_in[11];
    float* out = (float*)d_out;

    bf16 *kin_h,*kin_l,*vin_h,*vin_l,*qt_h,*qt_l;
    bf16 *wk_h,*wk_l,*wv_h,*wv_l,*wq_h,*wq_l,*wm_h,*wm_l;
    cudaGetSymbolAddress((void**)&kin_h, g_kin_h); cudaGetSymbolAddress((void**)&kin_l, g_kin_l);
    cudaGetSymbolAddress((void**)&vin_h, g_vin_h); cudaGetSymbolAddress((void**)&vin_l, g_vin_l);
    cudaGetSymbolAddress((void**)&qt_h,  g_qt_h);  cudaGetSymbolAddress((void**)&qt_l,  g_qt_l);
    cudaGetSymbolAddress((void**)&wk_h,  g_wk_h);  cudaGetSymbolAddress((void**)&wk_l,  g_wk_l);
    cudaGetSymbolAddress((void**)&wv_h,  g_wv_h);  cudaGetSymbolAddress((void**)&wv_l,  g_wv_l);
    cudaGetSymbolAddress((void**)&wq_h,  g_wq_h);  cudaGetSymbolAddress((void**)&wq_l,  g_wq_l);
    cudaGetSymbolAddress((void**)&wm_h,  g_wm_h);  cudaGetSymbolAddress((void**)&wm_l,  g_wm_l);

    const int GEMM_SMEM = 131072 + 16;
    const int ATTN_SMEM = (9216 + 2 * 9216) * 4;   // 110592
    cudaFuncSetAttribute((const void*)proj_gemm,  cudaFuncAttributeMaxDynamicSharedMemorySize, GEMM_SMEM);
    cudaFuncSetAttribute((const void*)out_gemm,   cudaFuncAttributeMaxDynamicSharedMemorySize, GEMM_SMEM);
    cudaFuncSetAttribute((const void*)attn_kernel, cudaFuncAttributeMaxDynamicSharedMemorySize, ATTN_SMEM);

    mask_norm_kernel<<<1, 256>>>(mask);

    split_tiled<<<(BB*LL*64 + 255)/256, 256>>>(k,  kin_h, kin_l, BB*LL*64);
    split_tiled<<<(BB*LL*64 + 255)/256, 256>>>(v,  vin_h, vin_l, BB*LL*64);
    split_tiled<<<(HID*64 + 255)/256, 256>>>(Wk, wk_h, wk_l, HID*64);
    split_tiled<<<(HID*64 + 255)/256, 256>>>(Wv, wv_h, wv_l, HID*64);
    split_tiled<<<(HID*64 + 255)/256, 256>>>(Wq, wq_h, wq_l, HID*64);
    split_tiled<<<(HID*64 + 255)/256, 256>>>(Wm, wm_h, wm_l, HID*64);
    transpose_split_q<<<dim3(HW/32, HID/32, BB), dim3(32, 8)>>>(q, qt_h, qt_l);

    // fused projections: z = {k, v, q}
    proj_gemm<<<dim3(HID/128, (BB*LL)/128, 3), 256, GEMM_SMEM>>>(bk, bv, bq);

    attn_kernel<<<dim3(HW/128, NH, BB), 256, ATTN_SMEM>>>();

    // output projection, batched over z
    out_gemm<<<dim3(HW/128, 512/128, BB), 256, GEMM_SMEM>>>(bm, out);
}

// round 9
// speedup vs baseline: 1.5385x; 1.3207x over previous
#include <cuda_runtime.h>
#include <cuda_bf16.h>
#include <cuda_fp16.h>
#include <math.h>
#include <stdint.h>

#define BB   8
#define LL   1024
#define HW   1024
#define HID  512
#define NH   8
#define DH   64

typedef __nv_bfloat16 bf16;

// tiled-swizzled GEMM operands: [tile (row>>7)*8 + (k>>6)][128x64 SW128 16KB]
__device__ bf16 g_kin_h[BB*LL*HID],  g_kin_l[BB*LL*HID];
__device__ bf16 g_vin_h[BB*LL*HID],  g_vin_l[BB*LL*HID];
__device__ bf16 g_qt_h [BB*HW*HID],  g_qt_l [BB*HW*HID];
__device__ bf16 g_wk_h[HID*HID], g_wk_l[HID*HID];
__device__ bf16 g_wv_h[HID*HID], g_wv_l[HID*HID];
__device__ bf16 g_wq_h[HID*HID], g_wq_l[HID*HID];
__device__ bf16 g_wm_h[HID*HID], g_wm_l[HID*HID];
__device__ bf16 g_ao_h[BB*HW*HID], g_ao_l[BB*HW*HID];   // tiled (out-proj B operand)
// fp16 row-major attention inputs
__device__ __half g_kf[BB*LL*HID];
__device__ __half g_vf[BB*LL*HID];
__device__ __half g_qf[BB*HW*HID];
__device__ unsigned char g_mask[BB*LL];

// ---------------- helpers ----------------
__device__ __forceinline__ void split2(float a, float b, uint32_t& h, uint32_t& l)
{
    __nv_bfloat162 hv = __floats2bfloat162_rn(a, b);
    float ra = a - __bfloat162float(hv.x);
    float rb = b - __bfloat162float(hv.y);
    __nv_bfloat162 lv = __floats2bfloat162_rn(ra, rb);
    h = *reinterpret_cast<uint32_t*>(&hv);
    l = *reinterpret_cast<uint32_t*>(&lv);
}
__device__ __forceinline__ uint32_t packh2(float a, float b)
{
    __half2 h = __floats2half2_rn(a, b);
    return *reinterpret_cast<uint32_t*>(&h);
}
__device__ __forceinline__ float fexp2f(float x)
{
    x = fmaxf(x, -126.0f);
    int   n = __float2int_rn(x);
    float f = x - (float)n;
    float p = 1.33336498e-3f;
    p = fmaf(p, f, 9.61817007e-3f);
    p = fmaf(p, f, 5.55041087e-2f);
    p = fmaf(p, f, 2.40226507e-1f);
    p = fmaf(p, f, 6.93147181e-1f);
    p = fmaf(p, f, 1.0f);
    return p * __int_as_float((n + 127) << 23);
}
__device__ __forceinline__ void ldsm4(uint32_t& r0, uint32_t& r1, uint32_t& r2, uint32_t& r3, uint32_t a)
{
    asm volatile("ldmatrix.sync.aligned.m8n8.x4.shared.b16 {%0,%1,%2,%3}, [%4];"
                 : "=r"(r0), "=r"(r1), "=r"(r2), "=r"(r3) : "r"(a));
}
__device__ __forceinline__ void ldsm4t(uint32_t& r0, uint32_t& r1, uint32_t& r2, uint32_t& r3, uint32_t a)
{
    asm volatile("ldmatrix.sync.aligned.m8n8.x4.trans.shared.b16 {%0,%1,%2,%3}, [%4];"
                 : "=r"(r0), "=r"(r1), "=r"(r2), "=r"(r3) : "r"(a));
}
__device__ __forceinline__ void mma16816(float* d, const uint32_t* a, uint32_t b0, uint32_t b1)
{
    asm volatile("mma.sync.aligned.m16n8k16.row.col.f32.bf16.bf16.f32 "
                 "{%0,%1,%2,%3}, {%4,%5,%6,%7}, {%8,%9}, {%0,%1,%2,%3};"
                 : "+f"(d[0]), "+f"(d[1]), "+f"(d[2]), "+f"(d[3])
                 : "r"(a[0]), "r"(a[1]), "r"(a[2]), "r"(a[3]), "r"(b0), "r"(b1));
}
__device__ __forceinline__ void mma16816h(float* d, const uint32_t* a, uint32_t b0, uint32_t b1)
{
    asm volatile("mma.sync.aligned.m16n8k16.row.col.f32.f16.f16.f32 "
                 "{%0,%1,%2,%3}, {%4,%5,%6,%7}, {%8,%9}, {%0,%1,%2,%3};"
                 : "+f"(d[0]), "+f"(d[1]), "+f"(d[2]), "+f"(d[3])
                 : "r"(a[0]), "r"(a[1]), "r"(a[2]), "r"(a[3]), "r"(b0), "r"(b1));
}
__device__ __forceinline__ void cpa16(uint32_t dst, const void* src)
{
    asm volatile("cp.async.ca.shared.global [%0], [%1], 16;" :: "r"(dst), "l"(src));
}
#define CP_COMMIT() asm volatile("cp.async.commit_group;")
#define CP_WAIT(n)  asm volatile("cp.async.wait_group %0;" :: "n"(n))

__device__ __forceinline__ uint32_t swz128(uint32_t o) { return o ^ ((o >> 3) & 0x70); }

__device__ __forceinline__ void mbar_init(uint32_t a, uint32_t c)
{ asm volatile("mbarrier.init.shared.b64 [%0], %1;" :: "r"(a), "r"(c) : "memory"); }
__device__ __forceinline__ void mbar_expect(uint32_t a, uint32_t bytes)
{ asm volatile("mbarrier.arrive.expect_tx.shared.b64 _, [%0], %1;" :: "r"(a), "r"(bytes) : "memory"); }
__device__ __forceinline__ void mbar_wait(uint32_t a, uint32_t par)
{
    asm volatile(
        "{\n\t.reg .pred P;\n"
        "W%=:\n\tmbarrier.try_wait.parity.acquire.cta.shared::cta.b64 P, [%0], %1, 0x989680;\n"
        "\t@P bra.uni D%=;\n\tbra.uni W%=;\nD%=:\n\t}"
        :: "r"(a), "r"(par) : "memory");
}
__device__ __forceinline__ void bulk_g2s(uint32_t dst, const void* src, uint32_t bytes, uint32_t mbar)
{
    asm volatile("cp.async.bulk.shared::cta.global.mbarrier::complete_tx::bytes [%0], [%1], %2, [%3];"
                 :: "r"(dst), "l"(src), "r"(bytes), "r"(mbar) : "memory");
}

// ---------------- mask normalization (verified) ----------------
__global__ void mask_norm_kernel(const unsigned char* __restrict__ m)
{
    __shared__ int s_wide, s_bytes;
    if (threadIdx.x == 0) { s_wide = 0; s_bytes = 0; }
    __syncthreads();
    int wide = 0, bytes = 0;
    for (int i = threadIdx.x; i < BB*LL; i += blockDim.x) {
        unsigned char c = m[i];
        if (c > 1) wide = 1;
        else if (c != 0 && (i & 3) != 0) bytes = 1;
    }
    if (wide)  atomicOr(&s_wide, 1);
    if (bytes) atomicOr(&s_bytes, 1);
    __syncthreads();
    const bool is_u8 = (!s_wide) && s_bytes;
    for (int i = threadIdx.x; i < BB*LL; i += blockDim.x) {
        unsigned char vv;
        if (is_u8) vv = (m[i] != 0);
        else       vv = (((const int*)m)[i] != 0);
        g_mask[i] = vv;
    }
}

// ---------------- split fp32 [R][512] -> tiled-swizzled bf16 h/l ----------------
__global__ void split_tiled(const float* __restrict__ in, bf16* __restrict__ oh,
                            bf16* __restrict__ ol, int nch)
{
    int i = blockIdx.x * blockDim.x + threadIdx.x;
    if (i >= nch) return;
    int row = i >> 6;
    int kc  = (i & 63) * 8;
    const float4* p = (const float4*)(in + (size_t)row * HID + kc);
    float4 a = p[0], b = p[1];
    uint32_t h0,l0,h1,l1,h2,l2,h3,l3;
    split2(a.x, a.y, h0, l0); split2(a.z, a.w, h1, l1);
    split2(b.x, b.y, h2, l2); split2(b.z, b.w, h3, l3);
    uint32_t o = swz128((uint32_t)((row & 127) * 128 + (kc & 63) * 2));
    size_t base = ((size_t)(row >> 7) * 8 + (kc >> 6)) * 16384 + o;
    *(uint4*)((char*)oh + base) = make_uint4(h0, h1, h2, h3);
    *(uint4*)((char*)ol + base) = make_uint4(l0, l1, l2, l3);
}

// ---------------- q transpose + split -> tiled ----------------
__global__ void transpose_split_q(const float* __restrict__ in,
                                  bf16* __restrict__ oh, bf16* __restrict__ ol)
{
    __shared__ float t[32][33];
    int b = blockIdx.z;
    int hw0 = blockIdx.x * 32, c0 = blockIdx.y * 32;
    const float* ip = in + ((long)b * HID + c0) * HW + hw0;
#pragma unroll
    for (int j = 0; j < 32; j += 8)
        t[threadIdx.y + j][threadIdx.x] = ip[(long)(threadIdx.y + j) * HW + threadIdx.x];
    __syncthreads();
#pragma unroll
    for (int j = 0; j < 32; j += 8) {
        float v = t[threadIdx.x][threadIdx.y + j];
        bf16 h = __float2bfloat16_rn(v);
        bf16 l = __float2bfloat16_rn(v - __bfloat162float(h));
        int rowg = b * HW + hw0 + threadIdx.y + j;
        int col  = c0 + threadIdx.x;
        uint32_t o = swz128((uint32_t)((rowg & 127) * 128 + (col & 63) * 2));
        size_t base = ((size_t)(rowg >> 7) * 8 + (col >> 6)) * 16384 + o;
        *(bf16*)((char*)oh + base) = h;
        *(bf16*)((char*)ol + base) = l;
    }
}

// ---------------------------------------------------------------------------
// Shared GEMM mainloop (verified R8): bulk-copy pipelined, 3-term bf16 mma.
// ---------------------------------------------------------------------------
__device__ __forceinline__ void gemm_mainloop(
    const bf16* Ah, const bf16* Al, const bf16* Bh, const bf16* Bl,
    size_t at, size_t bt, uint32_t sb, int tid, int lane, int wid,
    float acc[4][4][4])
{
    const int wm = (wid & 1) * 64, wn = (wid >> 1) * 32;
    const int arow = lane & 15, acol8 = (lane >> 4) * 8;
    const uint32_t F0 = 131072u, F1 = 131080u;

    if (tid == 0) { mbar_init(sb + F0, 1); mbar_init(sb + F1, 1); }
    __syncthreads();
    if (tid == 0) {
        mbar_expect(sb + F0, 65536u);
        bulk_g2s(sb,           Ah + at * 8192, 16384u, sb + F0);
        bulk_g2s(sb + 16384u,  Al + at * 8192, 16384u, sb + F0);
        bulk_g2s(sb + 32768u,  Bh + bt * 8192, 16384u, sb + F0);
        bulk_g2s(sb + 49152u,  Bl + bt * 8192, 16384u, sb + F0);
        mbar_expect(sb + F1, 65536u);
        bulk_g2s(sb + 65536u,  Ah + (at + 1) * 8192, 16384u, sb + F1);
        bulk_g2s(sb + 81920u,  Al + (at + 1) * 8192, 16384u, sb + F1);
        bulk_g2s(sb + 98304u,  Bh + (bt + 1) * 8192, 16384u, sb + F1);
        bulk_g2s(sb + 114688u, Bl + (bt + 1) * 8192, 16384u, sb + F1);
    }
    for (int s = 0; s < 8; s++) {
        mbar_wait((s & 1) ? sb + F1 : sb + F0, (uint32_t)((s >> 1) & 1));
        uint32_t bb = sb + (uint32_t)(s & 1) * 65536u;
#pragma unroll
        for (int ks = 0; ks < 4; ks++) {
            const int kc = ks * 16 + acol8;
            uint32_t ah[4][4], al[4][4];
#pragma unroll
            for (int i = 0; i < 4; i++) {
                uint32_t off = swz128((uint32_t)(((wm + 16 * i + arow) << 7) + (kc << 1)));
                ldsm4(ah[i][0], ah[i][1], ah[i][2], ah[i][3], bb + off);
                ldsm4(al[i][0], al[i][1], al[i][2], al[i][3], bb + 16384u + off);
            }
#pragma unroll
            for (int jj = 0; jj < 2; jj++) {
                uint32_t bh[4], bl[4];
                uint32_t off = swz128((uint32_t)(((wn + 16 * jj + arow) << 7) + (kc << 1)));
                ldsm4(bh[0], bh[1], bh[2], bh[3], bb + 32768u + off);
                ldsm4(bl[0], bl[1], bl[2], bl[3], bb + 49152u + off);
#pragma unroll
                for (int i = 0; i < 4; i++) {
                    mma16816(acc[i][2*jj],   ah[i], bh[0], bh[2]);
                    mma16816(acc[i][2*jj],   ah[i], bl[0], bl[2]);
                    mma16816(acc[i][2*jj],   al[i], bh[0], bh[2]);
                    mma16816(acc[i][2*jj+1], ah[i], bh[1], bh[3]);
                    mma16816(acc[i][2*jj+1], ah[i], bl[1], bl[3]);
                    mma16816(acc[i][2*jj+1], al[i], bh[1], bh[3]);
                }
            }
        }
        __syncthreads();
        if (tid == 0 && s + 2 < 8) {
            uint32_t full = (s & 1) ? sb + F1 : sb + F0;
            uint32_t base = sb + (uint32_t)(s & 1) * 65536u;
            mbar_expect(full, 65536u);
            bulk_g2s(base,           Ah + (at + s + 2) * 8192, 16384u, full);
            bulk_g2s(base + 16384u,  Al + (at + s + 2) * 8192, 16384u, full);
            bulk_g2s(base + 32768u,  Bh + (bt + s + 2) * 8192, 16384u, full);
            bulk_g2s(base + 49152u,  Bl + (bt + s + 2) * 8192, 16384u, full);
        }
    }
}

// ---- fused k/v/q projections: z selects problem; fp16 row-major out ----
__global__ __launch_bounds__(256, 1)
void proj_gemm(const float* __restrict__ bk, const float* __restrict__ bv,
               const float* __restrict__ bq)
{
    extern __shared__ char smc[];
    const uint32_t sb = (uint32_t)__cvta_generic_to_shared(smc);
    const int tid = threadIdx.x, lane = tid & 31, wid = tid >> 5;
    const int m0 = blockIdx.y * 128, n0 = blockIdx.x * 128, z = blockIdx.z;

    const bf16 *Ah, *Al, *Bh, *Bl;
    __half* Cfp;
    const float* bias;
    if (z == 0)      { Ah = g_kin_h; Al = g_kin_l; Bh = g_wk_h; Bl = g_wk_l; Cfp = g_kf; bias = bk; }
    else if (z == 1) { Ah = g_vin_h; Al = g_vin_l; Bh = g_wv_h; Bl = g_wv_l; Cfp = g_vf; bias = bv; }
    else             { Ah = g_qt_h;  Al = g_qt_l;  Bh = g_wq_h; Bl = g_wq_l; Cfp = g_qf; bias = bq; }

    float acc[4][4][4] = {};
    gemm_mainloop(Ah, Al, Bh, Bl, (size_t)(m0 >> 7) * 8, (size_t)(n0 >> 7) * 8,
                  sb, tid, lane, wid, acc);

    const int wm = (wid & 1) * 64, wn = (wid >> 1) * 32;
    const int g = lane >> 2, lam = lane & 3;
#pragma unroll
    for (int i = 0; i < 4; i++) {
#pragma unroll
        for (int j = 0; j < 4; j++) {
            int row0 = m0 + wm + 16 * i + g;
            int col  = n0 + wn + 8 * j + 2 * lam;
            float b0 = bias[col], b1 = bias[col + 1];
            *(uint32_t*)&Cfp[(size_t)row0 * HID + col]       = packh2(acc[i][j][0] + b0, acc[i][j][1] + b1);
            *(uint32_t*)&Cfp[(size_t)(row0 + 8) * HID + col] = packh2(acc[i][j][2] + b0, acc[i][j][3] + b1);
        }
    }
}

// ---- output projection (verified R8): C[z][o][hw] = Wm . ao^T + bm, relu ----
__global__ __launch_bounds__(256, 1)
void out_gemm(const float* __restrict__ bm, float* __restrict__ out)
{
    extern __shared__ char smc[];
    const uint32_t sb = (uint32_t)__cvta_generic_to_shared(smc);
    const int tid = threadIdx.x, lane = tid & 31, wid = tid >> 5;
    const int m0 = blockIdx.y * 128, n0 = blockIdx.x * 128, z = blockIdx.z;

    float acc[4][4][4] = {};
    gemm_mainloop(g_wm_h, g_wm_l, g_ao_h, g_ao_l,
                  (size_t)(m0 >> 7) * 8, (size_t)((z * HW + n0) >> 7) * 8,
                  sb, tid, lane, wid, acc);

    const int wm = (wid & 1) * 64, wn = (wid >> 1) * 32;
    const int g = lane >> 2, lam = lane & 3;
    float* cfp = out + (size_t)z * 512 * HW;
#pragma unroll
    for (int i = 0; i < 4; i++) {
#pragma unroll
        for (int j = 0; j < 4; j++) {
            int row0 = m0 + wm + 16 * i + g;
            int col  = n0 + wn + 8 * j + 2 * lam;
            float ba = bm[row0], bb2 = bm[row0 + 8];
            float v00 = fmaxf(acc[i][j][0] + ba, 0.f),  v01 = fmaxf(acc[i][j][1] + ba, 0.f);
            float v10 = fmaxf(acc[i][j][2] + bb2, 0.f), v11 = fmaxf(acc[i][j][3] + bb2, 0.f);
            *(float2*)&cfp[(size_t)row0 * HW + col]       = make_float2(v00, v01);
            *(float2*)&cfp[(size_t)(row0 + 8) * HW + col] = make_float2(v10, v11);
        }
    }
}

// ---------------------------------------------------------------------------
// Flash attention, fp16 single-precision operands (error-budgeted), Br=128,
// Bc=64, double-buffered K/V, 2 CTAs/SM. Epilogue -> tiled split-bf16 ao.
// smem: Q 18432 B | 2 x [K 9216 | V 9216]
// ---------------------------------------------------------------------------
__global__ __launch_bounds__(256, 2)
void attn_kernel()
{
    extern __shared__ uint32_t dsm[];
    __shared__ unsigned char s_maskAll[LL];
    const int tid = threadIdx.x, lane = tid & 31, wid = tid >> 5;
    const int b = blockIdx.z, h = blockIdx.y, q0 = blockIdx.x * 128;
    const int arow = lane & 15, acol8 = (lane >> 4) * 8;
    const int g = lane >> 2, lam = lane & 3;
    const uint32_t sb = (uint32_t)__cvta_generic_to_shared(dsm);
    const uint32_t KVB0 = 18432u, KVSZ = 18432u, VOFF = 9216u;

    for (int i = tid; i < LL; i += 256) s_maskAll[i] = g_mask[b * LL + i];

    // Q: 128 rows x 64 fp16, row stride 72 halves (144 B)
    {
        int r = tid >> 1;
        long src = (long)(b * HW + q0 + r) * HID + h * DH;
        uint32_t dst = sb + (uint32_t)(r * 144);
#pragma unroll
        for (int cc = 0; cc < 4; cc++) {
            int chs = (tid & 1) * 4 + cc;
            cpa16(dst + chs * 16, g_qf + src + chs * 8);
        }
    }
    CP_COMMIT();

    auto issueKV = [&](int kt) {
        int r = tid >> 2;
        long src = (long)(b * LL + kt * 64 + r) * HID + h * DH;
        uint32_t dst = sb + KVB0 + (uint32_t)(kt & 1) * KVSZ + (uint32_t)(r * 144);
#pragma unroll
        for (int cc = 0; cc < 2; cc++) {
            int chs = (tid & 3) * 2 + cc;
            cpa16(dst +        chs * 16, g_kf + src + chs * 8);
            cpa16(dst + VOFF + chs * 16, g_vf + src + chs * 8);
        }
    };
    issueKV(0); CP_COMMIT();

    CP_WAIT(1);
    __syncthreads();
    uint32_t qh[4][4];
    {
        int m0w = wid * 16;
#pragma unroll
        for (int ks = 0; ks < 4; ks++) {
            uint32_t off = (uint32_t)(((m0w + arow) * 72 + ks * 16 + acol8) * 2);
            ldsm4(qh[ks][0], qh[ks][1], qh[ks][2], qh[ks][3], sb + off);
        }
    }

    float oacc[8][4] = {};
    float mr0 = -1e30f, mr1 = -1e30f, lr0 = 0.f, lr1 = 0.f;

    for (int kt = 0; kt < LL / 64; kt++) {
        if (kt + 1 < LL / 64) { issueKV(kt + 1); CP_COMMIT(); CP_WAIT(1); }
        else                  { CP_WAIT(0); }
        __syncthreads();
        const uint32_t kvb = sb + KVB0 + (uint32_t)(kt & 1) * KVSZ;
        const int k0g = kt * 64;

        // S = Q K^T (fp16)
        float sacc[8][4] = {};
#pragma unroll
        for (int ks = 0; ks < 4; ks++) {
#pragma unroll
            for (int jj = 0; jj < 4; jj++) {
                uint32_t bh[4];
                uint32_t off = (uint32_t)(((16 * jj + arow) * 72 + ks * 16 + acol8) * 2);
                ldsm4(bh[0], bh[1], bh[2], bh[3], kvb + off);
                mma16816h(sacc[2*jj],   qh[ks], bh[0], bh[2]);
                mma16816h(sacc[2*jj+1], qh[ks], bh[1], bh[3]);
            }
        }

        // softmax (log2 domain)
        const float cscale = 0.1803368801f;
        float mn0 = mr0, mn1 = mr1;
#pragma unroll
        for (int j = 0; j < 8; j++) {
            int kc = 8 * j + 2 * lam;
            bool k0m = s_maskAll[k0g + kc] != 0, k1m = s_maskAll[k0g + kc + 1] != 0;
            sacc[j][0] = k0m ? -1e9f : sacc[j][0] * cscale;
            sacc[j][1] = k1m ? -1e9f : sacc[j][1] * cscale;
            sacc[j][2] = k0m ? -1e9f : sacc[j][2] * cscale;
            sacc[j][3] = k1m ? -1e9f : sacc[j][3] * cscale;
            mn0 = fmaxf(mn0, fmaxf(sacc[j][0], sacc[j][1]));
            mn1 = fmaxf(mn1, fmaxf(sacc[j][2], sacc[j][3]));
        }
        mn0 = fmaxf(mn0, __shfl_xor_sync(0xffffffffu, mn0, 1));
        mn0 = fmaxf(mn0, __shfl_xor_sync(0xffffffffu, mn0, 2));
        mn1 = fmaxf(mn1, __shfl_xor_sync(0xffffffffu, mn1, 1));
        mn1 = fmaxf(mn1, __shfl_xor_sync(0xffffffffu, mn1, 2));
        float cs0 = fexp2f(mr0 - mn0), cs1 = fexp2f(mr1 - mn1);
        mr0 = mn0; mr1 = mn1;
        float rs0 = 0.f, rs1 = 0.f;
        uint32_t ph[8][2];
#pragma unroll
        for (int j = 0; j < 8; j++) {
            float p0 = fexp2f(sacc[j][0] - mn0);
            float p1 = fexp2f(sacc[j][1] - mn0);
            float p2 = fexp2f(sacc[j][2] - mn1);
            float p3 = fexp2f(sacc[j][3] - mn1);
            rs0 += p0 + p1; rs1 += p2 + p3;
            ph[j][0] = packh2(p0, p1);
            ph[j][1] = packh2(p2, p3);
        }
        rs0 += __shfl_xor_sync(0xffffffffu, rs0, 1);
        rs0 += __shfl_xor_sync(0xffffffffu, rs0, 2);
        rs1 += __shfl_xor_sync(0xffffffffu, rs1, 1);
        rs1 += __shfl_xor_sync(0xffffffffu, rs1, 2);
        lr0 = lr0 * cs0 + rs0;
        lr1 = lr1 * cs1 + rs1;
#pragma unroll
        for (int j = 0; j < 8; j++) {
            oacc[j][0] *= cs0; oacc[j][1] *= cs0;
            oacc[j][2] *= cs1; oacc[j][3] *= cs1;
        }

        // O += P V (fp16)
#pragma unroll
        for (int s = 0; s < 4; s++) {
            uint32_t pah[4] = { ph[2*s][0], ph[2*s][1], ph[2*s+1][0], ph[2*s+1][1] };
#pragma unroll
            for (int jj = 0; jj < 4; jj++) {
                uint32_t vh[4];
                uint32_t off = (uint32_t)(((16 * s + arow) * 72 + jj * 16 + acol8) * 2);
                ldsm4t(vh[0], vh[1], vh[2], vh[3], kvb + VOFF + off);
                mma16816h(oacc[2*jj],   pah, vh[0], vh[1]);
                mma16816h(oacc[2*jj+1], pah, vh[2], vh[3]);
            }
        }
        __syncthreads();
    }

    // epilogue -> tiled split-bf16 ao (row-tile (b*HW+q0)>>7, k-tile h)
    float i0 = 1.f / lr0, i1 = 1.f / lr1;
    int row0 = q0 + wid * 16 + g;
    size_t tbase = ((size_t)b * HW + q0) * HID * 2 + (size_t)h * 16384;
#pragma unroll
    for (int j = 0; j < 8; j++) {
        int cin = 8 * j + 2 * lam;
        uint32_t h0, l0, h1, l1;
        split2(oacc[j][0] * i0, oacc[j][1] * i0, h0, l0);
        split2(oacc[j][2] * i1, oacc[j][3] * i1, h1, l1);
        uint32_t o0 = swz128((uint32_t)((row0 - q0) * 128 + cin * 2));
        uint32_t o1 = swz128((uint32_t)((row0 - q0 + 8) * 128 + cin * 2));
        *(uint32_t*)((char*)g_ao_h + tbase + o0) = h0;
        *(uint32_t*)((char*)g_ao_l + tbase + o0) = l0;
        *(uint32_t*)((char*)g_ao_h + tbase + o1) = h1;
        *(uint32_t*)((char*)g_ao_l + tbase + o1) = l1;
    }
}

// ---------------------------------------------------------------------------
extern "C" void kernel_launch(void* const* d_in, const int* in_sizes, int n_in,
                              void* d_out, int out_size)
{
    const float* v  = (const float*)d_in[0];
    const float* k  = (const float*)d_in[1];
    const float* q  = (const float*)d_in[2];
    const unsigned char* mask = (const unsigned char*)d_in[3];
    const float* Wv = (const float*)d_in[4];
    const float* bv = (const float*)d_in[5];
    const float* Wk = (const float*)d_in[6];
    const float* bk = (const float*)d_in[7];
    const float* Wq = (const float*)d_in[8];
    const float* bq = (const float*)d_in[9];
    const float* Wm = (const float*)d_in[10];
    const float* bm = (const float*)d_in[11];
    float* out = (float*)d_out;

    bf16 *kin_h,*kin_l,*vin_h,*vin_l,*qt_h,*qt_l;
    bf16 *wk_h,*wk_l,*wv_h,*wv_l,*wq_h,*wq_l,*wm_h,*wm_l;
    cudaGetSymbolAddress((void**)&kin_h, g_kin_h); cudaGetSymbolAddress((void**)&kin_l, g_kin_l);
    cudaGetSymbolAddress((void**)&vin_h, g_vin_h); cudaGetSymbolAddress((void**)&vin_l, g_vin_l);
    cudaGetSymbolAddress((void**)&qt_h,  g_qt_h);  cudaGetSymbolAddress((void**)&qt_l,  g_qt_l);
    cudaGetSymbolAddress((void**)&wk_h,  g_wk_h);  cudaGetSymbolAddress((void**)&wk_l,  g_wk_l);
    cudaGetSymbolAddress((void**)&wv_h,  g_wv_h);  cudaGetSymbolAddress((void**)&wv_l,  g_wv_l);
    cudaGetSymbolAddress((void**)&wq_h,  g_wq_h);  cudaGetSymbolAddress((void**)&wq_l,  g_wq_l);
    cudaGetSymbolAddress((void**)&wm_h,  g_wm_h);  cudaGetSymbolAddress((void**)&wm_l,  g_wm_l);

    const int GEMM_SMEM = 131072 + 16;
    const int ATTN_SMEM = 18432 + 2 * 18432;   // 55296
    cudaFuncSetAttribute((const void*)proj_gemm,   cudaFuncAttributeMaxDynamicSharedMemorySize, GEMM_SMEM);
    cudaFuncSetAttribute((const void*)out_gemm,    cudaFuncAttributeMaxDynamicSharedMemorySize, GEMM_SMEM);
    cudaFuncSetAttribute((const void*)attn_kernel, cudaFuncAttributeMaxDynamicSharedMemorySize, ATTN_SMEM);

    mask_norm_kernel<<<1, 256>>>(mask);

    split_tiled<<<(BB*LL*64 + 255)/256, 256>>>(k,  kin_h, kin_l, BB*LL*64);
    split_tiled<<<(BB*LL*64 + 255)/256, 256>>>(v,  vin_h, vin_l, BB*LL*64);
    split_tiled<<<(HID*64 + 255)/256, 256>>>(Wk, wk_h, wk_l, HID*64);
    split_tiled<<<(HID*64 + 255)/256, 256>>>(Wv, wv_h, wv_l, HID*64);
    split_tiled<<<(HID*64 + 255)/256, 256>>>(Wq, wq_h, wq_l, HID*64);
    split_tiled<<<(HID*64 + 255)/256, 256>>>(Wm, wm_h, wm_l, HID*64);
    transpose_split_q<<<dim3(HW/32, HID/32, BB), dim3(32, 8)>>>(q, qt_h, qt_l);

    // fused projections: z = {k, v, q} -> fp16 row-major
    proj_gemm<<<dim3(HID/128, (BB*LL)/128, 3), 256, GEMM_SMEM>>>(bk, bv, bq);

    attn_kernel<<<dim3(HW/128, NH, BB), 256, ATTN_SMEM>>>();

    // output projection, batched over z
    out_gemm<<<dim3(HW/128, 512/128, BB), 256, GEMM_SMEM>>>(bm, out);
}

// round 10
// speedup vs baseline: 2.0880x; 1.3572x over previous
#include <cuda_runtime.h>
#include <cuda_bf16.h>
#include <cuda_fp16.h>
#include <math.h>
#include <stdint.h>

#define BB   8
#define LL   1024
#define HW   1024
#define HID  512
#define NH   8
#define DH   64

typedef __nv_bfloat16 bf16;

// fp16 tiled-swizzled projection operands: [tile (row>>7)*8 + (k>>6)][128x64 SW128 16KB]
__device__ __half g_kin_f[BB*LL*HID];
__device__ __half g_vin_f[BB*LL*HID];
__device__ __half g_qt_f [BB*HW*HID];
__device__ __half g_wk_f[HID*HID];
__device__ __half g_wv_f[HID*HID];
__device__ __half g_wq_f[HID*HID];
// out-projection operands (3-term bf16, verified)
__device__ bf16 g_wm_h[HID*HID], g_wm_l[HID*HID];
__device__ bf16 g_ao_h[BB*HW*HID], g_ao_l[BB*HW*HID];   // tiled
// fp16 row-major attention inputs
__device__ __half g_kf[BB*LL*HID];
__device__ __half g_vf[BB*LL*HID];
__device__ __half g_qf[BB*HW*HID];
__device__ unsigned char g_mask[BB*LL];

// ---------------- helpers ----------------
__device__ __forceinline__ void split2(float a, float b, uint32_t& h, uint32_t& l)
{
    __nv_bfloat162 hv = __floats2bfloat162_rn(a, b);
    float ra = a - __bfloat162float(hv.x);
    float rb = b - __bfloat162float(hv.y);
    __nv_bfloat162 lv = __floats2bfloat162_rn(ra, rb);
    h = *reinterpret_cast<uint32_t*>(&hv);
    l = *reinterpret_cast<uint32_t*>(&lv);
}
__device__ __forceinline__ uint32_t packh2(float a, float b)
{
    __half2 h = __floats2half2_rn(a, b);
    return *reinterpret_cast<uint32_t*>(&h);
}
__device__ __forceinline__ float fexp2f(float x)
{
    x = fmaxf(x, -126.0f);
    int   n = __float2int_rn(x);
    float f = x - (float)n;
    float p = 1.33336498e-3f;
    p = fmaf(p, f, 9.61817007e-3f);
    p = fmaf(p, f, 5.55041087e-2f);
    p = fmaf(p, f, 2.40226507e-1f);
    p = fmaf(p, f, 6.93147181e-1f);
    p = fmaf(p, f, 1.0f);
    return p * __int_as_float((n + 127) << 23);
}
__device__ __forceinline__ void ldsm4(uint32_t& r0, uint32_t& r1, uint32_t& r2, uint32_t& r3, uint32_t a)
{
    asm volatile("ldmatrix.sync.aligned.m8n8.x4.shared.b16 {%0,%1,%2,%3}, [%4];"
                 : "=r"(r0), "=r"(r1), "=r"(r2), "=r"(r3) : "r"(a));
}
__device__ __forceinline__ void ldsm4t(uint32_t& r0, uint32_t& r1, uint32_t& r2, uint32_t& r3, uint32_t a)
{
    asm volatile("ldmatrix.sync.aligned.m8n8.x4.trans.shared.b16 {%0,%1,%2,%3}, [%4];"
                 : "=r"(r0), "=r"(r1), "=r"(r2), "=r"(r3) : "r"(a));
}
__device__ __forceinline__ void mma16816(float* d, const uint32_t* a, uint32_t b0, uint32_t b1)
{
    asm volatile("mma.sync.aligned.m16n8k16.row.col.f32.bf16.bf16.f32 "
                 "{%0,%1,%2,%3}, {%4,%5,%6,%7}, {%8,%9}, {%0,%1,%2,%3};"
                 : "+f"(d[0]), "+f"(d[1]), "+f"(d[2]), "+f"(d[3])
                 : "r"(a[0]), "r"(a[1]), "r"(a[2]), "r"(a[3]), "r"(b0), "r"(b1));
}
__device__ __forceinline__ void mma16816h(float* d, const uint32_t* a, uint32_t b0, uint32_t b1)
{
    asm volatile("mma.sync.aligned.m16n8k16.row.col.f32.f16.f16.f32 "
                 "{%0,%1,%2,%3}, {%4,%5,%6,%7}, {%8,%9}, {%0,%1,%2,%3};"
                 : "+f"(d[0]), "+f"(d[1]), "+f"(d[2]), "+f"(d[3])
                 : "r"(a[0]), "r"(a[1]), "r"(a[2]), "r"(a[3]), "r"(b0), "r"(b1));
}
__device__ __forceinline__ void cpa16(uint32_t dst, const void* src)
{
    asm volatile("cp.async.ca.shared.global [%0], [%1], 16;" :: "r"(dst), "l"(src));
}
#define CP_COMMIT() asm volatile("cp.async.commit_group;")
#define CP_WAIT(n)  asm volatile("cp.async.wait_group %0;" :: "n"(n))

__device__ __forceinline__ uint32_t swz128(uint32_t o) { return o ^ ((o >> 3) & 0x70); }

__device__ __forceinline__ void mbar_init(uint32_t a, uint32_t c)
{ asm volatile("mbarrier.init.shared.b64 [%0], %1;" :: "r"(a), "r"(c) : "memory"); }
__device__ __forceinline__ void mbar_expect(uint32_t a, uint32_t bytes)
{ asm volatile("mbarrier.arrive.expect_tx.shared.b64 _, [%0], %1;" :: "r"(a), "r"(bytes) : "memory"); }
__device__ __forceinline__ void mbar_wait(uint32_t a, uint32_t par)
{
    asm volatile(
        "{\n\t.reg .pred P;\n"
        "W%=:\n\tmbarrier.try_wait.parity.acquire.cta.shared::cta.b64 P, [%0], %1, 0x989680;\n"
        "\t@P bra.uni D%=;\n\tbra.uni W%=;\nD%=:\n\t}"
        :: "r"(a), "r"(par) : "memory");
}
__device__ __forceinline__ void bulk_g2s(uint32_t dst, const void* src, uint32_t bytes, uint32_t mbar)
{
    asm volatile("cp.async.bulk.shared::cta.global.mbarrier::complete_tx::bytes [%0], [%1], %2, [%3];"
                 :: "r"(dst), "l"(src), "r"(bytes), "r"(mbar) : "memory");
}

// ---------------- mask normalization (verified) ----------------
__global__ void mask_norm_kernel(const unsigned char* __restrict__ m)
{
    __shared__ int s_wide, s_bytes;
    if (threadIdx.x == 0) { s_wide = 0; s_bytes = 0; }
    __syncthreads();
    int wide = 0, bytes = 0;
    for (int i = threadIdx.x; i < BB*LL; i += blockDim.x) {
        unsigned char c = m[i];
        if (c > 1) wide = 1;
        else if (c != 0 && (i & 3) != 0) bytes = 1;
    }
    if (wide)  atomicOr(&s_wide, 1);
    if (bytes) atomicOr(&s_bytes, 1);
    __syncthreads();
    const bool is_u8 = (!s_wide) && s_bytes;
    for (int i = threadIdx.x; i < BB*LL; i += blockDim.x) {
        unsigned char vv;
        if (is_u8) vv = (m[i] != 0);
        else       vv = (((const int*)m)[i] != 0);
        g_mask[i] = vv;
    }
}

// ---------------- fp32 [R][512] -> fp16 tiled-swizzled ----------------
__global__ void pack_tiled_h(const float* __restrict__ in, __half* __restrict__ o, int nch)
{
    int i = blockIdx.x * blockDim.x + threadIdx.x;
    if (i >= nch) return;
    int row = i >> 6;
    int kc  = (i & 63) * 8;
    const float4* p = (const float4*)(in + (size_t)row * HID + kc);
    float4 a = p[0], b = p[1];
    uint32_t h0 = packh2(a.x, a.y), h1 = packh2(a.z, a.w);
    uint32_t h2 = packh2(b.x, b.y), h3 = packh2(b.z, b.w);
    uint32_t off = swz128((uint32_t)((row & 127) * 128 + (kc & 63) * 2));
    size_t base = ((size_t)(row >> 7) * 8 + (kc >> 6)) * 16384 + off;
    *(uint4*)((char*)o + base) = make_uint4(h0, h1, h2, h3);
}

// ---------------- fp32 [R][512] -> split-bf16 tiled (Wm only) ----------------
__global__ void split_tiled(const float* __restrict__ in, bf16* __restrict__ oh,
                            bf16* __restrict__ ol, int nch)
{
    int i = blockIdx.x * blockDim.x + threadIdx.x;
    if (i >= nch) return;
    int row = i >> 6;
    int kc  = (i & 63) * 8;
    const float4* p = (const float4*)(in + (size_t)row * HID + kc);
    float4 a = p[0], b = p[1];
    uint32_t h0,l0,h1,l1,h2,l2,h3,l3;
    split2(a.x, a.y, h0, l0); split2(a.z, a.w, h1, l1);
    split2(b.x, b.y, h2, l2); split2(b.z, b.w, h3, l3);
    uint32_t o = swz128((uint32_t)((row & 127) * 128 + (kc & 63) * 2));
    size_t base = ((size_t)(row >> 7) * 8 + (kc >> 6)) * 16384 + o;
    *(uint4*)((char*)oh + base) = make_uint4(h0, h1, h2, h3);
    *(uint4*)((char*)ol + base) = make_uint4(l0, l1, l2, l3);
}

// ---------------- q transpose -> fp16 tiled ----------------
__global__ void transpose_pack_q(const float* __restrict__ in, __half* __restrict__ o)
{
    __shared__ float t[32][33];
    int b = blockIdx.z;
    int hw0 = blockIdx.x * 32, c0 = blockIdx.y * 32;
    const float* ip = in + ((long)b * HID + c0) * HW + hw0;
#pragma unroll
    for (int j = 0; j < 32; j += 8)
        t[threadIdx.y + j][threadIdx.x] = ip[(long)(threadIdx.y + j) * HW + threadIdx.x];
    __syncthreads();
#pragma unroll
    for (int j = 0; j < 32; j += 8) {
        float v = t[threadIdx.x][threadIdx.y + j];
        int rowg = b * HW + hw0 + threadIdx.y + j;
        int col  = c0 + threadIdx.x;
        uint32_t off = swz128((uint32_t)((rowg & 127) * 128 + (col & 63) * 2));
        size_t base = ((size_t)(rowg >> 7) * 8 + (col >> 6)) * 16384 + off;
        *(__half*)((char*)o + base) = __float2half_rn(v);
    }
}

// ---------------------------------------------------------------------------
// fp16 single-term GEMM mainloop: 2 x 16KB bulk loads/stage, double-buffered.
// smem: 2 x [A 16KB | B 16KB] = 64KB, barriers at 65536.
// ---------------------------------------------------------------------------
__device__ __forceinline__ void gemm_mainloop_h(
    const __half* A, const __half* B, size_t at, size_t bt,
    uint32_t sb, int tid, int lane, int wid, float acc[4][4][4])
{
    const int wm = (wid & 1) * 64, wn = (wid >> 1) * 32;
    const int arow = lane & 15, acol8 = (lane >> 4) * 8;
    const uint32_t F0 = 65536u, F1 = 65544u;

    if (tid == 0) { mbar_init(sb + F0, 1); mbar_init(sb + F1, 1); }
    __syncthreads();
    if (tid == 0) {
        mbar_expect(sb + F0, 32768u);
        bulk_g2s(sb,           A + at * 8192, 16384u, sb + F0);
        bulk_g2s(sb + 16384u,  B + bt * 8192, 16384u, sb + F0);
        mbar_expect(sb + F1, 32768u);
        bulk_g2s(sb + 32768u,  A + (at + 1) * 8192, 16384u, sb + F1);
        bulk_g2s(sb + 49152u,  B + (bt + 1) * 8192, 16384u, sb + F1);
    }
    for (int s = 0; s < 8; s++) {
        mbar_wait((s & 1) ? sb + F1 : sb + F0, (uint32_t)((s >> 1) & 1));
        uint32_t bb = sb + (uint32_t)(s & 1) * 32768u;
#pragma unroll
        for (int ks = 0; ks < 4; ks++) {
            const int kc = ks * 16 + acol8;
            uint32_t ah[4][4];
#pragma unroll
            for (int i = 0; i < 4; i++) {
                uint32_t off = swz128((uint32_t)(((wm + 16 * i + arow) << 7) + (kc << 1)));
                ldsm4(ah[i][0], ah[i][1], ah[i][2], ah[i][3], bb + off);
            }
#pragma unroll
            for (int jj = 0; jj < 2; jj++) {
                uint32_t bh[4];
                uint32_t off = swz128((uint32_t)(((wn + 16 * jj + arow) << 7) + (kc << 1)));
                ldsm4(bh[0], bh[1], bh[2], bh[3], bb + 16384u + off);
#pragma unroll
                for (int i = 0; i < 4; i++) {
                    mma16816h(acc[i][2*jj],   ah[i], bh[0], bh[2]);
                    mma16816h(acc[i][2*jj+1], ah[i], bh[1], bh[3]);
                }
            }
        }
        __syncthreads();
        if (tid == 0 && s + 2 < 8) {
            uint32_t full = (s & 1) ? sb + F1 : sb + F0;
            uint32_t base = sb + (uint32_t)(s & 1) * 32768u;
            mbar_expect(full, 32768u);
            bulk_g2s(base,           A + (at + s + 2) * 8192, 16384u, full);
            bulk_g2s(base + 16384u,  B + (bt + s + 2) * 8192, 16384u, full);
        }
    }
}

// ---------------------------------------------------------------------------
// 3-term bf16 GEMM mainloop (verified R8) — out-projection only.
// ---------------------------------------------------------------------------
__device__ __forceinline__ void gemm_mainloop(
    const bf16* Ah, const bf16* Al, const bf16* Bh, const bf16* Bl,
    size_t at, size_t bt, uint32_t sb, int tid, int lane, int wid,
    float acc[4][4][4])
{
    const int wm = (wid & 1) * 64, wn = (wid >> 1) * 32;
    const int arow = lane & 15, acol8 = (lane >> 4) * 8;
    const uint32_t F0 = 131072u, F1 = 131080u;

    if (tid == 0) { mbar_init(sb + F0, 1); mbar_init(sb + F1, 1); }
    __syncthreads();
    if (tid == 0) {
        mbar_expect(sb + F0, 65536u);
        bulk_g2s(sb,           Ah + at * 8192, 16384u, sb + F0);
        bulk_g2s(sb + 16384u,  Al + at * 8192, 16384u, sb + F0);
        bulk_g2s(sb + 32768u,  Bh + bt * 8192, 16384u, sb + F0);
        bulk_g2s(sb + 49152u,  Bl + bt * 8192, 16384u, sb + F0);
        mbar_expect(sb + F1, 65536u);
        bulk_g2s(sb + 65536u,  Ah + (at + 1) * 8192, 16384u, sb + F1);
        bulk_g2s(sb + 81920u,  Al + (at + 1) * 8192, 16384u, sb + F1);
        bulk_g2s(sb + 98304u,  Bh + (bt + 1) * 8192, 16384u, sb + F1);
        bulk_g2s(sb + 114688u, Bl + (bt + 1) * 8192, 16384u, sb + F1);
    }
    for (int s = 0; s < 8; s++) {
        mbar_wait((s & 1) ? sb + F1 : sb + F0, (uint32_t)((s >> 1) & 1));
        uint32_t bb = sb + (uint32_t)(s & 1) * 65536u;
#pragma unroll
        for (int ks = 0; ks < 4; ks++) {
            const int kc = ks * 16 + acol8;
            uint32_t ah[4][4], al[4][4];
#pragma unroll
            for (int i = 0; i < 4; i++) {
                uint32_t off = swz128((uint32_t)(((wm + 16 * i + arow) << 7) + (kc << 1)));
                ldsm4(ah[i][0], ah[i][1], ah[i][2], ah[i][3], bb + off);
                ldsm4(al[i][0], al[i][1], al[i][2], al[i][3], bb + 16384u + off);
            }
#pragma unroll
            for (int jj = 0; jj < 2; jj++) {
                uint32_t bh[4], bl[4];
                uint32_t off = swz128((uint32_t)(((wn + 16 * jj + arow) << 7) + (kc << 1)));
                ldsm4(bh[0], bh[1], bh[2], bh[3], bb + 32768u + off);
                ldsm4(bl[0], bl[1], bl[2], bl[3], bb + 49152u + off);
#pragma unroll
                for (int i = 0; i < 4; i++) {
                    mma16816(acc[i][2*jj],   ah[i], bh[0], bh[2]);
                    mma16816(acc[i][2*jj],   ah[i], bl[0], bl[2]);
                    mma16816(acc[i][2*jj],   al[i], bh[0], bh[2]);
                    mma16816(acc[i][2*jj+1], ah[i], bh[1], bh[3]);
                    mma16816(acc[i][2*jj+1], ah[i], bl[1], bl[3]);
                    mma16816(acc[i][2*jj+1], al[i], bh[1], bh[3]);
                }
            }
        }
        __syncthreads();
        if (tid == 0 && s + 2 < 8) {
            uint32_t full = (s & 1) ? sb + F1 : sb + F0;
            uint32_t base = sb + (uint32_t)(s & 1) * 65536u;
            mbar_expect(full, 65536u);
            bulk_g2s(base,           Ah + (at + s + 2) * 8192, 16384u, full);
            bulk_g2s(base + 16384u,  Al + (at + s + 2) * 8192, 16384u, full);
            bulk_g2s(base + 32768u,  Bh + (bt + s + 2) * 8192, 16384u, full);
            bulk_g2s(base + 49152u,  Bl + (bt + s + 2) * 8192, 16384u, full);
        }
    }
}

// ---- fused k/v/q projections (fp16 single-term): z selects problem ----
__global__ __launch_bounds__(256, 1)
void proj_gemm(const float* __restrict__ bk, const float* __restrict__ bv,
               const float* __restrict__ bq)
{
    extern __shared__ char smc[];
    const uint32_t sb = (uint32_t)__cvta_generic_to_shared(smc);
    const int tid = threadIdx.x, lane = tid & 31, wid = tid >> 5;
    const int m0 = blockIdx.y * 128, n0 = blockIdx.x * 128, z = blockIdx.z;

    const __half *A, *B;
    __half* Cfp;
    const float* bias;
    if (z == 0)      { A = g_kin_f; B = g_wk_f; Cfp = g_kf; bias = bk; }
    else if (z == 1) { A = g_vin_f; B = g_wv_f; Cfp = g_vf; bias = bv; }
    else             { A = g_qt_f;  B = g_wq_f; Cfp = g_qf; bias = bq; }

    float acc[4][4][4] = {};
    gemm_mainloop_h(A, B, (size_t)(m0 >> 7) * 8, (size_t)(n0 >> 7) * 8,
                    sb, tid, lane, wid, acc);

    const int wm = (wid & 1) * 64, wn = (wid >> 1) * 32;
    const int g = lane >> 2, lam = lane & 3;
#pragma unroll
    for (int i = 0; i < 4; i++) {
#pragma unroll
        for (int j = 0; j < 4; j++) {
            int row0 = m0 + wm + 16 * i + g;
            int col  = n0 + wn + 8 * j + 2 * lam;
            float b0 = bias[col], b1 = bias[col + 1];
            *(uint32_t*)&Cfp[(size_t)row0 * HID + col]       = packh2(acc[i][j][0] + b0, acc[i][j][1] + b1);
            *(uint32_t*)&Cfp[(size_t)(row0 + 8) * HID + col] = packh2(acc[i][j][2] + b0, acc[i][j][3] + b1);
        }
    }
}

// ---- output projection (verified R8): C[z][o][hw] = Wm . ao^T + bm, relu ----
__global__ __launch_bounds__(256, 1)
void out_gemm(const float* __restrict__ bm, float* __restrict__ out)
{
    extern __shared__ char smc[];
    const uint32_t sb = (uint32_t)__cvta_generic_to_shared(smc);
    const int tid = threadIdx.x, lane = tid & 31, wid = tid >> 5;
    const int m0 = blockIdx.y * 128, n0 = blockIdx.x * 128, z = blockIdx.z;

    float acc[4][4][4] = {};
    gemm_mainloop(g_wm_h, g_wm_l, g_ao_h, g_ao_l,
                  (size_t)(m0 >> 7) * 8, (size_t)((z * HW + n0) >> 7) * 8,
                  sb, tid, lane, wid, acc);

    const int wm = (wid & 1) * 64, wn = (wid >> 1) * 32;
    const int g = lane >> 2, lam = lane & 3;
    float* cfp = out + (size_t)z * 512 * HW;
#pragma unroll
    for (int i = 0; i < 4; i++) {
#pragma unroll
        for (int j = 0; j < 4; j++) {
            int row0 = m0 + wm + 16 * i + g;
            int col  = n0 + wn + 8 * j + 2 * lam;
            float ba = bm[row0], bb2 = bm[row0 + 8];
            float v00 = fmaxf(acc[i][j][0] + ba, 0.f),  v01 = fmaxf(acc[i][j][1] + ba, 0.f);
            float v10 = fmaxf(acc[i][j][2] + bb2, 0.f), v11 = fmaxf(acc[i][j][3] + bb2, 0.f);
            *(float2*)&cfp[(size_t)row0 * HW + col]       = make_float2(v00, v01);
            *(float2*)&cfp[(size_t)(row0 + 8) * HW + col] = make_float2(v10, v11);
        }
    }
}

// ---------------------------------------------------------------------------
// Flash attention (verified R9): fp16 operands, Br=128, Bc=64, 2 CTAs/SM.
// ---------------------------------------------------------------------------
__global__ __launch_bounds__(256, 2)
void attn_kernel()
{
    extern __shared__ uint32_t dsm[];
    __shared__ unsigned char s_maskAll[LL];
    const int tid = threadIdx.x, lane = tid & 31, wid = tid >> 5;
    const int b = blockIdx.z, h = blockIdx.y, q0 = blockIdx.x * 128;
    const int arow = lane & 15, acol8 = (lane >> 4) * 8;
    const int g = lane >> 2, lam = lane & 3;
    const uint32_t sb = (uint32_t)__cvta_generic_to_shared(dsm);
    const uint32_t KVB0 = 18432u, KVSZ = 18432u, VOFF = 9216u;

    for (int i = tid; i < LL; i += 256) s_maskAll[i] = g_mask[b * LL + i];

    {
        int r = tid >> 1;
        long src = (long)(b * HW + q0 + r) * HID + h * DH;
        uint32_t dst = sb + (uint32_t)(r * 144);
#pragma unroll
        for (int cc = 0; cc < 4; cc++) {
            int chs = (tid & 1) * 4 + cc;
            cpa16(dst + chs * 16, g_qf + src + chs * 8);
        }
    }
    CP_COMMIT();

    auto issueKV = [&](int kt) {
        int r = tid >> 2;
        long src = (long)(b * LL + kt * 64 + r) * HID + h * DH;
        uint32_t dst = sb + KVB0 + (uint32_t)(kt & 1) * KVSZ + (uint32_t)(r * 144);
#pragma unroll
        for (int cc = 0; cc < 2; cc++) {
            int chs = (tid & 3) * 2 + cc;
            cpa16(dst +        chs * 16, g_kf + src + chs * 8);
            cpa16(dst + VOFF + chs * 16, g_vf + src + chs * 8);
        }
    };
    issueKV(0); CP_COMMIT();

    CP_WAIT(1);
    __syncthreads();
    uint32_t qh[4][4];
    {
        int m0w = wid * 16;
#pragma unroll
        for (int ks = 0; ks < 4; ks++) {
            uint32_t off = (uint32_t)(((m0w + arow) * 72 + ks * 16 + acol8) * 2);
            ldsm4(qh[ks][0], qh[ks][1], qh[ks][2], qh[ks][3], sb + off);
        }
    }

    float oacc[8][4] = {};
    float mr0 = -1e30f, mr1 = -1e30f, lr0 = 0.f, lr1 = 0.f;

    for (int kt = 0; kt < LL / 64; kt++) {
        if (kt + 1 < LL / 64) { issueKV(kt + 1); CP_COMMIT(); CP_WAIT(1); }
        else                  { CP_WAIT(0); }
        __syncthreads();
        const uint32_t kvb = sb + KVB0 + (uint32_t)(kt & 1) * KVSZ;
        const int k0g = kt * 64;

        float sacc[8][4] = {};
#pragma unroll
        for (int ks = 0; ks < 4; ks++) {
#pragma unroll
            for (int jj = 0; jj < 4; jj++) {
                uint32_t bh[4];
                uint32_t off = (uint32_t)(((16 * jj + arow) * 72 + ks * 16 + acol8) * 2);
                ldsm4(bh[0], bh[1], bh[2], bh[3], kvb + off);
                mma16816h(sacc[2*jj],   qh[ks], bh[0], bh[2]);
                mma16816h(sacc[2*jj+1], qh[ks], bh[1], bh[3]);
            }
        }

        const float cscale = 0.1803368801f;
        float mn0 = mr0, mn1 = mr1;
#pragma unroll
        for (int j = 0; j < 8; j++) {
            int kc = 8 * j + 2 * lam;
            bool k0m = s_maskAll[k0g + kc] != 0, k1m = s_maskAll[k0g + kc + 1] != 0;
            sacc[j][0] = k0m ? -1e9f : sacc[j][0] * cscale;
            sacc[j][1] = k1m ? -1e9f : sacc[j][1] * cscale;
            sacc[j][2] = k0m ? -1e9f : sacc[j][2] * cscale;
            sacc[j][3] = k1m ? -1e9f : sacc[j][3] * cscale;
            mn0 = fmaxf(mn0, fmaxf(sacc[j][0], sacc[j][1]));
            mn1 = fmaxf(mn1, fmaxf(sacc[j][2], sacc[j][3]));
        }
        mn0 = fmaxf(mn0, __shfl_xor_sync(0xffffffffu, mn0, 1));
        mn0 = fmaxf(mn0, __shfl_xor_sync(0xffffffffu, mn0, 2));
        mn1 = fmaxf(mn1, __shfl_xor_sync(0xffffffffu, mn1, 1));
        mn1 = fmaxf(mn1, __shfl_xor_sync(0xffffffffu, mn1, 2));
        float cs0 = fexp2f(mr0 - mn0), cs1 = fexp2f(mr1 - mn1);
        mr0 = mn0; mr1 = mn1;
        float rs0 = 0.f, rs1 = 0.f;
        uint32_t ph[8][2];
#pragma unroll
        for (int j = 0; j < 8; j++) {
            float p0 = fexp2f(sacc[j][0] - mn0);
            float p1 = fexp2f(sacc[j][1] - mn0);
            float p2 = fexp2f(sacc[j][2] - mn1);
            float p3 = fexp2f(sacc[j][3] - mn1);
            rs0 += p0 + p1; rs1 += p2 + p3;
            ph[j][0] = packh2(p0, p1);
            ph[j][1] = packh2(p2, p3);
        }
        rs0 += __shfl_xor_sync(0xffffffffu, rs0, 1);
        rs0 += __shfl_xor_sync(0xffffffffu, rs0, 2);
        rs1 += __shfl_xor_sync(0xffffffffu, rs1, 1);
        rs1 += __shfl_xor_sync(0xffffffffu, rs1, 2);
        lr0 = lr0 * cs0 + rs0;
        lr1 = lr1 * cs1 + rs1;
#pragma unroll
        for (int j = 0; j < 8; j++) {
            oacc[j][0] *= cs0; oacc[j][1] *= cs0;
            oacc[j][2] *= cs1; oacc[j][3] *= cs1;
        }

#pragma unroll
        for (int s = 0; s < 4; s++) {
            uint32_t pah[4] = { ph[2*s][0], ph[2*s][1], ph[2*s+1][0], ph[2*s+1][1] };
#pragma unroll
            for (int jj = 0; jj < 4; jj++) {
                uint32_t vh[4];
                uint32_t off = (uint32_t)(((16 * s + arow) * 72 + jj * 16 + acol8) * 2);
                ldsm4t(vh[0], vh[1], vh[2], vh[3], kvb + VOFF + off);
                mma16816h(oacc[2*jj],   pah, vh[0], vh[1]);
                mma16816h(oacc[2*jj+1], pah, vh[2], vh[3]);
            }
        }
        __syncthreads();
    }

    // epilogue -> tiled split-bf16 ao
    float i0 = 1.f / lr0, i1 = 1.f / lr1;
    int row0 = q0 + wid * 16 + g;
    size_t tbase = ((size_t)b * HW + q0) * HID * 2 + (size_t)h * 16384;
#pragma unroll
    for (int j = 0; j < 8; j++) {
        int cin = 8 * j + 2 * lam;
        uint32_t h0, l0, h1, l1;
        split2(oacc[j][0] * i0, oacc[j][1] * i0, h0, l0);
        split2(oacc[j][2] * i1, oacc[j][3] * i1, h1, l1);
        uint32_t o0 = swz128((uint32_t)((row0 - q0) * 128 + cin * 2));
        uint32_t o1 = swz128((uint32_t)((row0 - q0 + 8) * 128 + cin * 2));
        *(uint32_t*)((char*)g_ao_h + tbase + o0) = h0;
        *(uint32_t*)((char*)g_ao_l + tbase + o0) = l0;
        *(uint32_t*)((char*)g_ao_h + tbase + o1) = h1;
        *(uint32_t*)((char*)g_ao_l + tbase + o1) = l1;
    }
}

// ---------------------------------------------------------------------------
extern "C" void kernel_launch(void* const* d_in, const int* in_sizes, int n_in,
                              void* d_out, int out_size)
{
    const float* v  = (const float*)d_in[0];
    const float* k  = (const float*)d_in[1];
    const float* q  = (const float*)d_in[2];
    const unsigned char* mask = (const unsigned char*)d_in[3];
    const float* Wv = (const float*)d_in[4];
    const float* bv = (const float*)d_in[5];
    const float* Wk = (const float*)d_in[6];
    const float* bk = (const float*)d_in[7];
    const float* Wq = (const float*)d_in[8];
    const float* bq = (const float*)d_in[9];
    const float* Wm = (const float*)d_in[10];
    const float* bm = (const float*)d_in[11];
    float* out = (float*)d_out;

    __half *kin_f,*vin_f,*qt_f,*wk_f,*wv_f,*wq_f;
    bf16 *wm_h,*wm_l;
    cudaGetSymbolAddress((void**)&kin_f, g_kin_f);
    cudaGetSymbolAddress((void**)&vin_f, g_vin_f);
    cudaGetSymbolAddress((void**)&qt_f,  g_qt_f);
    cudaGetSymbolAddress((void**)&wk_f,  g_wk_f);
    cudaGetSymbolAddress((void**)&wv_f,  g_wv_f);
    cudaGetSymbolAddress((void**)&wq_f,  g_wq_f);
    cudaGetSymbolAddress((void**)&wm_h,  g_wm_h);
    cudaGetSymbolAddress((void**)&wm_l,  g_wm_l);

    const int PROJ_SMEM = 65536 + 16;
    const int OUT_SMEM  = 131072 + 16;
    const int ATTN_SMEM = 18432 + 2 * 18432;   // 55296
    cudaFuncSetAttribute((const void*)proj_gemm,   cudaFuncAttributeMaxDynamicSharedMemorySize, PROJ_SMEM);
    cudaFuncSetAttribute((const void*)out_gemm,    cudaFuncAttributeMaxDynamicSharedMemorySize, OUT_SMEM);
    cudaFuncSetAttribute((const void*)attn_kernel, cudaFuncAttributeMaxDynamicSharedMemorySize, ATTN_SMEM);

    mask_norm_kernel<<<1, 256>>>(mask);

    pack_tiled_h<<<(BB*LL*64 + 255)/256, 256>>>(k,  kin_f, BB*LL*64);
    pack_tiled_h<<<(BB*LL*64 + 255)/256, 256>>>(v,  vin_f, BB*LL*64);
    pack_tiled_h<<<(HID*64 + 255)/256, 256>>>(Wk, wk_f, HID*64);
    pack_tiled_h<<<(HID*64 + 255)/256, 256>>>(Wv, wv_f, HID*64);
    pack_tiled_h<<<(HID*64 + 255)/256, 256>>>(Wq, wq_f, HID*64);
    split_tiled<<<(HID*64 + 255)/256, 256>>>(Wm, wm_h, wm_l, HID*64);
    transpose_pack_q<<<dim3(HW/32, HID/32, BB), dim3(32, 8)>>>(q, qt_f);

    // fused projections: z = {k, v, q} -> fp16 row-major
    proj_gemm<<<dim3(HID/128, (BB*LL)/128, 3), 256, PROJ_SMEM>>>(bk, bv, bq);

    attn_kernel<<<dim3(HW/128, NH, BB), 256, ATTN_SMEM>>>();

    // output projection, batched over z
    out_gemm<<<dim3(HW/128, 512/128, BB), 256, OUT_SMEM>>>(bm, out);
}

// round 11
// speedup vs baseline: 2.4642x; 1.1802x over previous
#include <cuda_runtime.h>
#include <cuda_bf16.h>
#include <cuda_fp16.h>
#include <math.h>
#include <stdint.h>

#define BB   8
#define LL   1024
#define HW   1024
#define HID  512
#define NH   8
#define DH   64

// fp16 tiled-swizzled GEMM operands: [tile (row>>7)*8 + (k>>6)][128x64 SW128 16KB]
__device__ __half g_kin_f[BB*LL*HID];
__device__ __half g_vin_f[BB*LL*HID];
__device__ __half g_qt_f [BB*HW*HID];
__device__ __half g_wk_f[HID*HID];
__device__ __half g_wv_f[HID*HID];
__device__ __half g_wq_f[HID*HID];
__device__ __half g_wm_f[HID*HID];
__device__ __half g_ao_f[BB*HW*HID];    // tiled (out-proj B operand)
// fp16 row-major attention inputs
__device__ __half g_kf[BB*LL*HID];
__device__ __half g_vf[BB*LL*HID];
__device__ __half g_qf[BB*HW*HID];
__device__ unsigned char g_mask[BB*LL];

// ---------------- helpers ----------------
__device__ __forceinline__ uint32_t packh2(float a, float b)
{
    __half2 h = __floats2half2_rn(a, b);
    return *reinterpret_cast<uint32_t*>(&h);
}
__device__ __forceinline__ float fexp2f(float x)
{
    x = fmaxf(x, -126.0f);
    int   n = __float2int_rn(x);
    float f = x - (float)n;
    float p = 1.33336498e-3f;
    p = fmaf(p, f, 9.61817007e-3f);
    p = fmaf(p, f, 5.55041087e-2f);
    p = fmaf(p, f, 2.40226507e-1f);
    p = fmaf(p, f, 6.93147181e-1f);
    p = fmaf(p, f, 1.0f);
    return p * __int_as_float((n + 127) << 23);
}
__device__ __forceinline__ void ldsm4(uint32_t& r0, uint32_t& r1, uint32_t& r2, uint32_t& r3, uint32_t a)
{
    asm volatile("ldmatrix.sync.aligned.m8n8.x4.shared.b16 {%0,%1,%2,%3}, [%4];"
                 : "=r"(r0), "=r"(r1), "=r"(r2), "=r"(r3) : "r"(a));
}
__device__ __forceinline__ void ldsm4t(uint32_t& r0, uint32_t& r1, uint32_t& r2, uint32_t& r3, uint32_t a)
{
    asm volatile("ldmatrix.sync.aligned.m8n8.x4.trans.shared.b16 {%0,%1,%2,%3}, [%4];"
                 : "=r"(r0), "=r"(r1), "=r"(r2), "=r"(r3) : "r"(a));
}
__device__ __forceinline__ void mma16816h(float* d, const uint32_t* a, uint32_t b0, uint32_t b1)
{
    asm volatile("mma.sync.aligned.m16n8k16.row.col.f32.f16.f16.f32 "
                 "{%0,%1,%2,%3}, {%4,%5,%6,%7}, {%8,%9}, {%0,%1,%2,%3};"
                 : "+f"(d[0]), "+f"(d[1]), "+f"(d[2]), "+f"(d[3])
                 : "r"(a[0]), "r"(a[1]), "r"(a[2]), "r"(a[3]), "r"(b0), "r"(b1));
}
__device__ __forceinline__ void cpa16(uint32_t dst, const void* src)
{
    asm volatile("cp.async.ca.shared.global [%0], [%1], 16;" :: "r"(dst), "l"(src));
}
#define CP_COMMIT() asm volatile("cp.async.commit_group;")
#define CP_WAIT(n)  asm volatile("cp.async.wait_group %0;" :: "n"(n))

__device__ __forceinline__ uint32_t swz128(uint32_t o) { return o ^ ((o >> 3) & 0x70); }

__device__ __forceinline__ void mbar_init(uint32_t a, uint32_t c)
{ asm volatile("mbarrier.init.shared.b64 [%0], %1;" :: "r"(a), "r"(c) : "memory"); }
__device__ __forceinline__ void mbar_expect(uint32_t a, uint32_t bytes)
{ asm volatile("mbarrier.arrive.expect_tx.shared.b64 _, [%0], %1;" :: "r"(a), "r"(bytes) : "memory"); }
__device__ __forceinline__ void mbar_wait(uint32_t a, uint32_t par)
{
    asm volatile(
        "{\n\t.reg .pred P;\n"
        "W%=:\n\tmbarrier.try_wait.parity.acquire.cta.shared::cta.b64 P, [%0], %1, 0x989680;\n"
        "\t@P bra.uni D%=;\n\tbra.uni W%=;\nD%=:\n\t}"
        :: "r"(a), "r"(par) : "memory");
}
__device__ __forceinline__ void bulk_g2s(uint32_t dst, const void* src, uint32_t bytes, uint32_t mbar)
{
    asm volatile("cp.async.bulk.shared::cta.global.mbarrier::complete_tx::bytes [%0], [%1], %2, [%3];"
                 :: "r"(dst), "l"(src), "r"(bytes), "r"(mbar) : "memory");
}

// ---------------- mask normalization (verified) ----------------
__global__ void mask_norm_kernel(const unsigned char* __restrict__ m)
{
    __shared__ int s_wide, s_bytes;
    if (threadIdx.x == 0) { s_wide = 0; s_bytes = 0; }
    __syncthreads();
    int wide = 0, bytes = 0;
    for (int i = threadIdx.x; i < BB*LL; i += blockDim.x) {
        unsigned char c = m[i];
        if (c > 1) wide = 1;
        else if (c != 0 && (i & 3) != 0) bytes = 1;
    }
    if (wide)  atomicOr(&s_wide, 1);
    if (bytes) atomicOr(&s_bytes, 1);
    __syncthreads();
    const bool is_u8 = (!s_wide) && s_bytes;
    for (int i = threadIdx.x; i < BB*LL; i += blockDim.x) {
        unsigned char vv;
        if (is_u8) vv = (m[i] != 0);
        else       vv = (((const int*)m)[i] != 0);
        g_mask[i] = vv;
    }
}

// ---------------- fp32 [R][512] -> fp16 tiled-swizzled (core) ----------------
__device__ __forceinline__ void pack_one(const float* in, __half* o, int i)
{
    int row = i >> 6;
    int kc  = (i & 63) * 8;
    const float4* p = (const float4*)(in + (size_t)row * HID + kc);
    float4 a = p[0], b = p[1];
    uint32_t h0 = packh2(a.x, a.y), h1 = packh2(a.z, a.w);
    uint32_t h2 = packh2(b.x, b.y), h3 = packh2(b.z, b.w);
    uint32_t off = swz128((uint32_t)((row & 127) * 128 + (kc & 63) * 2));
    size_t base = ((size_t)(row >> 7) * 8 + (kc >> 6)) * 16384 + off;
    *(uint4*)((char*)o + base) = make_uint4(h0, h1, h2, h3);
}

// fused k+v input pack: z selects tensor
__global__ void pack_kv(const float* __restrict__ k, const float* __restrict__ v, int nch)
{
    int i = blockIdx.x * blockDim.x + threadIdx.x;
    if (i >= nch) return;
    if (blockIdx.y == 0) pack_one(k, g_kin_f, i);
    else                 pack_one(v, g_vin_f, i);
}

// fused weights pack: z selects weight (all fp16 now)
__global__ void pack_w(const float* __restrict__ Wk, const float* __restrict__ Wv,
                       const float* __restrict__ Wq, const float* __restrict__ Wm, int nch)
{
    int i = blockIdx.x * blockDim.x + threadIdx.x;
    if (i >= nch) return;
    int z = blockIdx.y;
    if (z == 0)      pack_one(Wk, g_wk_f, i);
    else if (z == 1) pack_one(Wv, g_wv_f, i);
    else if (z == 2) pack_one(Wq, g_wq_f, i);
    else             pack_one(Wm, g_wm_f, i);
}

// ---------------- q transpose -> fp16 tiled ----------------
__global__ void transpose_pack_q(const float* __restrict__ in, __half* __restrict__ o)
{
    __shared__ float t[32][33];
    int b = blockIdx.z;
    int hw0 = blockIdx.x * 32, c0 = blockIdx.y * 32;
    const float* ip = in + ((long)b * HID + c0) * HW + hw0;
#pragma unroll
    for (int j = 0; j < 32; j += 8)
        t[threadIdx.y + j][threadIdx.x] = ip[(long)(threadIdx.y + j) * HW + threadIdx.x];
    __syncthreads();
#pragma unroll
    for (int j = 0; j < 32; j += 8) {
        float v = t[threadIdx.x][threadIdx.y + j];
        int rowg = b * HW + hw0 + threadIdx.y + j;
        int col  = c0 + threadIdx.x;
        uint32_t off = swz128((uint32_t)((rowg & 127) * 128 + (col & 63) * 2));
        size_t base = ((size_t)(rowg >> 7) * 8 + (col >> 6)) * 16384 + off;
        *(__half*)((char*)o + base) = __float2half_rn(v);
    }
}

// ---------------------------------------------------------------------------
// fp16 single-term GEMM mainloop (verified R10): 2 x 16KB bulk loads/stage.
// smem: 2 x [A 16KB | B 16KB] = 64KB, barriers at 65536.
// ---------------------------------------------------------------------------
__device__ __forceinline__ void gemm_mainloop_h(
    const __half* A, const __half* B, size_t at, size_t bt,
    uint32_t sb, int tid, int lane, int wid, float acc[4][4][4])
{
    const int wm = (wid & 1) * 64, wn = (wid >> 1) * 32;
    const int arow = lane & 15, acol8 = (lane >> 4) * 8;
    const uint32_t F0 = 65536u, F1 = 65544u;

    if (tid == 0) { mbar_init(sb + F0, 1); mbar_init(sb + F1, 1); }
    __syncthreads();
    if (tid == 0) {
        mbar_expect(sb + F0, 32768u);
        bulk_g2s(sb,           A + at * 8192, 16384u, sb + F0);
        bulk_g2s(sb + 16384u,  B + bt * 8192, 16384u, sb + F0);
        mbar_expect(sb + F1, 32768u);
        bulk_g2s(sb + 32768u,  A + (at + 1) * 8192, 16384u, sb + F1);
        bulk_g2s(sb + 49152u,  B + (bt + 1) * 8192, 16384u, sb + F1);
    }
    for (int s = 0; s < 8; s++) {
        mbar_wait((s & 1) ? sb + F1 : sb + F0, (uint32_t)((s >> 1) & 1));
        uint32_t bb = sb + (uint32_t)(s & 1) * 32768u;
#pragma unroll
        for (int ks = 0; ks < 4; ks++) {
            const int kc = ks * 16 + acol8;
            uint32_t ah[4][4];
#pragma unroll
            for (int i = 0; i < 4; i++) {
                uint32_t off = swz128((uint32_t)(((wm + 16 * i + arow) << 7) + (kc << 1)));
                ldsm4(ah[i][0], ah[i][1], ah[i][2], ah[i][3], bb + off);
            }
#pragma unroll
            for (int jj = 0; jj < 2; jj++) {
                uint32_t bh[4];
                uint32_t off = swz128((uint32_t)(((wn + 16 * jj + arow) << 7) + (kc << 1)));
                ldsm4(bh[0], bh[1], bh[2], bh[3], bb + 16384u + off);
#pragma unroll
                for (int i = 0; i < 4; i++) {
                    mma16816h(acc[i][2*jj],   ah[i], bh[0], bh[2]);
                    mma16816h(acc[i][2*jj+1], ah[i], bh[1], bh[3]);
                }
            }
        }
        __syncthreads();
        if (tid == 0 && s + 2 < 8) {
            uint32_t full = (s & 1) ? sb + F1 : sb + F0;
            uint32_t base = sb + (uint32_t)(s & 1) * 32768u;
            mbar_expect(full, 32768u);
            bulk_g2s(base,           A + (at + s + 2) * 8192, 16384u, full);
            bulk_g2s(base + 16384u,  B + (bt + s + 2) * 8192, 16384u, full);
        }
    }
}

// ---- fused k/v/q projections (verified R10): z selects problem ----
__global__ __launch_bounds__(256, 1)
void proj_gemm(const float* __restrict__ bk, const float* __restrict__ bv,
               const float* __restrict__ bq)
{
    extern __shared__ char smc[];
    const uint32_t sb = (uint32_t)__cvta_generic_to_shared(smc);
    const int tid = threadIdx.x, lane = tid & 31, wid = tid >> 5;
    const int m0 = blockIdx.y * 128, n0 = blockIdx.x * 128, z = blockIdx.z;

    const __half *A, *B;
    __half* Cfp;
    const float* bias;
    if (z == 0)      { A = g_kin_f; B = g_wk_f; Cfp = g_kf; bias = bk; }
    else if (z == 1) { A = g_vin_f; B = g_wv_f; Cfp = g_vf; bias = bv; }
    else             { A = g_qt_f;  B = g_wq_f; Cfp = g_qf; bias = bq; }

    float acc[4][4][4] = {};
    gemm_mainloop_h(A, B, (size_t)(m0 >> 7) * 8, (size_t)(n0 >> 7) * 8,
                    sb, tid, lane, wid, acc);

    const int wm = (wid & 1) * 64, wn = (wid >> 1) * 32;
    const int g = lane >> 2, lam = lane & 3;
#pragma unroll
    for (int i = 0; i < 4; i++) {
#pragma unroll
        for (int j = 0; j < 4; j++) {
            int row0 = m0 + wm + 16 * i + g;
            int col  = n0 + wn + 8 * j + 2 * lam;
            float b0 = bias[col], b1 = bias[col + 1];
            *(uint32_t*)&Cfp[(size_t)row0 * HID + col]       = packh2(acc[i][j][0] + b0, acc[i][j][1] + b1);
            *(uint32_t*)&Cfp[(size_t)(row0 + 8) * HID + col] = packh2(acc[i][j][2] + b0, acc[i][j][3] + b1);
        }
    }
}

// ---- output projection (fp16 single-term): C[z][o][hw] = Wm . ao^T + bm, relu ----
__global__ __launch_bounds__(256, 1)
void out_gemm(const float* __restrict__ bm, float* __restrict__ out)
{
    extern __shared__ char smc[];
    const uint32_t sb = (uint32_t)__cvta_generic_to_shared(smc);
    const int tid = threadIdx.x, lane = tid & 31, wid = tid >> 5;
    const int m0 = blockIdx.y * 128, n0 = blockIdx.x * 128, z = blockIdx.z;

    float acc[4][4][4] = {};
    gemm_mainloop_h(g_wm_f, g_ao_f,
                    (size_t)(m0 >> 7) * 8, (size_t)((z * HW + n0) >> 7) * 8,
                    sb, tid, lane, wid, acc);

    const int wm = (wid & 1) * 64, wn = (wid >> 1) * 32;
    const int g = lane >> 2, lam = lane & 3;
    float* cfp = out + (size_t)z * 512 * HW;
#pragma unroll
    for (int i = 0; i < 4; i++) {
#pragma unroll
        for (int j = 0; j < 4; j++) {
            int row0 = m0 + wm + 16 * i + g;
            int col  = n0 + wn + 8 * j + 2 * lam;
            float ba = bm[row0], bb2 = bm[row0 + 8];
            float v00 = fmaxf(acc[i][j][0] + ba, 0.f),  v01 = fmaxf(acc[i][j][1] + ba, 0.f);
            float v10 = fmaxf(acc[i][j][2] + bb2, 0.f), v11 = fmaxf(acc[i][j][3] + bb2, 0.f);
            *(float2*)&cfp[(size_t)row0 * HW + col]       = make_float2(v00, v01);
            *(float2*)&cfp[(size_t)(row0 + 8) * HW + col] = make_float2(v10, v11);
        }
    }
}

// ---------------------------------------------------------------------------
// Flash attention (verified R9/R10): fp16 operands, Br=128, Bc=64, 2 CTAs/SM.
// Epilogue now writes fp16 tiled ao (no split2).
// ---------------------------------------------------------------------------
__global__ __launch_bounds__(256, 2)
void attn_kernel()
{
    extern __shared__ uint32_t dsm[];
    __shared__ unsigned char s_maskAll[LL];
    const int tid = threadIdx.x, lane = tid & 31, wid = tid >> 5;
    const int b = blockIdx.z, h = blockIdx.y, q0 = blockIdx.x * 128;
    const int arow = lane & 15, acol8 = (lane >> 4) * 8;
    const int g = lane >> 2, lam = lane & 3;
    const uint32_t sb = (uint32_t)__cvta_generic_to_shared(dsm);
    const uint32_t KVB0 = 18432u, KVSZ = 18432u, VOFF = 9216u;

    for (int i = tid; i < LL; i += 256) s_maskAll[i] = g_mask[b * LL + i];

    {
        int r = tid >> 1;
        long src = (long)(b * HW + q0 + r) * HID + h * DH;
        uint32_t dst = sb + (uint32_t)(r * 144);
#pragma unroll
        for (int cc = 0; cc < 4; cc++) {
            int chs = (tid & 1) * 4 + cc;
            cpa16(dst + chs * 16, g_qf + src + chs * 8);
        }
    }
    CP_COMMIT();

    auto issueKV = [&](int kt) {
        int r = tid >> 2;
        long src = (long)(b * LL + kt * 64 + r) * HID + h * DH;
        uint32_t dst = sb + KVB0 + (uint32_t)(kt & 1) * KVSZ + (uint32_t)(r * 144);
#pragma unroll
        for (int cc = 0; cc < 2; cc++) {
            int chs = (tid & 3) * 2 + cc;
            cpa16(dst +        chs * 16, g_kf + src + chs * 8);
            cpa16(dst + VOFF + chs * 16, g_vf + src + chs * 8);
        }
    };
    issueKV(0); CP_COMMIT();

    CP_WAIT(1);
    __syncthreads();
    uint32_t qh[4][4];
    {
        int m0w = wid * 16;
#pragma unroll
        for (int ks = 0; ks < 4; ks++) {
            uint32_t off = (uint32_t)(((m0w + arow) * 72 + ks * 16 + acol8) * 2);
            ldsm4(qh[ks][0], qh[ks][1], qh[ks][2], qh[ks][3], sb + off);
        }
    }

    float oacc[8][4] = {};
    float mr0 = -1e30f, mr1 = -1e30f, lr0 = 0.f, lr1 = 0.f;

    for (int kt = 0; kt < LL / 64; kt++) {
        if (kt + 1 < LL / 64) { issueKV(kt + 1); CP_COMMIT(); CP_WAIT(1); }
        else                  { CP_WAIT(0); }
        __syncthreads();
        const uint32_t kvb = sb + KVB0 + (uint32_t)(kt & 1) * KVSZ;
        const int k0g = kt * 64;

        float sacc[8][4] = {};
#pragma unroll
        for (int ks = 0; ks < 4; ks++) {
#pragma unroll
            for (int jj = 0; jj < 4; jj++) {
                uint32_t bh[4];
                uint32_t off = (uint32_t)(((16 * jj + arow) * 72 + ks * 16 + acol8) * 2);
                ldsm4(bh[0], bh[1], bh[2], bh[3], kvb + off);
                mma16816h(sacc[2*jj],   qh[ks], bh[0], bh[2]);
                mma16816h(sacc[2*jj+1], qh[ks], bh[1], bh[3]);
            }
        }

        const float cscale = 0.1803368801f;
        float mn0 = mr0, mn1 = mr1;
#pragma unroll
        for (int j = 0; j < 8; j++) {
            int kc = 8 * j + 2 * lam;
            bool k0m = s_maskAll[k0g + kc] != 0, k1m = s_maskAll[k0g + kc + 1] != 0;
            sacc[j][0] = k0m ? -1e9f : sacc[j][0] * cscale;
            sacc[j][1] = k1m ? -1e9f : sacc[j][1] * cscale;
            sacc[j][2] = k0m ? -1e9f : sacc[j][2] * cscale;
            sacc[j][3] = k1m ? -1e9f : sacc[j][3] * cscale;
            mn0 = fmaxf(mn0, fmaxf(sacc[j][0], sacc[j][1]));
            mn1 = fmaxf(mn1, fmaxf(sacc[j][2], sacc[j][3]));
        }
        mn0 = fmaxf(mn0, __shfl_xor_sync(0xffffffffu, mn0, 1));
        mn0 = fmaxf(mn0, __shfl_xor_sync(0xffffffffu, mn0, 2));
        mn1 = fmaxf(mn1, __shfl_xor_sync(0xffffffffu, mn1, 1));
        mn1 = fmaxf(mn1, __shfl_xor_sync(0xffffffffu, mn1, 2));
        float cs0 = fexp2f(mr0 - mn0), cs1 = fexp2f(mr1 - mn1);
        mr0 = mn0; mr1 = mn1;
        float rs0 = 0.f, rs1 = 0.f;
        uint32_t ph[8][2];
#pragma unroll
        for (int j = 0; j < 8; j++) {
            float p0 = fexp2f(sacc[j][0] - mn0);
            float p1 = fexp2f(sacc[j][1] - mn0);
            float p2 = fexp2f(sacc[j][2] - mn1);
            float p3 = fexp2f(sacc[j][3] - mn1);
            rs0 += p0 + p1; rs1 += p2 + p3;
            ph[j][0] = packh2(p0, p1);
            ph[j][1] = packh2(p2, p3);
        }
        rs0 += __shfl_xor_sync(0xffffffffu, rs0, 1);
        rs0 += __shfl_xor_sync(0xffffffffu, rs0, 2);
        rs1 += __shfl_xor_sync(0xffffffffu, rs1, 1);
        rs1 += __shfl_xor_sync(0xffffffffu, rs1, 2);
        lr0 = lr0 * cs0 + rs0;
        lr1 = lr1 * cs1 + rs1;
#pragma unroll
        for (int j = 0; j < 8; j++) {
            oacc[j][0] *= cs0; oacc[j][1] *= cs0;
            oacc[j][2] *= cs1; oacc[j][3] *= cs1;
        }

#pragma unroll
        for (int s = 0; s < 4; s++) {
            uint32_t pah[4] = { ph[2*s][0], ph[2*s][1], ph[2*s+1][0], ph[2*s+1][1] };
#pragma unroll
            for (int jj = 0; jj < 4; jj++) {
                uint32_t vh[4];
                uint32_t off = (uint32_t)(((16 * s + arow) * 72 + jj * 16 + acol8) * 2);
                ldsm4t(vh[0], vh[1], vh[2], vh[3], kvb + VOFF + off);
                mma16816h(oacc[2*jj],   pah, vh[0], vh[1]);
                mma16816h(oacc[2*jj+1], pah, vh[2], vh[3]);
            }
        }
        __syncthreads();
    }

    // epilogue -> fp16 tiled ao (row-tile (b*HW+q0)>>7, k-tile h)
    float i0 = 1.f / lr0, i1 = 1.f / lr1;
    int row0 = q0 + wid * 16 + g;
    size_t tbase = ((size_t)b * HW + q0) * HID * 2 + (size_t)h * 16384;
#pragma unroll
    for (int j = 0; j < 8; j++) {
        int cin = 8 * j + 2 * lam;
        uint32_t h0 = packh2(oacc[j][0] * i0, oacc[j][1] * i0);
        uint32_t h1 = packh2(oacc[j][2] * i1, oacc[j][3] * i1);
        uint32_t o0 = swz128((uint32_t)((row0 - q0) * 128 + cin * 2));
        uint32_t o1 = swz128((uint32_t)((row0 - q0 + 8) * 128 + cin * 2));
        *(uint32_t*)((char*)g_ao_f + tbase + o0) = h0;
        *(uint32_t*)((char*)g_ao_f + tbase + o1) = h1;
    }
}

// ---------------------------------------------------------------------------
extern "C" void kernel_launch(void* const* d_in, const int* in_sizes, int n_in,
                              void* d_out, int out_size)
{
    const float* v  = (const float*)d_in[0];
    const float* k  = (const float*)d_in[1];
    const float* q  = (const float*)d_in[2];
    const unsigned char* mask = (const unsigned char*)d_in[3];
    const float* Wv = (const float*)d_in[4];
    const float* bv = (const float*)d_in[5];
    const float* Wk = (const float*)d_in[6];
    const float* bk = (const float*)d_in[7];
    const float* Wq = (const float*)d_in[8];
    const float* bq = (const float*)d_in[9];
    const float* Wm = (const float*)d_in[10];
    const float* bm = (const float*)d_in[11];
    float* out = (float*)d_out;

    __half* qt_f;
    cudaGetSymbolAddress((void**)&qt_f, g_qt_f);

    const int GEMM_SMEM = 65536 + 16;
    const int ATTN_SMEM = 18432 + 2 * 18432;   // 55296
    cudaFuncSetAttribute((const void*)proj_gemm,   cudaFuncAttributeMaxDynamicSharedMemorySize, GEMM_SMEM);
    cudaFuncSetAttribute((const void*)out_gemm,    cudaFuncAttributeMaxDynamicSharedMemorySize, GEMM_SMEM);
    cudaFuncSetAttribute((const void*)attn_kernel, cudaFuncAttributeMaxDynamicSharedMemorySize, ATTN_SMEM);

    mask_norm_kernel<<<1, 256>>>(mask);

    // fused packs: k+v inputs (z 0..1), weights (z 0..3)
    pack_kv<<<dim3((BB*LL*64 + 255)/256, 2), 256>>>(k, v, BB*LL*64);
    pack_w <<<dim3((HID*64 + 255)/256, 4), 256>>>(Wk, Wv, Wq, Wm, HID*64);
    transpose_pack_q<<<dim3(HW/32, HID/32, BB), dim3(32, 8)>>>(q, qt_f);

    // fused projections: z = {k, v, q} -> fp16 row-major
    proj_gemm<<<dim3(HID/128, (BB*LL)/128, 3), 256, GEMM_SMEM>>>(bk, bv, bq);

    attn_kernel<<<dim3(HW/128, NH, BB), 256, ATTN_SMEM>>>();

    // output projection (fp16), batched over z
    out_gemm<<<dim3(HW/128, 512/128, BB), 256, GEMM_SMEM>>>(bm, out);
}

// round 12
// speedup vs baseline: 2.5139x; 1.0202x over previous
#include <cuda_runtime.h>
#include <cuda_bf16.h>
#include <cuda_fp16.h>
#include <math.h>
#include <stdint.h>

#define BB   8
#define LL   1024
#define HW   1024
#define HID  512
#define NH   8
#define DH   64

// fp16 tiled-swizzled GEMM operands: [tile (row>>7)*8 + (k>>6)][128x64 SW128 16KB]
__device__ __half g_kin_f[BB*LL*HID];
__device__ __half g_vin_f[BB*LL*HID];
__device__ __half g_qt_f [BB*HW*HID];
__device__ __half g_wk_f[HID*HID];
__device__ __half g_wv_f[HID*HID];
__device__ __half g_wq_f[HID*HID];
__device__ __half g_wm_f[HID*HID];
__device__ __half g_ao_f[BB*HW*HID];    // tiled (out-proj B operand)
// head-separated swizzled attention operands:
// K/V: [b][h][ltile 0..15][64x64 fp16 SW128 8KB]; Q: [b][h][qtile 0..7][128x64 16KB]
__device__ __half g_kf2[BB*LL*HID];
__device__ __half g_vf2[BB*LL*HID];
__device__ __half g_qf2[BB*HW*HID];
__device__ unsigned char g_mask[BB*LL];

// ---------------- helpers ----------------
__device__ __forceinline__ uint32_t packh2(float a, float b)
{
    __half2 h = __floats2half2_rn(a, b);
    return *reinterpret_cast<uint32_t*>(&h);
}
__device__ __forceinline__ float fexp2f(float x)
{
    x = fmaxf(x, -126.0f);
    int   n = __float2int_rn(x);
    float f = x - (float)n;
    float p = 1.33336498e-3f;
    p = fmaf(p, f, 9.61817007e-3f);
    p = fmaf(p, f, 5.55041087e-2f);
    p = fmaf(p, f, 2.40226507e-1f);
    p = fmaf(p, f, 6.93147181e-1f);
    p = fmaf(p, f, 1.0f);
    return p * __int_as_float((n + 127) << 23);
}
__device__ __forceinline__ void ldsm4(uint32_t& r0, uint32_t& r1, uint32_t& r2, uint32_t& r3, uint32_t a)
{
    asm volatile("ldmatrix.sync.aligned.m8n8.x4.shared.b16 {%0,%1,%2,%3}, [%4];"
                 : "=r"(r0), "=r"(r1), "=r"(r2), "=r"(r3) : "r"(a));
}
__device__ __forceinline__ void ldsm4t(uint32_t& r0, uint32_t& r1, uint32_t& r2, uint32_t& r3, uint32_t a)
{
    asm volatile("ldmatrix.sync.aligned.m8n8.x4.trans.shared.b16 {%0,%1,%2,%3}, [%4];"
                 : "=r"(r0), "=r"(r1), "=r"(r2), "=r"(r3) : "r"(a));
}
__device__ __forceinline__ void mma16816h(float* d, const uint32_t* a, uint32_t b0, uint32_t b1)
{
    asm volatile("mma.sync.aligned.m16n8k16.row.col.f32.f16.f16.f32 "
                 "{%0,%1,%2,%3}, {%4,%5,%6,%7}, {%8,%9}, {%0,%1,%2,%3};"
                 : "+f"(d[0]), "+f"(d[1]), "+f"(d[2]), "+f"(d[3])
                 : "r"(a[0]), "r"(a[1]), "r"(a[2]), "r"(a[3]), "r"(b0), "r"(b1));
}
__device__ __forceinline__ uint32_t swz128(uint32_t o) { return o ^ ((o >> 3) & 0x70); }

__device__ __forceinline__ void mbar_init(uint32_t a, uint32_t c)
{ asm volatile("mbarrier.init.shared.b64 [%0], %1;" :: "r"(a), "r"(c) : "memory"); }
__device__ __forceinline__ void mbar_expect(uint32_t a, uint32_t bytes)
{ asm volatile("mbarrier.arrive.expect_tx.shared.b64 _, [%0], %1;" :: "r"(a), "r"(bytes) : "memory"); }
__device__ __forceinline__ void mbar_wait(uint32_t a, uint32_t par)
{
    asm volatile(
        "{\n\t.reg .pred P;\n"
        "W%=:\n\tmbarrier.try_wait.parity.acquire.cta.shared::cta.b64 P, [%0], %1, 0x989680;\n"
        "\t@P bra.uni D%=;\n\tbra.uni W%=;\nD%=:\n\t}"
        :: "r"(a), "r"(par) : "memory");
}
__device__ __forceinline__ void bulk_g2s(uint32_t dst, const void* src, uint32_t bytes, uint32_t mbar)
{
    asm volatile("cp.async.bulk.shared::cta.global.mbarrier::complete_tx::bytes [%0], [%1], %2, [%3];"
                 :: "r"(dst), "l"(src), "r"(bytes), "r"(mbar) : "memory");
}

// ---------------- mask normalization (verified) ----------------
__global__ void mask_norm_kernel(const unsigned char* __restrict__ m)
{
    __shared__ int s_wide, s_bytes;
    if (threadIdx.x == 0) { s_wide = 0; s_bytes = 0; }
    __syncthreads();
    int wide = 0, bytes = 0;
    for (int i = threadIdx.x; i < BB*LL; i += blockDim.x) {
        unsigned char c = m[i];
        if (c > 1) wide = 1;
        else if (c != 0 && (i & 3) != 0) bytes = 1;
    }
    if (wide)  atomicOr(&s_wide, 1);
    if (bytes) atomicOr(&s_bytes, 1);
    __syncthreads();
    const bool is_u8 = (!s_wide) && s_bytes;
    for (int i = threadIdx.x; i < BB*LL; i += blockDim.x) {
        unsigned char vv;
        if (is_u8) vv = (m[i] != 0);
        else       vv = (((const int*)m)[i] != 0);
        g_mask[i] = vv;
    }
}

// ---------------- fp32 [R][512] -> fp16 tiled-swizzled (core) ----------------
__device__ __forceinline__ void pack_one(const float* in, __half* o, int i)
{
    int row = i >> 6;
    int kc  = (i & 63) * 8;
    const float4* p = (const float4*)(in + (size_t)row * HID + kc);
    float4 a = p[0], b = p[1];
    uint32_t h0 = packh2(a.x, a.y), h1 = packh2(a.z, a.w);
    uint32_t h2 = packh2(b.x, b.y), h3 = packh2(b.z, b.w);
    uint32_t off = swz128((uint32_t)((row & 127) * 128 + (kc & 63) * 2));
    size_t base = ((size_t)(row >> 7) * 8 + (kc >> 6)) * 16384 + off;
    *(uint4*)((char*)o + base) = make_uint4(h0, h1, h2, h3);
}

__global__ void pack_kv(const float* __restrict__ k, const float* __restrict__ v, int nch)
{
    int i = blockIdx.x * blockDim.x + threadIdx.x;
    if (i >= nch) return;
    if (blockIdx.y == 0) pack_one(k, g_kin_f, i);
    else                 pack_one(v, g_vin_f, i);
}

__global__ void pack_w(const float* __restrict__ Wk, const float* __restrict__ Wv,
                       const float* __restrict__ Wq, const float* __restrict__ Wm, int nch)
{
    int i = blockIdx.x * blockDim.x + threadIdx.x;
    if (i >= nch) return;
    int z = blockIdx.y;
    if (z == 0)      pack_one(Wk, g_wk_f, i);
    else if (z == 1) pack_one(Wv, g_wv_f, i);
    else if (z == 2) pack_one(Wq, g_wq_f, i);
    else             pack_one(Wm, g_wm_f, i);
}

// ---------------- q transpose -> fp16 tiled ----------------
__global__ void transpose_pack_q(const float* __restrict__ in, __half* __restrict__ o)
{
    __shared__ float t[32][33];
    int b = blockIdx.z;
    int hw0 = blockIdx.x * 32, c0 = blockIdx.y * 32;
    const float* ip = in + ((long)b * HID + c0) * HW + hw0;
#pragma unroll
    for (int j = 0; j < 32; j += 8)
        t[threadIdx.y + j][threadIdx.x] = ip[(long)(threadIdx.y + j) * HW + threadIdx.x];
    __syncthreads();
#pragma unroll
    for (int j = 0; j < 32; j += 8) {
        float v = t[threadIdx.x][threadIdx.y + j];
        int rowg = b * HW + hw0 + threadIdx.y + j;
        int col  = c0 + threadIdx.x;
        uint32_t off = swz128((uint32_t)((rowg & 127) * 128 + (col & 63) * 2));
        size_t base = ((size_t)(rowg >> 7) * 8 + (col >> 6)) * 16384 + off;
        *(__half*)((char*)o + base) = __float2half_rn(v);
    }
}

// ---------------------------------------------------------------------------
// fp16 single-term GEMM mainloop (verified R10/R11).
// ---------------------------------------------------------------------------
__device__ __forceinline__ void gemm_mainloop_h(
    const __half* A, const __half* B, size_t at, size_t bt,
    uint32_t sb, int tid, int lane, int wid, float acc[4][4][4])
{
    const int wm = (wid & 1) * 64, wn = (wid >> 1) * 32;
    const int arow = lane & 15, acol8 = (lane >> 4) * 8;
    const uint32_t F0 = 65536u, F1 = 65544u;

    if (tid == 0) { mbar_init(sb + F0, 1); mbar_init(sb + F1, 1); }
    __syncthreads();
    if (tid == 0) {
        mbar_expect(sb + F0, 32768u);
        bulk_g2s(sb,           A + at * 8192, 16384u, sb + F0);
        bulk_g2s(sb + 16384u,  B + bt * 8192, 16384u, sb + F0);
        mbar_expect(sb + F1, 32768u);
        bulk_g2s(sb + 32768u,  A + (at + 1) * 8192, 16384u, sb + F1);
        bulk_g2s(sb + 49152u,  B + (bt + 1) * 8192, 16384u, sb + F1);
    }
    for (int s = 0; s < 8; s++) {
        mbar_wait((s & 1) ? sb + F1 : sb + F0, (uint32_t)((s >> 1) & 1));
        uint32_t bb = sb + (uint32_t)(s & 1) * 32768u;
#pragma unroll
        for (int ks = 0; ks < 4; ks++) {
            const int kc = ks * 16 + acol8;
            uint32_t ah[4][4];
#pragma unroll
            for (int i = 0; i < 4; i++) {
                uint32_t off = swz128((uint32_t)(((wm + 16 * i + arow) << 7) + (kc << 1)));
                ldsm4(ah[i][0], ah[i][1], ah[i][2], ah[i][3], bb + off);
            }
#pragma unroll
            for (int jj = 0; jj < 2; jj++) {
                uint32_t bh[4];
                uint32_t off = swz128((uint32_t)(((wn + 16 * jj + arow) << 7) + (kc << 1)));
                ldsm4(bh[0], bh[1], bh[2], bh[3], bb + 16384u + off);
#pragma unroll
                for (int i = 0; i < 4; i++) {
                    mma16816h(acc[i][2*jj],   ah[i], bh[0], bh[2]);
                    mma16816h(acc[i][2*jj+1], ah[i], bh[1], bh[3]);
                }
            }
        }
        __syncthreads();
        if (tid == 0 && s + 2 < 8) {
            uint32_t full = (s & 1) ? sb + F1 : sb + F0;
            uint32_t base = sb + (uint32_t)(s & 1) * 32768u;
            mbar_expect(full, 32768u);
            bulk_g2s(base,           A + (at + s + 2) * 8192, 16384u, full);
            bulk_g2s(base + 16384u,  B + (bt + s + 2) * 8192, 16384u, full);
        }
    }
}

// ---- fused k/v/q projections: epilogue writes head-separated swizzled tiles ----
__global__ __launch_bounds__(256, 1)
void proj_gemm(const float* __restrict__ bk, const float* __restrict__ bv,
               const float* __restrict__ bq)
{
    extern __shared__ char smc[];
    const uint32_t sb = (uint32_t)__cvta_generic_to_shared(smc);
    const int tid = threadIdx.x, lane = tid & 31, wid = tid >> 5;
    const int m0 = blockIdx.y * 128, n0 = blockIdx.x * 128, z = blockIdx.z;

    const __half *A, *B;
    const float* bias;
    if (z == 0)      { A = g_kin_f; B = g_wk_f; bias = bk; }
    else if (z == 1) { A = g_vin_f; B = g_wv_f; bias = bv; }
    else             { A = g_qt_f;  B = g_wq_f; bias = bq; }

    float acc[4][4][4] = {};
    gemm_mainloop_h(A, B, (size_t)(m0 >> 7) * 8, (size_t)(n0 >> 7) * 8,
                    sb, tid, lane, wid, acc);

    const int wm = (wid & 1) * 64, wn = (wid >> 1) * 32;
    const int g = lane >> 2, lam = lane & 3;
#pragma unroll
    for (int i = 0; i < 4; i++) {
#pragma unroll
        for (int j = 0; j < 4; j++) {
            int row0 = m0 + wm + 16 * i + g;
            int col  = n0 + wn + 8 * j + 2 * lam;
            float b0 = bias[col], b1 = bias[col + 1];
            uint32_t p0 = packh2(acc[i][j][0] + b0, acc[i][j][1] + b1);
            uint32_t p1 = packh2(acc[i][j][2] + b0, acc[i][j][3] + b1);
            int hh = col >> 6, cin = col & 63;
            if (z < 2) {
                // 64x64 tiles: [b][h][ltile][8KB]
                __half* dst = (z == 0) ? g_kf2 : g_vf2;
                int r1 = row0 + 8;
                size_t tb0 = (((size_t)(row0 >> 10) * 8 + hh) * 16 + ((row0 & 1023) >> 6)) * 8192;
                size_t tb1 = (((size_t)(r1 >> 10) * 8 + hh) * 16 + ((r1 & 1023) >> 6)) * 8192;
                *(uint32_t*)((char*)dst + tb0 + swz128((uint32_t)((row0 & 63) * 128 + cin * 2))) = p0;
                *(uint32_t*)((char*)dst + tb1 + swz128((uint32_t)((r1 & 63) * 128 + cin * 2)))   = p1;
            } else {
                // 128x64 tiles: [b][h][qtile][16KB]
                int r1 = row0 + 8;
                size_t tb0 = (((size_t)(row0 >> 10) * 8 + hh) * 8 + ((row0 & 1023) >> 7)) * 16384;
                size_t tb1 = (((size_t)(r1 >> 10) * 8 + hh) * 8 + ((r1 & 1023) >> 7)) * 16384;
                *(uint32_t*)((char*)g_qf2 + tb0 + swz128((uint32_t)((row0 & 127) * 128 + cin * 2))) = p0;
                *(uint32_t*)((char*)g_qf2 + tb1 + swz128((uint32_t)((r1 & 127) * 128 + cin * 2)))   = p1;
            }
        }
    }
}

// ---- output projection (verified R11): C[z][o][hw] = Wm . ao^T + bm, relu ----
__global__ __launch_bounds__(256, 1)
void out_gemm(const float* __restrict__ bm, float* __restrict__ out)
{
    extern __shared__ char smc[];
    const uint32_t sb = (uint32_t)__cvta_generic_to_shared(smc);
    const int tid = threadIdx.x, lane = tid & 31, wid = tid >> 5;
    const int m0 = blockIdx.y * 128, n0 = blockIdx.x * 128, z = blockIdx.z;

    float acc[4][4][4] = {};
    gemm_mainloop_h(g_wm_f, g_ao_f,
                    (size_t)(m0 >> 7) * 8, (size_t)((z * HW + n0) >> 7) * 8,
                    sb, tid, lane, wid, acc);

    const int wm = (wid & 1) * 64, wn = (wid >> 1) * 32;
    const int g = lane >> 2, lam = lane & 3;
    float* cfp = out + (size_t)z * 512 * HW;
#pragma unroll
    for (int i = 0; i < 4; i++) {
#pragma unroll
        for (int j = 0; j < 4; j++) {
            int row0 = m0 + wm + 16 * i + g;
            int col  = n0 + wn + 8 * j + 2 * lam;
            float ba = bm[row0], bb2 = bm[row0 + 8];
            float v00 = fmaxf(acc[i][j][0] + ba, 0.f),  v01 = fmaxf(acc[i][j][1] + ba, 0.f);
            float v10 = fmaxf(acc[i][j][2] + bb2, 0.f), v11 = fmaxf(acc[i][j][3] + bb2, 0.f);
            *(float2*)&cfp[(size_t)row0 * HW + col]       = make_float2(v00, v01);
            *(float2*)&cfp[(size_t)(row0 + 8) * HW + col] = make_float2(v10, v11);
        }
    }
}

// ---------------------------------------------------------------------------
// Flash attention: fp16, Br=128, Bc=64, bulk-copy loads, 2 CTAs/SM.
// smem: Q 16KB | 2 x [K 8KB | V 8KB] = 48KB + barriers.
// ---------------------------------------------------------------------------
__global__ __launch_bounds__(256, 2)
void attn_kernel()
{
    extern __shared__ __align__(1024) uint32_t dsm[];
    __shared__ unsigned char s_maskAll[LL];
    const int tid = threadIdx.x, lane = tid & 31, wid = tid >> 5;
    const int b = blockIdx.z, h = blockIdx.y, q0 = blockIdx.x * 128;
    const int arow = lane & 15, acol8 = (lane >> 4) * 8;
    const int g = lane >> 2, lam = lane & 3;
    const uint32_t sb = (uint32_t)__cvta_generic_to_shared(dsm);
    const uint32_t KVB0 = 16384u, KVSZ = 16384u, VOFF = 8192u;
    const uint32_t FQ = 49152u, F0 = 49160u, F1 = 49168u;

    const __half* qtile = g_qf2 + (((size_t)b * 8 + h) * 8 + (q0 >> 7)) * 8192;
    const __half* kbase = g_kf2 + ((size_t)b * 8 + h) * 16 * 4096;
    const __half* vbase = g_vf2 + ((size_t)b * 8 + h) * 16 * 4096;

    if (tid == 0) { mbar_init(sb + FQ, 1); mbar_init(sb + F0, 1); mbar_init(sb + F1, 1); }
    __syncthreads();
    if (tid == 0) {
        mbar_expect(sb + FQ, 16384u);
        bulk_g2s(sb, qtile, 16384u, sb + FQ);
        mbar_expect(sb + F0, 16384u);
        bulk_g2s(sb + KVB0,        kbase,        8192u, sb + F0);
        bulk_g2s(sb + KVB0 + VOFF, vbase,        8192u, sb + F0);
        mbar_expect(sb + F1, 16384u);
        bulk_g2s(sb + KVB0 + KVSZ,        kbase + 4096, 8192u, sb + F1);
        bulk_g2s(sb + KVB0 + KVSZ + VOFF, vbase + 4096, 8192u, sb + F1);
    }
    for (int i = tid; i < LL; i += 256) s_maskAll[i] = g_mask[b * LL + i];

    mbar_wait(sb + FQ, 0u);
    uint32_t qh[4][4];
    {
        int m0w = wid * 16;
#pragma unroll
        for (int ks = 0; ks < 4; ks++) {
            uint32_t off = swz128((uint32_t)(((m0w + arow) << 7) + ((ks * 16 + acol8) << 1)));
            ldsm4(qh[ks][0], qh[ks][1], qh[ks][2], qh[ks][3], sb + off);
        }
    }

    float oacc[8][4] = {};
    float mr0 = -1e30f, mr1 = -1e30f, lr0 = 0.f, lr1 = 0.f;

    for (int kt = 0; kt < LL / 64; kt++) {
        mbar_wait((kt & 1) ? sb + F1 : sb + F0, (uint32_t)((kt >> 1) & 1));
        const uint32_t kvb = sb + KVB0 + (uint32_t)(kt & 1) * KVSZ;
        const int k0g = kt * 64;

        // S = Q K^T (fp16)
        float sacc[8][4] = {};
#pragma unroll
        for (int ks = 0; ks < 4; ks++) {
#pragma unroll
            for (int jj = 0; jj < 4; jj++) {
                uint32_t bh[4];
                uint32_t off = swz128((uint32_t)(((16 * jj + arow) << 7) + ((ks * 16 + acol8) << 1)));
                ldsm4(bh[0], bh[1], bh[2], bh[3], kvb + off);
                mma16816h(sacc[2*jj],   qh[ks], bh[0], bh[2]);
                mma16816h(sacc[2*jj+1], qh[ks], bh[1], bh[3]);
            }
        }

        // softmax (log2 domain)
        const float cscale = 0.1803368801f;
        float mn0 = mr0, mn1 = mr1;
#pragma unroll
        for (int j = 0; j < 8; j++) {
            int kc = 8 * j + 2 * lam;
            bool k0m = s_maskAll[k0g + kc] != 0, k1m = s_maskAll[k0g + kc + 1] != 0;
            sacc[j][0] = k0m ? -1e9f : sacc[j][0] * cscale;
            sacc[j][1] = k1m ? -1e9f : sacc[j][1] * cscale;
            sacc[j][2] = k0m ? -1e9f : sacc[j][2] * cscale;
            sacc[j][3] = k1m ? -1e9f : sacc[j][3] * cscale;
            mn0 = fmaxf(mn0, fmaxf(sacc[j][0], sacc[j][1]));
            mn1 = fmaxf(mn1, fmaxf(sacc[j][2], sacc[j][3]));
        }
        mn0 = fmaxf(mn0, __shfl_xor_sync(0xffffffffu, mn0, 1));
        mn0 = fmaxf(mn0, __shfl_xor_sync(0xffffffffu, mn0, 2));
        mn1 = fmaxf(mn1, __shfl_xor_sync(0xffffffffu, mn1, 1));
        mn1 = fmaxf(mn1, __shfl_xor_sync(0xffffffffu, mn1, 2));
        float cs0 = fexp2f(mr0 - mn0), cs1 = fexp2f(mr1 - mn1);
        mr0 = mn0; mr1 = mn1;
        float rs0 = 0.f, rs1 = 0.f;
        uint32_t ph[8][2];
#pragma unroll
        for (int j = 0; j < 8; j++) {
            float p0 = fexp2f(sacc[j][0] - mn0);
            float p1 = fexp2f(sacc[j][1] - mn0);
            float p2 = fexp2f(sacc[j][2] - mn1);
            float p3 = fexp2f(sacc[j][3] - mn1);
            rs0 += p0 + p1; rs1 += p2 + p3;
            ph[j][0] = packh2(p0, p1);
            ph[j][1] = packh2(p2, p3);
        }
        rs0 += __shfl_xor_sync(0xffffffffu, rs0, 1);
        rs0 += __shfl_xor_sync(0xffffffffu, rs0, 2);
        rs1 += __shfl_xor_sync(0xffffffffu, rs1, 1);
        rs1 += __shfl_xor_sync(0xffffffffu, rs1, 2);
        lr0 = lr0 * cs0 + rs0;
        lr1 = lr1 * cs1 + rs1;
#pragma unroll
        for (int j = 0; j < 8; j++) {
            oacc[j][0] *= cs0; oacc[j][1] *= cs0;
            oacc[j][2] *= cs1; oacc[j][3] *= cs1;
        }

        // O += P V (fp16)
#pragma unroll
        for (int s = 0; s < 4; s++) {
            uint32_t pah[4] = { ph[2*s][0], ph[2*s][1], ph[2*s+1][0], ph[2*s+1][1] };
#pragma unroll
            for (int jj = 0; jj < 4; jj++) {
                uint32_t vh[4];
                uint32_t off = swz128((uint32_t)(((16 * s + arow) << 7) + ((jj * 16 + acol8) << 1)));
                ldsm4t(vh[0], vh[1], vh[2], vh[3], kvb + VOFF + off);
                mma16816h(oacc[2*jj],   pah, vh[0], vh[1]);
                mma16816h(oacc[2*jj+1], pah, vh[2], vh[3]);
            }
        }
        __syncthreads();
        if (tid == 0 && kt + 2 < LL / 64) {
            uint32_t full = (kt & 1) ? sb + F1 : sb + F0;
            uint32_t base = sb + KVB0 + (uint32_t)(kt & 1) * KVSZ;
            mbar_expect(full, 16384u);
            bulk_g2s(base,        kbase + (size_t)(kt + 2) * 4096, 8192u, full);
            bulk_g2s(base + VOFF, vbase + (size_t)(kt + 2) * 4096, 8192u, full);
        }
    }

    // epilogue -> fp16 tiled ao (row-tile (b*HW+q0)>>7, k-tile h)
    float i0 = 1.f / lr0, i1 = 1.f / lr1;
    int row0 = q0 + wid * 16 + g;
    size_t tbase = ((size_t)b * HW + q0) * HID * 2 + (size_t)h * 16384;
#pragma unroll
    for (int j = 0; j < 8; j++) {
        int cin = 8 * j + 2 * lam;
        uint32_t h0 = packh2(oacc[j][0] * i0, oacc[j][1] * i0);
        uint32_t h1 = packh2(oacc[j][2] * i1, oacc[j][3] * i1);
        uint32_t o0 = swz128((uint32_t)((row0 - q0) * 128 + cin * 2));
        uint32_t o1 = swz128((uint32_t)((row0 - q0 + 8) * 128 + cin * 2));
        *(uint32_t*)((char*)g_ao_f + tbase + o0) = h0;
        *(uint32_t*)((char*)g_ao_f + tbase + o1) = h1;
    }
}

// ---------------------------------------------------------------------------
extern "C" void kernel_launch(void* const* d_in, const int* in_sizes, int n_in,
                              void* d_out, int out_size)
{
    const float* v  = (const float*)d_in[0];
    const float* k  = (const float*)d_in[1];
    const float* q  = (const float*)d_in[2];
    const unsigned char* mask = (const unsigned char*)d_in[3];
    const float* Wv = (const float*)d_in[4];
    const float* bv = (const float*)d_in[5];
    const float* Wk = (const float*)d_in[6];
    const float* bk = (const float*)d_in[7];
    const float* Wq = (const float*)d_in[8];
    const float* bq = (const float*)d_in[9];
    const float* Wm = (const float*)d_in[10];
    const float* bm = (const float*)d_in[11];
    float* out = (float*)d_out;

    __half* qt_f;
    cudaGetSymbolAddress((void**)&qt_f, g_qt_f);

    const int GEMM_SMEM = 65536 + 16;
    const int ATTN_SMEM = 49152 + 32;
    cudaFuncSetAttribute((const void*)proj_gemm,   cudaFuncAttributeMaxDynamicSharedMemorySize, GEMM_SMEM);
    cudaFuncSetAttribute((const void*)out_gemm,    cudaFuncAttributeMaxDynamicSharedMemorySize, GEMM_SMEM);
    cudaFuncSetAttribute((const void*)attn_kernel, cudaFuncAttributeMaxDynamicSharedMemorySize, ATTN_SMEM);

    mask_norm_kernel<<<1, 256>>>(mask);

    pack_kv<<<dim3((BB*LL*64 + 255)/256, 2), 256>>>(k, v, BB*LL*64);
    pack_w <<<dim3((HID*64 + 255)/256, 4), 256>>>(Wk, Wv, Wq, Wm, HID*64);
    transpose_pack_q<<<dim3(HW/32, HID/32, BB), dim3(32, 8)>>>(q, qt_f);

    // fused projections -> head-separated swizzled K/V/Q tiles
    proj_gemm<<<dim3(HID/128, (BB*LL)/128, 3), 256, GEMM_SMEM>>>(bk, bv, bq);

    attn_kernel<<<dim3(HW/128, NH, BB), 256, ATTN_SMEM>>>();

    // output projection (fp16), batched over z
    out_gemm<<<dim3(HW/128, 512/128, BB), 256, GEMM_SMEM>>>(bm, out);
}

// round 13
// speedup vs baseline: 2.7234x; 1.0833x over previous
#include <cuda_runtime.h>
#include <cuda_bf16.h>
#include <cuda_fp16.h>
#include <math.h>
#include <stdint.h>

#define BB   8
#define LL   1024
#define HW   1024
#define HID  512
#define NH   8
#define DH   64

// fp16 tiled-swizzled GEMM operands: [tile (row>>7)*8 + (k>>6)][128x64 SW128 16KB]
__device__ __half g_kin_f[BB*LL*HID];
__device__ __half g_vin_f[BB*LL*HID];
__device__ __half g_qt_f [BB*HW*HID];
__device__ __half g_wk_f[HID*HID];
__device__ __half g_wv_f[HID*HID];
__device__ __half g_wq_f[HID*HID];
__device__ __half g_wm_f[HID*HID];
__device__ __half g_ao_f[BB*HW*HID];    // tiled (out-proj B operand)
// head-separated swizzled attention operands:
// K/V: [b][h][ltile 0..15][64x64 fp16 SW128 8KB]; Q: [b][h][qtile 0..7][128x64 16KB]
__device__ __half g_kf2[BB*LL*HID];
__device__ __half g_vf2[BB*LL*HID];
__device__ __half g_qf2[BB*HW*HID];
__device__ unsigned char g_mask[BB*LL];

// ---------------- helpers ----------------
__device__ __forceinline__ uint32_t packh2(float a, float b)
{
    __half2 h = __floats2half2_rn(a, b);
    return *reinterpret_cast<uint32_t*>(&h);
}
__device__ __forceinline__ float fexp2f(float x)
{
    x = fmaxf(x, -126.0f);
    int   n = __float2int_rn(x);
    float f = x - (float)n;
    float p = 1.33336498e-3f;
    p = fmaf(p, f, 9.61817007e-3f);
    p = fmaf(p, f, 5.55041087e-2f);
    p = fmaf(p, f, 2.40226507e-1f);
    p = fmaf(p, f, 6.93147181e-1f);
    p = fmaf(p, f, 1.0f);
    return p * __int_as_float((n + 127) << 23);
}
__device__ __forceinline__ void ldsm4(uint32_t& r0, uint32_t& r1, uint32_t& r2, uint32_t& r3, uint32_t a)
{
    asm volatile("ldmatrix.sync.aligned.m8n8.x4.shared.b16 {%0,%1,%2,%3}, [%4];"
                 : "=r"(r0), "=r"(r1), "=r"(r2), "=r"(r3) : "r"(a));
}
__device__ __forceinline__ void ldsm4t(uint32_t& r0, uint32_t& r1, uint32_t& r2, uint32_t& r3, uint32_t a)
{
    asm volatile("ldmatrix.sync.aligned.m8n8.x4.trans.shared.b16 {%0,%1,%2,%3}, [%4];"
                 : "=r"(r0), "=r"(r1), "=r"(r2), "=r"(r3) : "r"(a));
}
__device__ __forceinline__ void mma16816h(float* d, const uint32_t* a, uint32_t b0, uint32_t b1)
{
    asm volatile("mma.sync.aligned.m16n8k16.row.col.f32.f16.f16.f32 "
                 "{%0,%1,%2,%3}, {%4,%5,%6,%7}, {%8,%9}, {%0,%1,%2,%3};"
                 : "+f"(d[0]), "+f"(d[1]), "+f"(d[2]), "+f"(d[3])
                 : "r"(a[0]), "r"(a[1]), "r"(a[2]), "r"(a[3]), "r"(b0), "r"(b1));
}
__device__ __forceinline__ uint32_t swz128(uint32_t o) { return o ^ ((o >> 3) & 0x70); }

__device__ __forceinline__ void mbar_init(uint32_t a, uint32_t c)
{ asm volatile("mbarrier.init.shared.b64 [%0], %1;" :: "r"(a), "r"(c) : "memory"); }
__device__ __forceinline__ void mbar_expect(uint32_t a, uint32_t bytes)
{ asm volatile("mbarrier.arrive.expect_tx.shared.b64 _, [%0], %1;" :: "r"(a), "r"(bytes) : "memory"); }
__device__ __forceinline__ void mbar_wait(uint32_t a, uint32_t par)
{
    asm volatile(
        "{\n\t.reg .pred P;\n"
        "W%=:\n\tmbarrier.try_wait.parity.acquire.cta.shared::cta.b64 P, [%0], %1, 0x989680;\n"
        "\t@P bra.uni D%=;\n\tbra.uni W%=;\nD%=:\n\t}"
        :: "r"(a), "r"(par) : "memory");
}
__device__ __forceinline__ void bulk_g2s(uint32_t dst, const void* src, uint32_t bytes, uint32_t mbar)
{
    asm volatile("cp.async.bulk.shared::cta.global.mbarrier::complete_tx::bytes [%0], [%1], %2, [%3];"
                 :: "r"(dst), "l"(src), "r"(bytes), "r"(mbar) : "memory");
}

// ---------------- fp32 [R][512] -> fp16 tiled-swizzled (core) ----------------
__device__ __forceinline__ void pack_one(const float* in, __half* o, int i)
{
    int row = i >> 6;
    int kc  = (i & 63) * 8;
    const float4* p = (const float4*)(in + (size_t)row * HID + kc);
    float4 a = p[0], b = p[1];
    uint32_t h0 = packh2(a.x, a.y), h1 = packh2(a.z, a.w);
    uint32_t h2 = packh2(b.x, b.y), h3 = packh2(b.z, b.w);
    uint32_t off = swz128((uint32_t)((row & 127) * 128 + (kc & 63) * 2));
    size_t base = ((size_t)(row >> 7) * 8 + (kc >> 6)) * 16384 + off;
    *(uint4*)((char*)o + base) = make_uint4(h0, h1, h2, h3);
}

// ---------------------------------------------------------------------------
// Fused preprocessing: one launch handles q-transpose, k/v packs, weight
// packs, and mask normalization (mask blocks each re-detect dtype locally —
// deterministic, removes cross-block dependency).
// blocks: [0,4096) transQ | [4096,8192) pack k/v | [8192,8704) pack W | [8704,8736) mask
// ---------------------------------------------------------------------------
__global__ __launch_bounds__(256)
void fused_pre(const float* __restrict__ q, const float* __restrict__ k,
               const float* __restrict__ v, const float* __restrict__ Wk,
               const float* __restrict__ Wv, const float* __restrict__ Wq,
               const float* __restrict__ Wm, const unsigned char* __restrict__ m)
{
    const int blk = blockIdx.x, tid = threadIdx.x;
    if (blk < 4096) {
        // q transpose + pack: bx 0..31 (hw), by 0..15 (c), bz 0..7 (b)
        __shared__ float t[32][33];
        int bx = blk & 31, by = (blk >> 5) & 15, bz = blk >> 9;
        int tx = tid & 31, ty = tid >> 5;
        int hw0 = bx * 32, c0 = by * 32;
        const float* ip = q + ((long)bz * HID + c0) * HW + hw0;
#pragma unroll
        for (int j = 0; j < 32; j += 8)
            t[ty + j][tx] = ip[(long)(ty + j) * HW + tx];
        __syncthreads();
#pragma unroll
        for (int j = 0; j < 32; j += 8) {
            float vv = t[tx][ty + j];
            int rowg = bz * HW + hw0 + ty + j;
            int col  = c0 + tx;
            uint32_t off = swz128((uint32_t)((rowg & 127) * 128 + (col & 63) * 2));
            size_t base = ((size_t)(rowg >> 7) * 8 + (col >> 6)) * 16384 + off;
            *(__half*)((char*)g_qt_f + base) = __float2half_rn(vv);
        }
    } else if (blk < 8192) {
        int bb = blk - 4096;
        int i = (bb & 2047) * 256 + tid;
        if (bb < 2048) pack_one(k, g_kin_f, i);
        else           pack_one(v, g_vin_f, i);
    } else if (blk < 8704) {
        int bb = blk - 8192;
        int i = (bb & 127) * 256 + tid;
        int z = bb >> 7;
        if (z == 0)      pack_one(Wk, g_wk_f, i);
        else if (z == 1) pack_one(Wv, g_wv_f, i);
        else if (z == 2) pack_one(Wq, g_wq_f, i);
        else             pack_one(Wm, g_wm_f, i);
    } else {
        // mask normalization: local full detection + write a 256-elem slice
        __shared__ int s_wide, s_bytes;
        if (tid == 0) { s_wide = 0; s_bytes = 0; }
        __syncthreads();
        int wide = 0, bytes = 0;
        for (int i = tid; i < BB*LL; i += 256) {
            unsigned char c = m[i];
            if (c > 1) wide = 1;
            else if (c != 0 && (i & 3) != 0) bytes = 1;
        }
        if (wide)  atomicOr(&s_wide, 1);
        if (bytes) atomicOr(&s_bytes, 1);
        __syncthreads();
        const bool is_u8 = (!s_wide) && s_bytes;
        int i = (blk - 8704) * 256 + tid;
        unsigned char vv;
        if (is_u8) vv = (m[i] != 0);
        else       vv = (((const int*)m)[i] != 0);
        g_mask[i] = vv;
    }
}

// ---------------------------------------------------------------------------
// fp16 single-term GEMM mainloop (verified R10/R11).
// ---------------------------------------------------------------------------
__device__ __forceinline__ void gemm_mainloop_h(
    const __half* A, const __half* B, size_t at, size_t bt,
    uint32_t sb, int tid, int lane, int wid, float acc[4][4][4])
{
    const int wm = (wid & 1) * 64, wn = (wid >> 1) * 32;
    const int arow = lane & 15, acol8 = (lane >> 4) * 8;
    const uint32_t F0 = 65536u, F1 = 65544u;

    if (tid == 0) { mbar_init(sb + F0, 1); mbar_init(sb + F1, 1); }
    __syncthreads();
    if (tid == 0) {
        mbar_expect(sb + F0, 32768u);
        bulk_g2s(sb,           A + at * 8192, 16384u, sb + F0);
        bulk_g2s(sb + 16384u,  B + bt * 8192, 16384u, sb + F0);
        mbar_expect(sb + F1, 32768u);
        bulk_g2s(sb + 32768u,  A + (at + 1) * 8192, 16384u, sb + F1);
        bulk_g2s(sb + 49152u,  B + (bt + 1) * 8192, 16384u, sb + F1);
    }
    for (int s = 0; s < 8; s++) {
        mbar_wait((s & 1) ? sb + F1 : sb + F0, (uint32_t)((s >> 1) & 1));
        uint32_t bb = sb + (uint32_t)(s & 1) * 32768u;
#pragma unroll
        for (int ks = 0; ks < 4; ks++) {
            const int kc = ks * 16 + acol8;
            uint32_t ah[4][4];
#pragma unroll
            for (int i = 0; i < 4; i++) {
                uint32_t off = swz128((uint32_t)(((wm + 16 * i + arow) << 7) + (kc << 1)));
                ldsm4(ah[i][0], ah[i][1], ah[i][2], ah[i][3], bb + off);
            }
#pragma unroll
            for (int jj = 0; jj < 2; jj++) {
                uint32_t bh[4];
                uint32_t off = swz128((uint32_t)(((wn + 16 * jj + arow) << 7) + (kc << 1)));
                ldsm4(bh[0], bh[1], bh[2], bh[3], bb + 16384u + off);
#pragma unroll
                for (int i = 0; i < 4; i++) {
                    mma16816h(acc[i][2*jj],   ah[i], bh[0], bh[2]);
                    mma16816h(acc[i][2*jj+1], ah[i], bh[1], bh[3]);
                }
            }
        }
        __syncthreads();
        if (tid == 0 && s + 2 < 8) {
            uint32_t full = (s & 1) ? sb + F1 : sb + F0;
            uint32_t base = sb + (uint32_t)(s & 1) * 32768u;
            mbar_expect(full, 32768u);
            bulk_g2s(base,           A + (at + s + 2) * 8192, 16384u, full);
            bulk_g2s(base + 16384u,  B + (bt + s + 2) * 8192, 16384u, full);
        }
    }
}

// ---- fused k/v/q projections (verified R12 epilogue), now 2 CTAs/SM ----
__global__ __launch_bounds__(256, 2)
void proj_gemm(const float* __restrict__ bk, const float* __restrict__ bv,
               const float* __restrict__ bq)
{
    extern __shared__ char smc[];
    const uint32_t sb = (uint32_t)__cvta_generic_to_shared(smc);
    const int tid = threadIdx.x, lane = tid & 31, wid = tid >> 5;
    const int m0 = blockIdx.y * 128, n0 = blockIdx.x * 128, z = blockIdx.z;

    const __half *A, *B;
    const float* bias;
    if (z == 0)      { A = g_kin_f; B = g_wk_f; bias = bk; }
    else if (z == 1) { A = g_vin_f; B = g_wv_f; bias = bv; }
    else             { A = g_qt_f;  B = g_wq_f; bias = bq; }

    float acc[4][4][4] = {};
    gemm_mainloop_h(A, B, (size_t)(m0 >> 7) * 8, (size_t)(n0 >> 7) * 8,
                    sb, tid, lane, wid, acc);

    const int wm = (wid & 1) * 64, wn = (wid >> 1) * 32;
    const int g = lane >> 2, lam = lane & 3;
#pragma unroll
    for (int i = 0; i < 4; i++) {
#pragma unroll
        for (int j = 0; j < 4; j++) {
            int row0 = m0 + wm + 16 * i + g;
            int col  = n0 + wn + 8 * j + 2 * lam;
            float b0 = bias[col], b1 = bias[col + 1];
            uint32_t p0 = packh2(acc[i][j][0] + b0, acc[i][j][1] + b1);
            uint32_t p1 = packh2(acc[i][j][2] + b0, acc[i][j][3] + b1);
            int hh = col >> 6, cin = col & 63;
            if (z < 2) {
                __half* dst = (z == 0) ? g_kf2 : g_vf2;
                int r1 = row0 + 8;
                size_t tb0 = (((size_t)(row0 >> 10) * 8 + hh) * 16 + ((row0 & 1023) >> 6)) * 8192;
                size_t tb1 = (((size_t)(r1 >> 10) * 8 + hh) * 16 + ((r1 & 1023) >> 6)) * 8192;
                *(uint32_t*)((char*)dst + tb0 + swz128((uint32_t)((row0 & 63) * 128 + cin * 2))) = p0;
                *(uint32_t*)((char*)dst + tb1 + swz128((uint32_t)((r1 & 63) * 128 + cin * 2)))   = p1;
            } else {
                int r1 = row0 + 8;
                size_t tb0 = (((size_t)(row0 >> 10) * 8 + hh) * 8 + ((row0 & 1023) >> 7)) * 16384;
                size_t tb1 = (((size_t)(r1 >> 10) * 8 + hh) * 8 + ((r1 & 1023) >> 7)) * 16384;
                *(uint32_t*)((char*)g_qf2 + tb0 + swz128((uint32_t)((row0 & 127) * 128 + cin * 2))) = p0;
                *(uint32_t*)((char*)g_qf2 + tb1 + swz128((uint32_t)((r1 & 127) * 128 + cin * 2)))   = p1;
            }
        }
    }
}

// ---- output projection (verified R11), now 2 CTAs/SM ----
__global__ __launch_bounds__(256, 2)
void out_gemm(const float* __restrict__ bm, float* __restrict__ out)
{
    extern __shared__ char smc[];
    const uint32_t sb = (uint32_t)__cvta_generic_to_shared(smc);
    const int tid = threadIdx.x, lane = tid & 31, wid = tid >> 5;
    const int m0 = blockIdx.y * 128, n0 = blockIdx.x * 128, z = blockIdx.z;

    float acc[4][4][4] = {};
    gemm_mainloop_h(g_wm_f, g_ao_f,
                    (size_t)(m0 >> 7) * 8, (size_t)((z * HW + n0) >> 7) * 8,
                    sb, tid, lane, wid, acc);

    const int wm = (wid & 1) * 64, wn = (wid >> 1) * 32;
    const int g = lane >> 2, lam = lane & 3;
    float* cfp = out + (size_t)z * 512 * HW;
#pragma unroll
    for (int i = 0; i < 4; i++) {
#pragma unroll
        for (int j = 0; j < 4; j++) {
            int row0 = m0 + wm + 16 * i + g;
            int col  = n0 + wn + 8 * j + 2 * lam;
            float ba = bm[row0], bb2 = bm[row0 + 8];
            float v00 = fmaxf(acc[i][j][0] + ba, 0.f),  v01 = fmaxf(acc[i][j][1] + ba, 0.f);
            float v10 = fmaxf(acc[i][j][2] + bb2, 0.f), v11 = fmaxf(acc[i][j][3] + bb2, 0.f);
            *(float2*)&cfp[(size_t)row0 * HW + col]       = make_float2(v00, v01);
            *(float2*)&cfp[(size_t)(row0 + 8) * HW + col] = make_float2(v10, v11);
        }
    }
}

// ---------------------------------------------------------------------------
// Flash attention (verified R12): fp16, Br=128, Bc=64, bulk loads, 2 CTAs/SM.
// ---------------------------------------------------------------------------
__global__ __launch_bounds__(256, 2)
void attn_kernel()
{
    extern __shared__ __align__(1024) uint32_t dsm[];
    __shared__ unsigned char s_maskAll[LL];
    const int tid = threadIdx.x, lane = tid & 31, wid = tid >> 5;
    const int b = blockIdx.z, h = blockIdx.y, q0 = blockIdx.x * 128;
    const int arow = lane & 15, acol8 = (lane >> 4) * 8;
    const int g = lane >> 2, lam = lane & 3;
    const uint32_t sb = (uint32_t)__cvta_generic_to_shared(dsm);
    const uint32_t KVB0 = 16384u, KVSZ = 16384u, VOFF = 8192u;
    const uint32_t FQ = 49152u, F0 = 49160u, F1 = 49168u;

    const __half* qtile = g_qf2 + (((size_t)b * 8 + h) * 8 + (q0 >> 7)) * 8192;
    const __half* kbase = g_kf2 + ((size_t)b * 8 + h) * 16 * 4096;
    const __half* vbase = g_vf2 + ((size_t)b * 8 + h) * 16 * 4096;

    if (tid == 0) { mbar_init(sb + FQ, 1); mbar_init(sb + F0, 1); mbar_init(sb + F1, 1); }
    __syncthreads();
    if (tid == 0) {
        mbar_expect(sb + FQ, 16384u);
        bulk_g2s(sb, qtile, 16384u, sb + FQ);
        mbar_expect(sb + F0, 16384u);
        bulk_g2s(sb + KVB0,        kbase,        8192u, sb + F0);
        bulk_g2s(sb + KVB0 + VOFF, vbase,        8192u, sb + F0);
        mbar_expect(sb + F1, 16384u);
        bulk_g2s(sb + KVB0 + KVSZ,        kbase + 4096, 8192u, sb + F1);
        bulk_g2s(sb + KVB0 + KVSZ + VOFF, vbase + 4096, 8192u, sb + F1);
    }
    for (int i = tid; i < LL; i += 256) s_maskAll[i] = g_mask[b * LL + i];

    mbar_wait(sb + FQ, 0u);
    uint32_t qh[4][4];
    {
        int m0w = wid * 16;
#pragma unroll
        for (int ks = 0; ks < 4; ks++) {
            uint32_t off = swz128((uint32_t)(((m0w + arow) << 7) + ((ks * 16 + acol8) << 1)));
            ldsm4(qh[ks][0], qh[ks][1], qh[ks][2], qh[ks][3], sb + off);
        }
    }

    float oacc[8][4] = {};
    float mr0 = -1e30f, mr1 = -1e30f, lr0 = 0.f, lr1 = 0.f;

    for (int kt = 0; kt < LL / 64; kt++) {
        mbar_wait((kt & 1) ? sb + F1 : sb + F0, (uint32_t)((kt >> 1) & 1));
        const uint32_t kvb = sb + KVB0 + (uint32_t)(kt & 1) * KVSZ;
        const int k0g = kt * 64;

        float sacc[8][4] = {};
#pragma unroll
        for (int ks = 0; ks < 4; ks++) {
#pragma unroll
            for (int jj = 0; jj < 4; jj++) {
                uint32_t bh[4];
                uint32_t off = swz128((uint32_t)(((16 * jj + arow) << 7) + ((ks * 16 + acol8) << 1)));
                ldsm4(bh[0], bh[1], bh[2], bh[3], kvb + off);
                mma16816h(sacc[2*jj],   qh[ks], bh[0], bh[2]);
                mma16816h(sacc[2*jj+1], qh[ks], bh[1], bh[3]);
            }
        }

        const float cscale = 0.1803368801f;
        float mn0 = mr0, mn1 = mr1;
#pragma unroll
        for (int j = 0; j < 8; j++) {
            int kc = 8 * j + 2 * lam;
            bool k0m = s_maskAll[k0g + kc] != 0, k1m = s_maskAll[k0g + kc + 1] != 0;
            sacc[j][0] = k0m ? -1e9f : sacc[j][0] * cscale;
            sacc[j][1] = k1m ? -1e9f : sacc[j][1] * cscale;
            sacc[j][2] = k0m ? -1e9f : sacc[j][2] * cscale;
            sacc[j][3] = k1m ? -1e9f : sacc[j][3] * cscale;
            mn0 = fmaxf(mn0, fmaxf(sacc[j][0], sacc[j][1]));
            mn1 = fmaxf(mn1, fmaxf(sacc[j][2], sacc[j][3]));
        }
        mn0 = fmaxf(mn0, __shfl_xor_sync(0xffffffffu, mn0, 1));
        mn0 = fmaxf(mn0, __shfl_xor_sync(0xffffffffu, mn0, 2));
        mn1 = fmaxf(mn1, __shfl_xor_sync(0xffffffffu, mn1, 1));
        mn1 = fmaxf(mn1, __shfl_xor_sync(0xffffffffu, mn1, 2));
        float cs0 = fexp2f(mr0 - mn0), cs1 = fexp2f(mr1 - mn1);
        mr0 = mn0; mr1 = mn1;
        float rs0 = 0.f, rs1 = 0.f;
        uint32_t ph[8][2];
#pragma unroll
        for (int j = 0; j < 8; j++) {
            float p0 = fexp2f(sacc[j][0] - mn0);
            float p1 = fexp2f(sacc[j][1] - mn0);
            float p2 = fexp2f(sacc[j][2] - mn1);
            float p3 = fexp2f(sacc[j][3] - mn1);
            rs0 += p0 + p1; rs1 += p2 + p3;
            ph[j][0] = packh2(p0, p1);
            ph[j][1] = packh2(p2, p3);
        }
        rs0 += __shfl_xor_sync(0xffffffffu, rs0, 1);
        rs0 += __shfl_xor_sync(0xffffffffu, rs0, 2);
        rs1 += __shfl_xor_sync(0xffffffffu, rs1, 1);
        rs1 += __shfl_xor_sync(0xffffffffu, rs1, 2);
        lr0 = lr0 * cs0 + rs0;
        lr1 = lr1 * cs1 + rs1;
#pragma unroll
        for (int j = 0; j < 8; j++) {
            oacc[j][0] *= cs0; oacc[j][1] *= cs0;
            oacc[j][2] *= cs1; oacc[j][3] *= cs1;
        }

#pragma unroll
        for (int s = 0; s < 4; s++) {
            uint32_t pah[4] = { ph[2*s][0], ph[2*s][1], ph[2*s+1][0], ph[2*s+1][1] };
#pragma unroll
            for (int jj = 0; jj < 4; jj++) {
                uint32_t vh[4];
                uint32_t off = swz128((uint32_t)(((16 * s + arow) << 7) + ((jj * 16 + acol8) << 1)));
                ldsm4t(vh[0], vh[1], vh[2], vh[3], kvb + VOFF + off);
                mma16816h(oacc[2*jj],   pah, vh[0], vh[1]);
                mma16816h(oacc[2*jj+1], pah, vh[2], vh[3]);
            }
        }
        __syncthreads();
        if (tid == 0 && kt + 2 < LL / 64) {
            uint32_t full = (kt & 1) ? sb + F1 : sb + F0;
            uint32_t base = sb + KVB0 + (uint32_t)(kt & 1) * KVSZ;
            mbar_expect(full, 16384u);
            bulk_g2s(base,        kbase + (size_t)(kt + 2) * 4096, 8192u, full);
            bulk_g2s(base + VOFF, vbase + (size_t)(kt + 2) * 4096, 8192u, full);
        }
    }

    // epilogue -> fp16 tiled ao (row-tile (b*HW+q0)>>7, k-tile h)
    float i0 = 1.f / lr0, i1 = 1.f / lr1;
    int row0 = q0 + wid * 16 + g;
    size_t tbase = ((size_t)b * HW + q0) * HID * 2 + (size_t)h * 16384;
#pragma unroll
    for (int j = 0; j < 8; j++) {
        int cin = 8 * j + 2 * lam;
        uint32_t h0 = packh2(oacc[j][0] * i0, oacc[j][1] * i0);
        uint32_t h1 = packh2(oacc[j][2] * i1, oacc[j][3] * i1);
        uint32_t o0 = swz128((uint32_t)((row0 - q0) * 128 + cin * 2));
        uint32_t o1 = swz128((uint32_t)((row0 - q0 + 8) * 128 + cin * 2));
        *(uint32_t*)((char*)g_ao_f + tbase + o0) = h0;
        *(uint32_t*)((char*)g_ao_f + tbase + o1) = h1;
    }
}

// ---------------------------------------------------------------------------
extern "C" void kernel_launch(void* const* d_in, const int* in_sizes, int n_in,
                              void* d_out, int out_size)
{
    const float* v  = (const float*)d_in[0];
    const float* k  = (const float*)d_in[1];
    const float* q  = (const float*)d_in[2];
    const unsigned char* mask = (const unsigned char*)d_in[3];
    const float* Wv = (const float*)d_in[4];
    const float* bv = (const float*)d_in[5];
    const float* Wk = (const float*)d_in[6];
    const float* bk = (const float*)d_in[7];
    const float* Wq = (const float*)d_in[8];
    const float* bq = (const float*)d_in[9];
    const float* Wm = (const float*)d_in[10];
    const float* bm = (const float*)d_in[11];
    float* out = (float*)d_out;

    const int GEMM_SMEM = 65536 + 16;
    const int ATTN_SMEM = 49152 + 32;
    cudaFuncSetAttribute((const void*)proj_gemm,   cudaFuncAttributeMaxDynamicSharedMemorySize, GEMM_SMEM);
    cudaFuncSetAttribute((const void*)out_gemm,    cudaFuncAttributeMaxDynamicSharedMemorySize, GEMM_SMEM);
    cudaFuncSetAttribute((const void*)attn_kernel, cudaFuncAttributeMaxDynamicSharedMemorySize, ATTN_SMEM);

    // single fused preprocessing launch
    fused_pre<<<8736, 256>>>(q, k, v, Wk, Wv, Wq, Wm, mask);

    // fused projections -> head-separated swizzled K/V/Q tiles
    proj_gemm<<<dim3(HID/128, (BB*LL)/128, 3), 256, GEMM_SMEM>>>(bk, bv, bq);

    attn_kernel<<<dim3(HW/128, NH, BB), 256, ATTN_SMEM>>>();

    // output projection (fp16), batched over z
    out_gemm<<<dim3(HW/128, 512/128, BB), 256, GEMM_SMEM>>>(bm, out);
}